// round 2
// baseline (speedup 1.0000x reference)
#include <cuda_runtime.h>

// ---------------------------------------------------------------------------
// MGKBertSelfAttention: B=4, S=1024, HID=768, H=12, D=32, AH=384
// out = [ctx (B,S,AH) ; probs (B,H,S,S)]  fp32
// ---------------------------------------------------------------------------

namespace {
constexpr int kB = 4, kS = 1024, kHid = 768, kH = 12, kD = 32, kAH = 384;
constexpr int kBH = kB * kH;                       // 48
constexpr float kScaling = 0.17677669529663687f;   // 32^-0.5
constexpr float kC1 = 0.5f * kScaling;             // SCALING/2
constexpr float kC2 = 0.75f * kScaling;            // 1.5*SCALING/2
}

// Scratch (device globals; allocation is forbidden)
__device__ float g_q [kBH * kD * kS];   // [B,H,D,S]  (transposed)
__device__ float g_k1[kBH * kD * kS];   // [B,H,D,S]
__device__ float g_k2[kBH * kD * kS];   // [B,H,D,S]
__device__ float g_v [kBH * kS * kD];   // [B,H,S,D]
__device__ float g_nq [kBH * kS];
__device__ float g_nk1[kBH * kS];
__device__ float g_nk2[kBH * kS];

// ---------------------------------------------------------------------------
// Projection GEMM: out = X[4096,768] @ W[384,768]^T + bias
// sel: 0=q, 1=k1, 2=k2 (write transposed [B,H,D,S]), 3=v (write [B,H,S,D])
// Tiles BM=64, BN=64, BK=16; 256 threads, 4x4 micro-tile.
// ---------------------------------------------------------------------------
__global__ __launch_bounds__(256) void proj_kernel(
    const float* __restrict__ X, const float* __restrict__ W,
    const float* __restrict__ bias, int sel)
{
  __shared__ float As[16][64];
  __shared__ float Bs[16][64];
  __shared__ float Ts[64][65];

  const int tid = threadIdx.x;
  const int tx = tid & 15, ty = tid >> 4;
  const int m0 = blockIdx.y * 64, n0 = blockIdx.x * 64;
  const int lr = tid >> 2, lc = (tid & 3) * 4;

  float acc[4][4];
#pragma unroll
  for (int i = 0; i < 4; i++)
#pragma unroll
    for (int j = 0; j < 4; j++) acc[i][j] = 0.f;

  for (int k0 = 0; k0 < kHid; k0 += 16) {
    __syncthreads();
    float4 av = *(const float4*)&X[(size_t)(m0 + lr) * kHid + k0 + lc];
    As[lc + 0][lr] = av.x; As[lc + 1][lr] = av.y;
    As[lc + 2][lr] = av.z; As[lc + 3][lr] = av.w;
    float4 bv = *(const float4*)&W[(size_t)(n0 + lr) * kHid + k0 + lc];
    Bs[lc + 0][lr] = bv.x; Bs[lc + 1][lr] = bv.y;
    Bs[lc + 2][lr] = bv.z; Bs[lc + 3][lr] = bv.w;
    __syncthreads();
#pragma unroll
    for (int kk = 0; kk < 16; kk++) {
      float4 a = *(const float4*)&As[kk][ty * 4];
      float4 b = *(const float4*)&Bs[kk][tx * 4];
      float aa[4] = {a.x, a.y, a.z, a.w};
      float bb[4] = {b.x, b.y, b.z, b.w};
#pragma unroll
      for (int i = 0; i < 4; i++)
#pragma unroll
        for (int j = 0; j < 4; j++)
          acc[i][j] = fmaf(aa[i], bb[j], acc[i][j]);
    }
  }

  float4 bb4 = *(const float4*)&bias[n0 + tx * 4];
  float bvals[4] = {bb4.x, bb4.y, bb4.z, bb4.w};

  if (sel == 3) {
    // V: [B,H,S,D] direct float4 store (d contiguous within a head)
    const int n = n0 + tx * 4;
    const int h = n >> 5, d = n & 31;
#pragma unroll
    for (int i = 0; i < 4; i++) {
      const int m = m0 + ty * 4 + i;
      const int b = m >> 10, s = m & 1023;
      float4 o = make_float4(acc[i][0] + bvals[0], acc[i][1] + bvals[1],
                             acc[i][2] + bvals[2], acc[i][3] + bvals[3]);
      *(float4*)&g_v[(((size_t)b * kH + h) * kS + s) * kD + d] = o;
    }
  } else {
    float* out = (sel == 0) ? g_q : (sel == 1) ? g_k1 : g_k2;
#pragma unroll
    for (int i = 0; i < 4; i++)
#pragma unroll
      for (int j = 0; j < 4; j++)
        Ts[ty * 4 + i][tx * 4 + j] = acc[i][j] + bvals[j];
    __syncthreads();
    // coalesced transposed store: [B,H,D,S]
    for (int idx = tid; idx < 64 * 64; idx += 256) {
      const int ni = idx >> 6, mi = idx & 63;
      const int n = n0 + ni, m = m0 + mi;
      const int b = m >> 10, s = m & 1023;
      const int h = n >> 5, d = n & 31;
      out[(((size_t)b * kH + h) * kD + d) * kS + s] = Ts[mi][ni];
    }
  }
}

// ---------------------------------------------------------------------------
// Row norms |x|^2 over D for q/k1/k2 (transposed [B,H,D,S] layout)
// ---------------------------------------------------------------------------
__global__ __launch_bounds__(256) void norm_kernel() {
  const int bh = blockIdx.x;
  const float* src = (blockIdx.y == 0) ? g_q : (blockIdx.y == 1) ? g_k1 : g_k2;
  float* dst = (blockIdx.y == 0) ? g_nq : (blockIdx.y == 1) ? g_nk1 : g_nk2;
  const size_t base = (size_t)bh * kD * kS;
  for (int s = threadIdx.x; s < kS; s += 256) {
    float acc = 0.f;
#pragma unroll 8
    for (int d = 0; d < kD; d++) {
      float v = src[base + (size_t)d * kS + s];
      acc = fmaf(v, v, acc);
    }
    dst[bh * kS + s] = acc;
  }
}

// ---------------------------------------------------------------------------
// Fused attention. Block = (128 q rows) x (one bh). 256 threads.
// Pass 1: row maxes m1,m2.  Pass 2: e=pi0*exp(d1-m1)+pi1*exp(d2-m2),
// rowsum, ctx += E @ V.  Pass 3: write normalized probs.
// ---------------------------------------------------------------------------
struct AttnSmem {
  float Qs [kD][128];
  float K1s[kD][128];
  float K2s[kD][128];
  float Vs [128][kD];
  float Es [128][129];   // padded
  float nqs[128];
  float nk1s[128];
  float nk2s[128];
  float msk[128];
  float invs[128];
};

__device__ __forceinline__ void cross_tile(const float (&Qs)[kD][128],
                                           const float (&Ks)[kD][128],
                                           int r0, int c0, float (&c)[8][8]) {
#pragma unroll
  for (int i = 0; i < 8; i++)
#pragma unroll
    for (int j = 0; j < 8; j++) c[i][j] = 0.f;
#pragma unroll 4
  for (int d = 0; d < kD; d++) {
    float4 a0 = *(const float4*)&Qs[d][r0];
    float4 a1 = *(const float4*)&Qs[d][r0 + 4];
    float4 b0 = *(const float4*)&Ks[d][c0];
    float4 b1 = *(const float4*)&Ks[d][c0 + 4];
    float av[8] = {a0.x, a0.y, a0.z, a0.w, a1.x, a1.y, a1.z, a1.w};
    float bv[8] = {b0.x, b0.y, b0.z, b0.w, b1.x, b1.y, b1.z, b1.w};
#pragma unroll
    for (int i = 0; i < 8; i++)
#pragma unroll
      for (int j = 0; j < 8; j++)
        c[i][j] = fmaf(av[i], bv[j], c[i][j]);
  }
}

__device__ __forceinline__ void load_kt(AttnSmem& sm, size_t kbase, size_t vbase,
                                        int nbase, int j0, int tid,
                                        const float* __restrict__ mask, int b,
                                        bool withV) {
  for (int idx = tid; idx < kD * 128; idx += 256) {
    const int d = idx >> 7, j = idx & 127;
    sm.K1s[d][j] = g_k1[kbase + (size_t)d * kS + j0 + j];
    sm.K2s[d][j] = g_k2[kbase + (size_t)d * kS + j0 + j];
  }
  if (withV) {
    for (int idx = tid; idx < 128 * kD; idx += 256) {
      const int j = idx >> 5, d = idx & 31;
      sm.Vs[j][d] = g_v[vbase + (size_t)(j0 + j) * kD + d];
    }
  }
  if (tid < 128) {
    sm.nk1s[tid] = g_nk1[nbase + j0 + tid];
    sm.nk2s[tid] = g_nk2[nbase + j0 + tid];
    sm.msk[tid]  = mask[b * kS + j0 + tid];
  }
}

__global__ __launch_bounds__(256) void attn_kernel(
    const float* __restrict__ mask, const float* __restrict__ pi,
    float* __restrict__ out_ctx, float* __restrict__ out_probs)
{
  extern __shared__ char smem_raw[];
  AttnSmem& sm = *reinterpret_cast<AttnSmem*>(smem_raw);
  const int tid = threadIdx.x;
  const int qt = blockIdx.x, bh = blockIdx.y;
  const int b = bh / kH, h = bh % kH;
  const size_t kbase = (size_t)bh * kD * kS;
  const size_t vbase = (size_t)bh * kS * kD;
  const int nbase = bh * kS;
  const float pi0 = fminf(fmaxf(pi[h],      1e-6f), 2.0f);
  const float pi1 = fminf(fmaxf(pi[kH + h], 1e-6f), 2.0f);
  const int q0 = qt * 128;

  // Q tile (already transposed in global)
  for (int idx = tid; idx < kD * 128; idx += 256) {
    const int d = idx >> 7, m = idx & 127;
    sm.Qs[d][m] = g_q[kbase + (size_t)d * kS + q0 + m];
  }
  if (tid < 128) sm.nqs[tid] = g_nq[nbase + q0 + tid];
  __syncthreads();

  const int tx = tid & 15, ty = tid >> 4;
  const int r0 = ty * 8, c0 = tx * 8;

  float nq[8];
#pragma unroll
  for (int i = 0; i < 8; i++) nq[i] = sm.nqs[r0 + i];

  float m1[8], m2[8];
#pragma unroll
  for (int i = 0; i < 8; i++) { m1[i] = -1e30f; m2[i] = -1e30f; }

  float c[8][8];

  // -------- pass 1: exact row maxes of d1 and d2 --------
  for (int kt = 0; kt < 8; kt++) {
    __syncthreads();
    load_kt(sm, kbase, vbase, nbase, kt * 128, tid, mask, b, false);
    __syncthreads();
    cross_tile(sm.Qs, sm.K1s, r0, c0, c);
#pragma unroll
    for (int i = 0; i < 8; i++)
#pragma unroll
      for (int j = 0; j < 8; j++) {
        float dist = fmaxf(nq[i] + sm.nk1s[c0 + j] - 2.f * c[i][j], 0.f);
        m1[i] = fmaxf(m1[i], fmaf(-kC1, dist, sm.msk[c0 + j]));
      }
    cross_tile(sm.Qs, sm.K2s, r0, c0, c);
#pragma unroll
    for (int i = 0; i < 8; i++)
#pragma unroll
      for (int j = 0; j < 8; j++) {
        float dist = fmaxf(nq[i] + sm.nk2s[c0 + j] - 2.f * c[i][j], 0.f);
        m2[i] = fmaxf(m2[i], fmaf(-kC2, dist, sm.msk[c0 + j]));
      }
  }
  // reduce across the 16 threads sharing each row (16-lane halves of warp)
#pragma unroll
  for (int i = 0; i < 8; i++) {
#pragma unroll
    for (int off = 8; off > 0; off >>= 1) {
      m1[i] = fmaxf(m1[i], __shfl_xor_sync(0xffffffffu, m1[i], off));
      m2[i] = fmaxf(m2[i], __shfl_xor_sync(0xffffffffu, m2[i], off));
    }
  }

  // -------- pass 2: rowsum + ctx --------
  float rs[8];
#pragma unroll
  for (int i = 0; i < 8; i++) rs[i] = 0.f;
  float cacc[4][4];
#pragma unroll
  for (int i = 0; i < 4; i++)
#pragma unroll
    for (int j = 0; j < 4; j++) cacc[i][j] = 0.f;
  const int cm = (tid >> 3) * 4;   // ctx row group   (0..124)
  const int cd = (tid & 7) * 4;    // ctx d group     (0..28)

  for (int kt = 0; kt < 8; kt++) {
    __syncthreads();
    load_kt(sm, kbase, vbase, nbase, kt * 128, tid, mask, b, true);
    __syncthreads();
    cross_tile(sm.Qs, sm.K1s, r0, c0, c);
#pragma unroll
    for (int i = 0; i < 8; i++)
#pragma unroll
      for (int j = 0; j < 8; j++) {
        float dist = fmaxf(nq[i] + sm.nk1s[c0 + j] - 2.f * c[i][j], 0.f);
        float d1 = fmaf(-kC1, dist, sm.msk[c0 + j]);
        sm.Es[r0 + i][c0 + j] = pi0 * __expf(d1 - m1[i]);
      }
    cross_tile(sm.Qs, sm.K2s, r0, c0, c);
#pragma unroll
    for (int i = 0; i < 8; i++)
#pragma unroll
      for (int j = 0; j < 8; j++) {
        float dist = fmaxf(nq[i] + sm.nk2s[c0 + j] - 2.f * c[i][j], 0.f);
        float d2 = fmaf(-kC2, dist, sm.msk[c0 + j]);
        float e = sm.Es[r0 + i][c0 + j] + pi1 * __expf(d2 - m2[i]);
        sm.Es[r0 + i][c0 + j] = e;
        rs[i] += e;
      }
    __syncthreads();
    // ctx += E @ V  (re-mapped thread layout, smem-staged)
#pragma unroll 4
    for (int jj = 0; jj < 128; jj++) {
      float4 bv = *(const float4*)&sm.Vs[jj][cd];
      float a0 = sm.Es[cm + 0][jj], a1 = sm.Es[cm + 1][jj];
      float a2 = sm.Es[cm + 2][jj], a3 = sm.Es[cm + 3][jj];
      cacc[0][0] = fmaf(a0, bv.x, cacc[0][0]); cacc[0][1] = fmaf(a0, bv.y, cacc[0][1]);
      cacc[0][2] = fmaf(a0, bv.z, cacc[0][2]); cacc[0][3] = fmaf(a0, bv.w, cacc[0][3]);
      cacc[1][0] = fmaf(a1, bv.x, cacc[1][0]); cacc[1][1] = fmaf(a1, bv.y, cacc[1][1]);
      cacc[1][2] = fmaf(a1, bv.z, cacc[1][2]); cacc[1][3] = fmaf(a1, bv.w, cacc[1][3]);
      cacc[2][0] = fmaf(a2, bv.x, cacc[2][0]); cacc[2][1] = fmaf(a2, bv.y, cacc[2][1]);
      cacc[2][2] = fmaf(a2, bv.z, cacc[2][2]); cacc[2][3] = fmaf(a2, bv.w, cacc[2][3]);
      cacc[3][0] = fmaf(a3, bv.x, cacc[3][0]); cacc[3][1] = fmaf(a3, bv.y, cacc[3][1]);
      cacc[3][2] = fmaf(a3, bv.z, cacc[3][2]); cacc[3][3] = fmaf(a3, bv.w, cacc[3][3]);
    }
  }
  // reduce rowsums across the 16 threads per row
#pragma unroll
  for (int i = 0; i < 8; i++) {
#pragma unroll
    for (int off = 8; off > 0; off >>= 1)
      rs[i] += __shfl_xor_sync(0xffffffffu, rs[i], off);
  }
  if (tx == 0) {
#pragma unroll
    for (int i = 0; i < 8; i++)
      sm.invs[r0 + i] = 1.0f / (rs[i] + 1e-6f);
  }
  __syncthreads();

  // write ctx (normalized)
#pragma unroll
  for (int i = 0; i < 4; i++) {
    const int s = q0 + cm + i;
    const float inv = sm.invs[cm + i];
    float4 o = make_float4(cacc[i][0] * inv, cacc[i][1] * inv,
                           cacc[i][2] * inv, cacc[i][3] * inv);
    *(float4*)&out_ctx[((size_t)b * kS + s) * kAH + h * kD + cd] = o;
  }

  // -------- pass 3: normalized probs --------
  float iv[8];
#pragma unroll
  for (int i = 0; i < 8; i++) iv[i] = sm.invs[r0 + i];

  for (int kt = 0; kt < 8; kt++) {
    __syncthreads();
    load_kt(sm, kbase, vbase, nbase, kt * 128, tid, mask, b, false);
    __syncthreads();
    cross_tile(sm.Qs, sm.K1s, r0, c0, c);
#pragma unroll
    for (int i = 0; i < 8; i++)
#pragma unroll
      for (int j = 0; j < 8; j++) {
        float dist = fmaxf(nq[i] + sm.nk1s[c0 + j] - 2.f * c[i][j], 0.f);
        float d1 = fmaf(-kC1, dist, sm.msk[c0 + j]);
        sm.Es[r0 + i][c0 + j] = pi0 * __expf(d1 - m1[i]);
      }
    cross_tile(sm.Qs, sm.K2s, r0, c0, c);
#pragma unroll
    for (int i = 0; i < 8; i++) {
      float p[8];
#pragma unroll
      for (int j = 0; j < 8; j++) {
        float dist = fmaxf(nq[i] + sm.nk2s[c0 + j] - 2.f * c[i][j], 0.f);
        float d2 = fmaf(-kC2, dist, sm.msk[c0 + j]);
        float e = sm.Es[r0 + i][c0 + j] + pi1 * __expf(d2 - m2[i]);
        p[j] = e * iv[i];
      }
      float* dst = &out_probs[((size_t)bh * kS + q0 + r0 + i) * kS + kt * 128 + c0];
      *(float4*)dst       = make_float4(p[0], p[1], p[2], p[3]);
      *(float4*)(dst + 4) = make_float4(p[4], p[5], p[6], p[7]);
    }
  }
}

// ---------------------------------------------------------------------------
extern "C" void kernel_launch(void* const* d_in, const int* in_sizes, int n_in,
                              void* d_out, int out_size) {
  (void)in_sizes; (void)n_in; (void)out_size;
  const float* hs   = (const float*)d_in[0];
  const float* mask = (const float*)d_in[1];
  const float* Wq   = (const float*)d_in[2];
  const float* bq   = (const float*)d_in[3];
  const float* Wk1  = (const float*)d_in[4];
  const float* bk1  = (const float*)d_in[5];
  const float* Wk2  = (const float*)d_in[6];
  const float* bk2  = (const float*)d_in[7];
  const float* Wv   = (const float*)d_in[8];
  const float* bv   = (const float*)d_in[9];
  const float* pi   = (const float*)d_in[10];

  float* out_ctx   = (float*)d_out;
  float* out_probs = out_ctx + (size_t)kB * kS * kAH;

  cudaFuncSetAttribute(attn_kernel, cudaFuncAttributeMaxDynamicSharedMemorySize,
                       (int)sizeof(AttnSmem));

  dim3 pgrid(kAH / 64, (kB * kS) / 64);   // (6, 64)
  proj_kernel<<<pgrid, 256>>>(hs, Wq,  bq,  0);
  proj_kernel<<<pgrid, 256>>>(hs, Wk1, bk1, 1);
  proj_kernel<<<pgrid, 256>>>(hs, Wk2, bk2, 2);
  proj_kernel<<<pgrid, 256>>>(hs, Wv,  bv,  3);
  norm_kernel<<<dim3(kBH, 3), 256>>>();
  attn_kernel<<<dim3(kS / 128, kBH), 256, sizeof(AttnSmem)>>>(
      mask, pi, out_ctx, out_probs);
}

// round 3
// speedup vs baseline: 1.0001x; 1.0001x over previous
#include <cuda_runtime.h>

// ---------------------------------------------------------------------------
// MGKBertSelfAttention: B=4, S=1024, HID=768, H=12, D=32, AH=384
// out = [ctx (B,S,AH) ; probs (B,H,S,S)]  fp32
// ---------------------------------------------------------------------------

namespace {
constexpr int kB = 4, kS = 1024, kHid = 768, kH = 12, kD = 32, kAH = 384;
constexpr int kBH = kB * kH;                       // 48
constexpr float kScaling = 0.17677669529663687f;   // 32^-0.5
constexpr float kC1 = 0.5f * kScaling;             // SCALING/2
constexpr float kC2 = 0.75f * kScaling;            // 1.5*SCALING/2
}

// Scratch (device globals; allocation is forbidden)
__device__ float g_q [kBH * kD * kS];   // [B,H,D,S]  (transposed)
__device__ float g_k1[kBH * kD * kS];   // [B,H,D,S]
__device__ float g_k2[kBH * kD * kS];   // [B,H,D,S]
__device__ float g_v [kBH * kS * kD];   // [B,H,S,D]
__device__ float g_nq [kBH * kS];
__device__ float g_nk1[kBH * kS];
__device__ float g_nk2[kBH * kS];

// ---------------------------------------------------------------------------
// Projection GEMM: out = X[4096,768] @ W[384,768]^T + bias
// sel: 0=q, 1=k1, 2=k2 (write transposed [B,H,D,S]), 3=v (write [B,H,S,D])
// Tiles BM=64, BN=64, BK=16; 256 threads, 4x4 micro-tile.
// ---------------------------------------------------------------------------
__global__ __launch_bounds__(256) void proj_kernel(
    const float* __restrict__ X, const float* __restrict__ W,
    const float* __restrict__ bias, int sel)
{
  __shared__ float As[16][64];
  __shared__ float Bs[16][64];
  __shared__ float Ts[64][65];

  const int tid = threadIdx.x;
  const int tx = tid & 15, ty = tid >> 4;
  const int m0 = blockIdx.y * 64, n0 = blockIdx.x * 64;
  const int lr = tid >> 2, lc = (tid & 3) * 4;

  float acc[4][4];
#pragma unroll
  for (int i = 0; i < 4; i++)
#pragma unroll
    for (int j = 0; j < 4; j++) acc[i][j] = 0.f;

  for (int k0 = 0; k0 < kHid; k0 += 16) {
    __syncthreads();
    float4 av = *(const float4*)&X[(size_t)(m0 + lr) * kHid + k0 + lc];
    As[lc + 0][lr] = av.x; As[lc + 1][lr] = av.y;
    As[lc + 2][lr] = av.z; As[lc + 3][lr] = av.w;
    float4 bv = *(const float4*)&W[(size_t)(n0 + lr) * kHid + k0 + lc];
    Bs[lc + 0][lr] = bv.x; Bs[lc + 1][lr] = bv.y;
    Bs[lc + 2][lr] = bv.z; Bs[lc + 3][lr] = bv.w;
    __syncthreads();
#pragma unroll
    for (int kk = 0; kk < 16; kk++) {
      float4 a = *(const float4*)&As[kk][ty * 4];
      float4 b = *(const float4*)&Bs[kk][tx * 4];
      float aa[4] = {a.x, a.y, a.z, a.w};
      float bb[4] = {b.x, b.y, b.z, b.w};
#pragma unroll
      for (int i = 0; i < 4; i++)
#pragma unroll
        for (int j = 0; j < 4; j++)
          acc[i][j] = fmaf(aa[i], bb[j], acc[i][j]);
    }
  }

  float4 bb4 = *(const float4*)&bias[n0 + tx * 4];
  float bvals[4] = {bb4.x, bb4.y, bb4.z, bb4.w};

  if (sel == 3) {
    // V: [B,H,S,D] direct float4 store (d contiguous within a head)
    const int n = n0 + tx * 4;
    const int h = n >> 5, d = n & 31;
#pragma unroll
    for (int i = 0; i < 4; i++) {
      const int m = m0 + ty * 4 + i;
      const int b = m >> 10, s = m & 1023;
      float4 o = make_float4(acc[i][0] + bvals[0], acc[i][1] + bvals[1],
                             acc[i][2] + bvals[2], acc[i][3] + bvals[3]);
      *(float4*)&g_v[(((size_t)b * kH + h) * kS + s) * kD + d] = o;
    }
  } else {
    float* out = (sel == 0) ? g_q : (sel == 1) ? g_k1 : g_k2;
#pragma unroll
    for (int i = 0; i < 4; i++)
#pragma unroll
      for (int j = 0; j < 4; j++)
        Ts[ty * 4 + i][tx * 4 + j] = acc[i][j] + bvals[j];
    __syncthreads();
    // coalesced transposed store: [B,H,D,S]
    for (int idx = tid; idx < 64 * 64; idx += 256) {
      const int ni = idx >> 6, mi = idx & 63;
      const int n = n0 + ni, m = m0 + mi;
      const int b = m >> 10, s = m & 1023;
      const int h = n >> 5, d = n & 31;
      out[(((size_t)b * kH + h) * kD + d) * kS + s] = Ts[mi][ni];
    }
  }
}

// ---------------------------------------------------------------------------
// Row norms |x|^2 over D for q/k1/k2 (transposed [B,H,D,S] layout)
// ---------------------------------------------------------------------------
__global__ __launch_bounds__(256) void norm_kernel() {
  const int bh = blockIdx.x;
  const float* src = (blockIdx.y == 0) ? g_q : (blockIdx.y == 1) ? g_k1 : g_k2;
  float* dst = (blockIdx.y == 0) ? g_nq : (blockIdx.y == 1) ? g_nk1 : g_nk2;
  const size_t base = (size_t)bh * kD * kS;
  for (int s = threadIdx.x; s < kS; s += 256) {
    float acc = 0.f;
#pragma unroll 8
    for (int d = 0; d < kD; d++) {
      float v = src[base + (size_t)d * kS + s];
      acc = fmaf(v, v, acc);
    }
    dst[bh * kS + s] = acc;
  }
}

// ---------------------------------------------------------------------------
// Fused attention. Block = (128 q rows) x (one bh). 256 threads.
// Pass 1: row maxes m1,m2.  Pass 2: e=pi0*exp(d1-m1)+pi1*exp(d2-m2),
// rowsum, ctx += E @ V.  Pass 3: write normalized probs.
// ---------------------------------------------------------------------------
struct AttnSmem {
  float Qs [kD][128];
  float K1s[kD][128];
  float K2s[kD][128];
  float Vs [128][kD];
  float Es [128][129];   // padded
  float nqs[128];
  float nk1s[128];
  float nk2s[128];
  float msk[128];
  float invs[128];
};

__device__ __forceinline__ void cross_tile(const float (&Qs)[kD][128],
                                           const float (&Ks)[kD][128],
                                           int r0, int c0, float (&c)[8][8]) {
#pragma unroll
  for (int i = 0; i < 8; i++)
#pragma unroll
    for (int j = 0; j < 8; j++) c[i][j] = 0.f;
#pragma unroll 4
  for (int d = 0; d < kD; d++) {
    float4 a0 = *(const float4*)&Qs[d][r0];
    float4 a1 = *(const float4*)&Qs[d][r0 + 4];
    float4 b0 = *(const float4*)&Ks[d][c0];
    float4 b1 = *(const float4*)&Ks[d][c0 + 4];
    float av[8] = {a0.x, a0.y, a0.z, a0.w, a1.x, a1.y, a1.z, a1.w};
    float bv[8] = {b0.x, b0.y, b0.z, b0.w, b1.x, b1.y, b1.z, b1.w};
#pragma unroll
    for (int i = 0; i < 8; i++)
#pragma unroll
      for (int j = 0; j < 8; j++)
        c[i][j] = fmaf(av[i], bv[j], c[i][j]);
  }
}

__device__ __forceinline__ void load_kt(AttnSmem& sm, size_t kbase, size_t vbase,
                                        int nbase, int j0, int tid,
                                        const float* __restrict__ mask, int b,
                                        bool withV) {
  for (int idx = tid; idx < kD * 128; idx += 256) {
    const int d = idx >> 7, j = idx & 127;
    sm.K1s[d][j] = g_k1[kbase + (size_t)d * kS + j0 + j];
    sm.K2s[d][j] = g_k2[kbase + (size_t)d * kS + j0 + j];
  }
  if (withV) {
    for (int idx = tid; idx < 128 * kD; idx += 256) {
      const int j = idx >> 5, d = idx & 31;
      sm.Vs[j][d] = g_v[vbase + (size_t)(j0 + j) * kD + d];
    }
  }
  if (tid < 128) {
    sm.nk1s[tid] = g_nk1[nbase + j0 + tid];
    sm.nk2s[tid] = g_nk2[nbase + j0 + tid];
    sm.msk[tid]  = mask[b * kS + j0 + tid];
  }
}

__global__ __launch_bounds__(256) void attn_kernel(
    const float* __restrict__ mask, const float* __restrict__ pi,
    float* __restrict__ out_ctx, float* __restrict__ out_probs)
{
  extern __shared__ char smem_raw[];
  AttnSmem& sm = *reinterpret_cast<AttnSmem*>(smem_raw);
  const int tid = threadIdx.x;
  const int qt = blockIdx.x, bh = blockIdx.y;
  const int b = bh / kH, h = bh % kH;
  const size_t kbase = (size_t)bh * kD * kS;
  const size_t vbase = (size_t)bh * kS * kD;
  const int nbase = bh * kS;
  const float pi0 = fminf(fmaxf(pi[h],      1e-6f), 2.0f);
  const float pi1 = fminf(fmaxf(pi[kH + h], 1e-6f), 2.0f);
  const int q0 = qt * 128;

  // Q tile (already transposed in global)
  for (int idx = tid; idx < kD * 128; idx += 256) {
    const int d = idx >> 7, m = idx & 127;
    sm.Qs[d][m] = g_q[kbase + (size_t)d * kS + q0 + m];
  }
  if (tid < 128) sm.nqs[tid] = g_nq[nbase + q0 + tid];
  __syncthreads();

  const int tx = tid & 15, ty = tid >> 4;
  const int r0 = ty * 8, c0 = tx * 8;

  float nq[8];
#pragma unroll
  for (int i = 0; i < 8; i++) nq[i] = sm.nqs[r0 + i];

  float m1[8], m2[8];
#pragma unroll
  for (int i = 0; i < 8; i++) { m1[i] = -1e30f; m2[i] = -1e30f; }

  float c[8][8];

  // -------- pass 1: exact row maxes of d1 and d2 --------
  for (int kt = 0; kt < 8; kt++) {
    __syncthreads();
    load_kt(sm, kbase, vbase, nbase, kt * 128, tid, mask, b, false);
    __syncthreads();
    cross_tile(sm.Qs, sm.K1s, r0, c0, c);
#pragma unroll
    for (int i = 0; i < 8; i++)
#pragma unroll
      for (int j = 0; j < 8; j++) {
        float dist = fmaxf(nq[i] + sm.nk1s[c0 + j] - 2.f * c[i][j], 0.f);
        m1[i] = fmaxf(m1[i], fmaf(-kC1, dist, sm.msk[c0 + j]));
      }
    cross_tile(sm.Qs, sm.K2s, r0, c0, c);
#pragma unroll
    for (int i = 0; i < 8; i++)
#pragma unroll
      for (int j = 0; j < 8; j++) {
        float dist = fmaxf(nq[i] + sm.nk2s[c0 + j] - 2.f * c[i][j], 0.f);
        m2[i] = fmaxf(m2[i], fmaf(-kC2, dist, sm.msk[c0 + j]));
      }
  }
  // reduce across the 16 threads sharing each row (16-lane halves of warp)
#pragma unroll
  for (int i = 0; i < 8; i++) {
#pragma unroll
    for (int off = 8; off > 0; off >>= 1) {
      m1[i] = fmaxf(m1[i], __shfl_xor_sync(0xffffffffu, m1[i], off));
      m2[i] = fmaxf(m2[i], __shfl_xor_sync(0xffffffffu, m2[i], off));
    }
  }

  // -------- pass 2: rowsum + ctx --------
  float rs[8];
#pragma unroll
  for (int i = 0; i < 8; i++) rs[i] = 0.f;
  float cacc[4][4];
#pragma unroll
  for (int i = 0; i < 4; i++)
#pragma unroll
    for (int j = 0; j < 4; j++) cacc[i][j] = 0.f;
  const int cm = (tid >> 3) * 4;   // ctx row group   (0..124)
  const int cd = (tid & 7) * 4;    // ctx d group     (0..28)

  for (int kt = 0; kt < 8; kt++) {
    __syncthreads();
    load_kt(sm, kbase, vbase, nbase, kt * 128, tid, mask, b, true);
    __syncthreads();
    cross_tile(sm.Qs, sm.K1s, r0, c0, c);
#pragma unroll
    for (int i = 0; i < 8; i++)
#pragma unroll
      for (int j = 0; j < 8; j++) {
        float dist = fmaxf(nq[i] + sm.nk1s[c0 + j] - 2.f * c[i][j], 0.f);
        float d1 = fmaf(-kC1, dist, sm.msk[c0 + j]);
        sm.Es[r0 + i][c0 + j] = pi0 * __expf(d1 - m1[i]);
      }
    cross_tile(sm.Qs, sm.K2s, r0, c0, c);
#pragma unroll
    for (int i = 0; i < 8; i++)
#pragma unroll
      for (int j = 0; j < 8; j++) {
        float dist = fmaxf(nq[i] + sm.nk2s[c0 + j] - 2.f * c[i][j], 0.f);
        float d2 = fmaf(-kC2, dist, sm.msk[c0 + j]);
        float e = sm.Es[r0 + i][c0 + j] + pi1 * __expf(d2 - m2[i]);
        sm.Es[r0 + i][c0 + j] = e;
        rs[i] += e;
      }
    __syncthreads();
    // ctx += E @ V  (re-mapped thread layout, smem-staged)
#pragma unroll 4
    for (int jj = 0; jj < 128; jj++) {
      float4 bv = *(const float4*)&sm.Vs[jj][cd];
      float a0 = sm.Es[cm + 0][jj], a1 = sm.Es[cm + 1][jj];
      float a2 = sm.Es[cm + 2][jj], a3 = sm.Es[cm + 3][jj];
      cacc[0][0] = fmaf(a0, bv.x, cacc[0][0]); cacc[0][1] = fmaf(a0, bv.y, cacc[0][1]);
      cacc[0][2] = fmaf(a0, bv.z, cacc[0][2]); cacc[0][3] = fmaf(a0, bv.w, cacc[0][3]);
      cacc[1][0] = fmaf(a1, bv.x, cacc[1][0]); cacc[1][1] = fmaf(a1, bv.y, cacc[1][1]);
      cacc[1][2] = fmaf(a1, bv.z, cacc[1][2]); cacc[1][3] = fmaf(a1, bv.w, cacc[1][3]);
      cacc[2][0] = fmaf(a2, bv.x, cacc[2][0]); cacc[2][1] = fmaf(a2, bv.y, cacc[2][1]);
      cacc[2][2] = fmaf(a2, bv.z, cacc[2][2]); cacc[2][3] = fmaf(a2, bv.w, cacc[2][3]);
      cacc[3][0] = fmaf(a3, bv.x, cacc[3][0]); cacc[3][1] = fmaf(a3, bv.y, cacc[3][1]);
      cacc[3][2] = fmaf(a3, bv.z, cacc[3][2]); cacc[3][3] = fmaf(a3, bv.w, cacc[3][3]);
    }
  }
  // reduce rowsums across the 16 threads per row
#pragma unroll
  for (int i = 0; i < 8; i++) {
#pragma unroll
    for (int off = 8; off > 0; off >>= 1)
      rs[i] += __shfl_xor_sync(0xffffffffu, rs[i], off);
  }
  if (tx == 0) {
#pragma unroll
    for (int i = 0; i < 8; i++)
      sm.invs[r0 + i] = 1.0f / (rs[i] + 1e-6f);
  }
  __syncthreads();

  // write ctx (normalized)
#pragma unroll
  for (int i = 0; i < 4; i++) {
    const int s = q0 + cm + i;
    const float inv = sm.invs[cm + i];
    float4 o = make_float4(cacc[i][0] * inv, cacc[i][1] * inv,
                           cacc[i][2] * inv, cacc[i][3] * inv);
    *(float4*)&out_ctx[((size_t)b * kS + s) * kAH + h * kD + cd] = o;
  }

  // -------- pass 3: normalized probs --------
  float iv[8];
#pragma unroll
  for (int i = 0; i < 8; i++) iv[i] = sm.invs[r0 + i];

  for (int kt = 0; kt < 8; kt++) {
    __syncthreads();
    load_kt(sm, kbase, vbase, nbase, kt * 128, tid, mask, b, false);
    __syncthreads();
    cross_tile(sm.Qs, sm.K1s, r0, c0, c);
#pragma unroll
    for (int i = 0; i < 8; i++)
#pragma unroll
      for (int j = 0; j < 8; j++) {
        float dist = fmaxf(nq[i] + sm.nk1s[c0 + j] - 2.f * c[i][j], 0.f);
        float d1 = fmaf(-kC1, dist, sm.msk[c0 + j]);
        sm.Es[r0 + i][c0 + j] = pi0 * __expf(d1 - m1[i]);
      }
    cross_tile(sm.Qs, sm.K2s, r0, c0, c);
#pragma unroll
    for (int i = 0; i < 8; i++) {
      float p[8];
#pragma unroll
      for (int j = 0; j < 8; j++) {
        float dist = fmaxf(nq[i] + sm.nk2s[c0 + j] - 2.f * c[i][j], 0.f);
        float d2 = fmaf(-kC2, dist, sm.msk[c0 + j]);
        float e = sm.Es[r0 + i][c0 + j] + pi1 * __expf(d2 - m2[i]);
        p[j] = e * iv[i];
      }
      float* dst = &out_probs[((size_t)bh * kS + q0 + r0 + i) * kS + kt * 128 + c0];
      *(float4*)dst       = make_float4(p[0], p[1], p[2], p[3]);
      *(float4*)(dst + 4) = make_float4(p[4], p[5], p[6], p[7]);
    }
  }
}

// ---------------------------------------------------------------------------
extern "C" void kernel_launch(void* const* d_in, const int* in_sizes, int n_in,
                              void* d_out, int out_size) {
  (void)in_sizes; (void)n_in; (void)out_size;
  const float* hs   = (const float*)d_in[0];
  const float* mask = (const float*)d_in[1];
  const float* Wq   = (const float*)d_in[2];
  const float* bq   = (const float*)d_in[3];
  const float* Wk1  = (const float*)d_in[4];
  const float* bk1  = (const float*)d_in[5];
  const float* Wk2  = (const float*)d_in[6];
  const float* bk2  = (const float*)d_in[7];
  const float* Wv   = (const float*)d_in[8];
  const float* bv   = (const float*)d_in[9];
  const float* pi   = (const float*)d_in[10];

  float* out_ctx   = (float*)d_out;
  float* out_probs = out_ctx + (size_t)kB * kS * kAH;

  cudaFuncSetAttribute(attn_kernel, cudaFuncAttributeMaxDynamicSharedMemorySize,
                       (int)sizeof(AttnSmem));

  dim3 pgrid(kAH / 64, (kB * kS) / 64);   // (6, 64)
  proj_kernel<<<pgrid, 256>>>(hs, Wq,  bq,  0);
  proj_kernel<<<pgrid, 256>>>(hs, Wk1, bk1, 1);
  proj_kernel<<<pgrid, 256>>>(hs, Wk2, bk2, 2);
  proj_kernel<<<pgrid, 256>>>(hs, Wv,  bv,  3);
  norm_kernel<<<dim3(kBH, 3), 256>>>();
  attn_kernel<<<dim3(kS / 128, kBH), 256, sizeof(AttnSmem)>>>(
      mask, pi, out_ctx, out_probs);
}

// round 5
// speedup vs baseline: 1.1449x; 1.1448x over previous
#include <cuda_runtime.h>
#include <cstdint>

// ---------------------------------------------------------------------------
// MGKBertSelfAttention: B=4, S=1024, HID=768, H=12, D=32, AH=384
// out = [ctx (B,S,AH) ; probs (B,H,S,S)]  fp32
// Score cross terms via split-TF32 mma.sync (fp32-equivalent precision).
// NOTE: harness compiles for base sm_103 -> no tcgen05; mma.sync only.
// ---------------------------------------------------------------------------

namespace {
constexpr int kB = 4, kS = 1024, kHid = 768, kH = 12, kD = 32, kAH = 384;
constexpr int kBH = kB * kH;                       // 48
constexpr float kScaling = 0.17677669529663687f;   // 32^-0.5
constexpr float kC1 = 0.5f * kScaling;
constexpr float kC2 = 0.75f * kScaling;

// smem layout (bytes)
constexpr int OFF_NQ  = 0;
constexpr int OFF_NK1 = 512;
constexpr int OFF_NK2 = 1024;
constexpr int OFF_MSK = 1536;
constexpr int OFF_INV = 2048;
constexpr int OFF_V   = 2560;                       // 128*32*4 = 16384
constexpr int OFF_K1H = OFF_V + 16384;              // each K tile 128*36*4 = 18432
constexpr int OFF_K1L = OFF_K1H + 18432;
constexpr int OFF_K2H = OFF_K1L + 18432;
constexpr int OFF_K2L = OFF_K2H + 18432;
constexpr int OFF_ES  = OFF_K2L + 18432;            // 128*129*4 = 66048 (Q stage aliases)
constexpr int kSmemBytes = OFF_ES + 128 * 129 * 4;  // 158720
}

// Scratch (device globals; allocation is forbidden)
__device__ float g_q [kBH * kS * kD];   // [bh][s][d]
__device__ float g_k1[kBH * kS * kD];
__device__ float g_k2[kBH * kS * kD];
__device__ float g_v [kBH * kS * kD];
__device__ float g_nq [kBH * kS];
__device__ float g_nk1[kBH * kS];
__device__ float g_nk2[kBH * kS];

// ---------------------------------------------------------------------------
// tf32 helpers
// ---------------------------------------------------------------------------
__device__ __forceinline__ uint32_t f2tf32(float x) {
  uint32_t u;
  asm("cvt.rna.tf32.f32 %0, %1;" : "=r"(u) : "f"(x));
  return u;
}
__device__ __forceinline__ void split_tf32(float x, uint32_t& hi, uint32_t& lo) {
  hi = f2tf32(x);
  lo = f2tf32(x - __uint_as_float(hi));
}
__device__ __forceinline__ void mma_tf32(float* c, const uint32_t* a,
                                         uint32_t b0, uint32_t b1) {
  asm volatile(
      "mma.sync.aligned.m16n8k8.row.col.f32.tf32.tf32.f32 "
      "{%0,%1,%2,%3}, {%4,%5,%6,%7}, {%8,%9}, {%0,%1,%2,%3};\n"
      : "+f"(c[0]), "+f"(c[1]), "+f"(c[2]), "+f"(c[3])
      : "r"(a[0]), "r"(a[1]), "r"(a[2]), "r"(a[3]), "r"(b0), "r"(b1));
}

// 3-product split-tf32 score tile: c = Q(16xD) . K(8cols x D)^T
__device__ __forceinline__ void score_mma(float* c,
                                          const uint32_t* ahi, const uint32_t* alo,
                                          const uint32_t* __restrict__ Kh,
                                          const uint32_t* __restrict__ Kl,
                                          int cb, int t) {
  c[0] = c[1] = c[2] = c[3] = 0.f;
#pragma unroll
  for (int ks = 0; ks < 4; ks++) {
    const int o = cb + ks * 8 + t;
    uint32_t bh0 = Kh[o], bh1 = Kh[o + 4];
    uint32_t bl0 = Kl[o], bl1 = Kl[o + 4];
    mma_tf32(c, ahi + ks * 4, bh0, bh1);
    mma_tf32(c, ahi + ks * 4, bl0, bl1);
    mma_tf32(c, alo + ks * 4, bh0, bh1);
  }
}

__device__ __forceinline__ float score_of(float cr, float nqv, float nkv,
                                          float mskv, float scale) {
  return fmaf(-scale, fmaxf(nqv + nkv - 2.f * cr, 0.f), mskv);
}

// ---------------------------------------------------------------------------
// Projection GEMM: out = X[4096,768] @ W[384,768]^T + bias -> [bh][s][d] fp32
// sel 0/1/2 also write row norms. Tiles 64x64x16, 256 thr, 4x4 micro-tile.
// ---------------------------------------------------------------------------
__global__ __launch_bounds__(256) void proj_kernel(
    const float* __restrict__ X, const float* __restrict__ W,
    const float* __restrict__ bias, int sel)
{
  __shared__ float As[16][64];
  __shared__ float Bs[16][64];

  const int tid = threadIdx.x;
  const int tx = tid & 15, ty = tid >> 4;
  const int m0 = blockIdx.y * 64, n0 = blockIdx.x * 64;
  const int lr = tid >> 2, lc = (tid & 3) * 4;

  float acc[4][4];
#pragma unroll
  for (int i = 0; i < 4; i++)
#pragma unroll
    for (int j = 0; j < 4; j++) acc[i][j] = 0.f;

  for (int k0 = 0; k0 < kHid; k0 += 16) {
    __syncthreads();
    float4 av = *(const float4*)&X[(size_t)(m0 + lr) * kHid + k0 + lc];
    As[lc + 0][lr] = av.x; As[lc + 1][lr] = av.y;
    As[lc + 2][lr] = av.z; As[lc + 3][lr] = av.w;
    float4 bv = *(const float4*)&W[(size_t)(n0 + lr) * kHid + k0 + lc];
    Bs[lc + 0][lr] = bv.x; Bs[lc + 1][lr] = bv.y;
    Bs[lc + 2][lr] = bv.z; Bs[lc + 3][lr] = bv.w;
    __syncthreads();
#pragma unroll
    for (int kk = 0; kk < 16; kk++) {
      float4 a = *(const float4*)&As[kk][ty * 4];
      float4 b = *(const float4*)&Bs[kk][tx * 4];
      float aa[4] = {a.x, a.y, a.z, a.w};
      float bb[4] = {b.x, b.y, b.z, b.w};
#pragma unroll
      for (int i = 0; i < 4; i++)
#pragma unroll
        for (int j = 0; j < 4; j++)
          acc[i][j] = fmaf(aa[i], bb[j], acc[i][j]);
    }
  }

  float4 bb4 = *(const float4*)&bias[n0 + tx * 4];
  float bvals[4] = {bb4.x, bb4.y, bb4.z, bb4.w};
#pragma unroll
  for (int i = 0; i < 4; i++)
#pragma unroll
    for (int j = 0; j < 4; j++) acc[i][j] += bvals[j];

  float* out = (sel == 0) ? g_q : (sel == 1) ? g_k1 : (sel == 2) ? g_k2 : g_v;
  const int n = n0 + tx * 4;
  const int h = n >> 5, d = n & 31;

#pragma unroll
  for (int i = 0; i < 4; i++) {
    const int m = m0 + ty * 4 + i;
    const int b = m >> 10, s = m & 1023;
    float4 o = make_float4(acc[i][0], acc[i][1], acc[i][2], acc[i][3]);
    *(float4*)&out[(((size_t)b * kH + h) * kS + s) * kD + d] = o;
  }

  if (sel < 3) {
    float* nrm = (sel == 0) ? g_nq : (sel == 1) ? g_nk1 : g_nk2;
    float ps[4];
#pragma unroll
    for (int i = 0; i < 4; i++) {
      ps[i] = 0.f;
#pragma unroll
      for (int j = 0; j < 4; j++) ps[i] = fmaf(acc[i][j], acc[i][j], ps[i]);
    }
    // reduce over the 8 lanes spanning one head (lanes are 8-aligned groups)
#pragma unroll
    for (int i = 0; i < 4; i++) {
#pragma unroll
      for (int o = 1; o < 8; o <<= 1)
        ps[i] += __shfl_xor_sync(0xffffffffu, ps[i], o);
    }
    if ((tx & 7) == 0) {
#pragma unroll
      for (int i = 0; i < 4; i++) {
        const int m = m0 + ty * 4 + i;
        const int b = m >> 10, s = m & 1023;
        nrm[(b * kH + h) * kS + s] = ps[i];
      }
    }
  }
}

// ---------------------------------------------------------------------------
// Fused attention. Block = (128 q rows, one bh). 256 threads, 8 warps.
// Warp w owns score rows 16w..16w+15 via m16n8k8 tf32 fragments.
// ---------------------------------------------------------------------------
__global__ __launch_bounds__(256) void attn_kernel(
    const float* __restrict__ mask, const float* __restrict__ pi,
    float* __restrict__ out_ctx, float* __restrict__ out_probs)
{
  extern __shared__ char smc[];
  float* nqs  = (float*)(smc + OFF_NQ);
  float* nk1s = (float*)(smc + OFF_NK1);
  float* nk2s = (float*)(smc + OFF_NK2);
  float* msk  = (float*)(smc + OFF_MSK);
  float* invs = (float*)(smc + OFF_INV);
  float* Vs   = (float*)(smc + OFF_V);
  uint32_t* K1h = (uint32_t*)(smc + OFF_K1H);
  uint32_t* K1l = (uint32_t*)(smc + OFF_K1L);
  uint32_t* K2h = (uint32_t*)(smc + OFF_K2H);
  uint32_t* K2l = (uint32_t*)(smc + OFF_K2L);
  float* Es   = (float*)(smc + OFF_ES);

  const int tid = threadIdx.x;
  const int w = tid >> 5, lane = tid & 31;
  const int g = lane >> 2, t = lane & 3;
  const int R0 = w * 16 + g, R1 = R0 + 8;

  const int qt = blockIdx.x, bh = blockIdx.y;
  const int b = bh / kH, h = bh % kH;
  const int q0 = qt * 128;
  const int nbase = bh * kS;
  const size_t gbase = (size_t)bh * kS * kD;

  const float pi0 = fminf(fmaxf(pi[h],      1e-6f), 2.0f);
  const float pi1 = fminf(fmaxf(pi[kH + h], 1e-6f), 2.0f);

  // ---- stage Q (aliased onto Es region) and build persistent A fragments ----
  {
    float* qstage = Es;   // [128][33]
    for (int idx = tid; idx < 1024; idx += 256) {
      const int j = idx >> 3, dg = (idx & 7) * 4;
      float4 v = *(const float4*)&g_q[gbase + (size_t)(q0 + j) * kD + dg];
      qstage[j * 33 + dg + 0] = v.x; qstage[j * 33 + dg + 1] = v.y;
      qstage[j * 33 + dg + 2] = v.z; qstage[j * 33 + dg + 3] = v.w;
    }
    if (tid < 128) nqs[tid] = g_nq[nbase + q0 + tid];
  }
  __syncthreads();

  uint32_t ahi[16], alo[16];
  {
    float* qstage = Es;
#pragma unroll
    for (int ks = 0; ks < 4; ks++) {
      float a0 = qstage[R0 * 33 + ks * 8 + t];
      float a1 = qstage[R1 * 33 + ks * 8 + t];
      float a2 = qstage[R0 * 33 + ks * 8 + t + 4];
      float a3 = qstage[R1 * 33 + ks * 8 + t + 4];
      split_tf32(a0, ahi[ks * 4 + 0], alo[ks * 4 + 0]);
      split_tf32(a1, ahi[ks * 4 + 1], alo[ks * 4 + 1]);
      split_tf32(a2, ahi[ks * 4 + 2], alo[ks * 4 + 2]);
      split_tf32(a3, ahi[ks * 4 + 3], alo[ks * 4 + 3]);
    }
  }
  const float nq0 = nqs[R0], nq1 = nqs[R1];
  __syncthreads();

#define LOAD_KT(j0, WITHV)                                                     \
  {                                                                            \
    for (int idx = tid; idx < 1024; idx += 256) {                              \
      const int j = idx >> 3, dg = (idx & 7) * 4;                              \
      float4 v1 = *(const float4*)&g_k1[gbase + (size_t)((j0) + j) * kD + dg]; \
      float4 v2 = *(const float4*)&g_k2[gbase + (size_t)((j0) + j) * kD + dg]; \
      uint4 h1, l1, h2, l2;                                                    \
      split_tf32(v1.x, h1.x, l1.x); split_tf32(v1.y, h1.y, l1.y);              \
      split_tf32(v1.z, h1.z, l1.z); split_tf32(v1.w, h1.w, l1.w);              \
      split_tf32(v2.x, h2.x, l2.x); split_tf32(v2.y, h2.y, l2.y);              \
      split_tf32(v2.z, h2.z, l2.z); split_tf32(v2.w, h2.w, l2.w);              \
      const int so = j * 36 + dg;                                              \
      *(uint4*)&K1h[so] = h1; *(uint4*)&K1l[so] = l1;                          \
      *(uint4*)&K2h[so] = h2; *(uint4*)&K2l[so] = l2;                          \
      if (WITHV) {                                                             \
        float4 vv = *(const float4*)&g_v[gbase + (size_t)((j0) + j) * kD + dg];\
        *(float4*)&Vs[j * 32 + dg] = vv;                                       \
      }                                                                        \
    }                                                                          \
    if (tid < 128) {                                                           \
      nk1s[tid] = g_nk1[nbase + (j0) + tid];                                   \
      nk2s[tid] = g_nk2[nbase + (j0) + tid];                                   \
      msk[tid]  = mask[b * kS + (j0) + tid];                                   \
    }                                                                          \
  }

  // ================= pass 1: exact row maxes =================
  float m1r0 = -1e30f, m1r1 = -1e30f, m2r0 = -1e30f, m2r1 = -1e30f;
  for (int kt = 0; kt < 8; kt++) {
    __syncthreads();
    LOAD_KT(kt * 128, false)
    __syncthreads();
#pragma unroll 2
    for (int nt = 0; nt < 16; nt++) {
      const int n0 = nt * 8;
      const int cb = (n0 + g) * 36;
      const int col0 = n0 + 2 * t, col1 = col0 + 1;
      const float mk0 = msk[col0], mk1 = msk[col1];
      float c[4];
      score_mma(c, ahi, alo, K1h, K1l, cb, t);
      {
        const float k0v = nk1s[col0], k1v = nk1s[col1];
        m1r0 = fmaxf(m1r0, fmaxf(score_of(c[0], nq0, k0v, mk0, kC1),
                                 score_of(c[1], nq0, k1v, mk1, kC1)));
        m1r1 = fmaxf(m1r1, fmaxf(score_of(c[2], nq1, k0v, mk0, kC1),
                                 score_of(c[3], nq1, k1v, mk1, kC1)));
      }
      score_mma(c, ahi, alo, K2h, K2l, cb, t);
      {
        const float k0v = nk2s[col0], k1v = nk2s[col1];
        m2r0 = fmaxf(m2r0, fmaxf(score_of(c[0], nq0, k0v, mk0, kC2),
                                 score_of(c[1], nq0, k1v, mk1, kC2)));
        m2r1 = fmaxf(m2r1, fmaxf(score_of(c[2], nq1, k0v, mk0, kC2),
                                 score_of(c[3], nq1, k1v, mk1, kC2)));
      }
    }
  }
  // reduce across the quad (4 lanes sharing each row)
#pragma unroll
  for (int o = 1; o < 4; o <<= 1) {
    m1r0 = fmaxf(m1r0, __shfl_xor_sync(0xffffffffu, m1r0, o));
    m1r1 = fmaxf(m1r1, __shfl_xor_sync(0xffffffffu, m1r1, o));
    m2r0 = fmaxf(m2r0, __shfl_xor_sync(0xffffffffu, m2r0, o));
    m2r1 = fmaxf(m2r1, __shfl_xor_sync(0xffffffffu, m2r1, o));
  }

  // ================= pass 2: rowsum + ctx =================
  float rs0 = 0.f, rs1 = 0.f;
  float cacc[4][4];
#pragma unroll
  for (int i = 0; i < 4; i++)
#pragma unroll
    for (int j = 0; j < 4; j++) cacc[i][j] = 0.f;
  const int cm = (tid >> 3) * 4;   // ctx row group
  const int cd = (tid & 7) * 4;    // ctx d group

  for (int kt = 0; kt < 8; kt++) {
    __syncthreads();
    LOAD_KT(kt * 128, true)
    __syncthreads();
#pragma unroll 2
    for (int nt = 0; nt < 16; nt++) {
      const int n0 = nt * 8;
      const int cb = (n0 + g) * 36;
      const int col0 = n0 + 2 * t, col1 = col0 + 1;
      const float mk0 = msk[col0], mk1 = msk[col1];
      float c1[4], c2[4];
      score_mma(c1, ahi, alo, K1h, K1l, cb, t);
      score_mma(c2, ahi, alo, K2h, K2l, cb, t);
      const float a0 = nk1s[col0], a1 = nk1s[col1];
      const float b0 = nk2s[col0], b1 = nk2s[col1];
      float e00 = pi0 * __expf(score_of(c1[0], nq0, a0, mk0, kC1) - m1r0)
                + pi1 * __expf(score_of(c2[0], nq0, b0, mk0, kC2) - m2r0);
      float e01 = pi0 * __expf(score_of(c1[1], nq0, a1, mk1, kC1) - m1r0)
                + pi1 * __expf(score_of(c2[1], nq0, b1, mk1, kC2) - m2r0);
      float e10 = pi0 * __expf(score_of(c1[2], nq1, a0, mk0, kC1) - m1r1)
                + pi1 * __expf(score_of(c2[2], nq1, b0, mk0, kC2) - m2r1);
      float e11 = pi0 * __expf(score_of(c1[3], nq1, a1, mk1, kC1) - m1r1)
                + pi1 * __expf(score_of(c2[3], nq1, b1, mk1, kC2) - m2r1);
      Es[R0 * 129 + col0] = e00; Es[R0 * 129 + col1] = e01;
      Es[R1 * 129 + col0] = e10; Es[R1 * 129 + col1] = e11;
      rs0 += e00 + e01; rs1 += e10 + e11;
    }
    __syncthreads();
    // ctx += E @ V  (fp32 FFMA)
#pragma unroll 4
    for (int jj = 0; jj < 128; jj++) {
      float4 bv = *(const float4*)&Vs[jj * 32 + cd];
      float a0 = Es[(cm + 0) * 129 + jj], a1 = Es[(cm + 1) * 129 + jj];
      float a2 = Es[(cm + 2) * 129 + jj], a3 = Es[(cm + 3) * 129 + jj];
      cacc[0][0] = fmaf(a0, bv.x, cacc[0][0]); cacc[0][1] = fmaf(a0, bv.y, cacc[0][1]);
      cacc[0][2] = fmaf(a0, bv.z, cacc[0][2]); cacc[0][3] = fmaf(a0, bv.w, cacc[0][3]);
      cacc[1][0] = fmaf(a1, bv.x, cacc[1][0]); cacc[1][1] = fmaf(a1, bv.y, cacc[1][1]);
      cacc[1][2] = fmaf(a1, bv.z, cacc[1][2]); cacc[1][3] = fmaf(a1, bv.w, cacc[1][3]);
      cacc[2][0] = fmaf(a2, bv.x, cacc[2][0]); cacc[2][1] = fmaf(a2, bv.y, cacc[2][1]);
      cacc[2][2] = fmaf(a2, bv.z, cacc[2][2]); cacc[2][3] = fmaf(a2, bv.w, cacc[2][3]);
      cacc[3][0] = fmaf(a3, bv.x, cacc[3][0]); cacc[3][1] = fmaf(a3, bv.y, cacc[3][1]);
      cacc[3][2] = fmaf(a3, bv.z, cacc[3][2]); cacc[3][3] = fmaf(a3, bv.w, cacc[3][3]);
    }
  }
  // quad-reduce rowsums; all quad lanes end with the full sum
#pragma unroll
  for (int o = 1; o < 4; o <<= 1) {
    rs0 += __shfl_xor_sync(0xffffffffu, rs0, o);
    rs1 += __shfl_xor_sync(0xffffffffu, rs1, o);
  }
  const float inv0 = 1.0f / (rs0 + 1e-6f);
  const float inv1 = 1.0f / (rs1 + 1e-6f);
  if (t == 0) { invs[R0] = inv0; invs[R1] = inv1; }
  __syncthreads();

  // write normalized ctx
#pragma unroll
  for (int i = 0; i < 4; i++) {
    const int s = q0 + cm + i;
    const float ivv = invs[cm + i];
    float4 o = make_float4(cacc[i][0] * ivv, cacc[i][1] * ivv,
                           cacc[i][2] * ivv, cacc[i][3] * ivv);
    *(float4*)&out_ctx[((size_t)b * kS + s) * kAH + h * kD + cd] = o;
  }

  // ================= pass 3: normalized probs =================
  for (int kt = 0; kt < 8; kt++) {
    __syncthreads();
    LOAD_KT(kt * 128, false)
    __syncthreads();
#pragma unroll 2
    for (int nt = 0; nt < 16; nt++) {
      const int n0 = nt * 8;
      const int cb = (n0 + g) * 36;
      const int col0 = n0 + 2 * t, col1 = col0 + 1;
      const float mk0 = msk[col0], mk1 = msk[col1];
      float c1[4], c2[4];
      score_mma(c1, ahi, alo, K1h, K1l, cb, t);
      score_mma(c2, ahi, alo, K2h, K2l, cb, t);
      const float a0 = nk1s[col0], a1 = nk1s[col1];
      const float b0 = nk2s[col0], b1 = nk2s[col1];
      Es[R0 * 129 + col0] = inv0 *
          (pi0 * __expf(score_of(c1[0], nq0, a0, mk0, kC1) - m1r0)
         + pi1 * __expf(score_of(c2[0], nq0, b0, mk0, kC2) - m2r0));
      Es[R0 * 129 + col1] = inv0 *
          (pi0 * __expf(score_of(c1[1], nq0, a1, mk1, kC1) - m1r0)
         + pi1 * __expf(score_of(c2[1], nq0, b1, mk1, kC2) - m2r0));
      Es[R1 * 129 + col0] = inv1 *
          (pi0 * __expf(score_of(c1[2], nq1, a0, mk0, kC1) - m1r1)
         + pi1 * __expf(score_of(c2[2], nq1, b0, mk0, kC2) - m2r1));
      Es[R1 * 129 + col1] = inv1 *
          (pi0 * __expf(score_of(c1[3], nq1, a1, mk1, kC1) - m1r1)
         + pi1 * __expf(score_of(c2[3], nq1, b1, mk1, kC2) - m2r1));
    }
    __syncthreads();
    // coalesced probs store
    for (int idx = tid; idx < 128 * 128; idx += 256) {
      const int rr = idx >> 7, cc = idx & 127;
      out_probs[((size_t)bh * kS + q0 + rr) * kS + kt * 128 + cc] = Es[rr * 129 + cc];
    }
  }
#undef LOAD_KT
}

// ---------------------------------------------------------------------------
extern "C" void kernel_launch(void* const* d_in, const int* in_sizes, int n_in,
                              void* d_out, int out_size) {
  (void)in_sizes; (void)n_in; (void)out_size;
  const float* hs   = (const float*)d_in[0];
  const float* mask = (const float*)d_in[1];
  const float* Wq   = (const float*)d_in[2];
  const float* bq   = (const float*)d_in[3];
  const float* Wk1  = (const float*)d_in[4];
  const float* bk1  = (const float*)d_in[5];
  const float* Wk2  = (const float*)d_in[6];
  const float* bk2  = (const float*)d_in[7];
  const float* Wv   = (const float*)d_in[8];
  const float* bv   = (const float*)d_in[9];
  const float* pi   = (const float*)d_in[10];

  float* out_ctx   = (float*)d_out;
  float* out_probs = out_ctx + (size_t)kB * kS * kAH;

  cudaFuncSetAttribute(attn_kernel, cudaFuncAttributeMaxDynamicSharedMemorySize,
                       kSmemBytes);

  dim3 pgrid(kAH / 64, (kB * kS) / 64);   // (6, 64)
  proj_kernel<<<pgrid, 256>>>(hs, Wq,  bq,  0);
  proj_kernel<<<pgrid, 256>>>(hs, Wk1, bk1, 1);
  proj_kernel<<<pgrid, 256>>>(hs, Wk2, bk2, 2);
  proj_kernel<<<pgrid, 256>>>(hs, Wv,  bv,  3);
  attn_kernel<<<dim3(kS / 128, kBH), 256, kSmemBytes>>>(
      mask, pi, out_ctx, out_probs);
}

// round 6
// speedup vs baseline: 1.3659x; 1.1929x over previous
#include <cuda_runtime.h>
#include <cstdint>

// ---------------------------------------------------------------------------
// MGKBertSelfAttention: B=4, S=1024, HID=768, H=12, D=32, AH=384
// out = [ctx (B,S,AH) ; probs (B,H,S,S)]  fp32
// Scores via split-TF32 mma.sync (3-product, fp32-equivalent precision).
// 2-pass attention (max, then exp+EV+unnormalized-probs) + stream normalize.
// ---------------------------------------------------------------------------

namespace {
constexpr int kB = 4, kS = 1024, kHid = 768, kH = 12, kD = 32, kAH = 384;
constexpr int kBH = kB * kH;                       // 48
constexpr float kScaling = 0.17677669529663687f;   // 32^-0.5
constexpr float kC1 = 0.5f * kScaling;
constexpr float kC2 = 0.75f * kScaling;

// smem layout (bytes)
constexpr int OFF_NQ  = 0;
constexpr int OFF_NK1 = 512;
constexpr int OFF_NK2 = 1024;
constexpr int OFF_MSK = 1536;
constexpr int OFF_INV = 2048;
constexpr int OFF_V   = 2560;                       // 128*32*4 = 16384
constexpr int OFF_K1H = OFF_V + 16384;              // each K tile 128*36*4 = 18432
constexpr int OFF_K1L = OFF_K1H + 18432;
constexpr int OFF_K2H = OFF_K1L + 18432;
constexpr int OFF_K2L = OFF_K2H + 18432;
constexpr int OFF_ES  = OFF_K2L + 18432;            // 128*132*4 = 67584 (Q stage aliases)
constexpr int kSmemBytes = OFF_ES + 128 * 132 * 4;  // 160256
}

// Scratch (device globals; allocation is forbidden)
__device__ float    g_q  [kBH * kS * kD];   // fp32 [bh][s][d]
__device__ uint32_t g_k1h[kBH * kS * kD];   // tf32 hi
__device__ uint32_t g_k1l[kBH * kS * kD];   // tf32 lo
__device__ uint32_t g_k2h[kBH * kS * kD];
__device__ uint32_t g_k2l[kBH * kS * kD];
__device__ float    g_v  [kBH * kS * kD];
__device__ float    g_nq [kBH * kS];
__device__ float    g_nk1[kBH * kS];
__device__ float    g_nk2[kBH * kS];
__device__ float    g_inv[kBH * kS];

// ---------------------------------------------------------------------------
// tf32 helpers
// ---------------------------------------------------------------------------
__device__ __forceinline__ uint32_t f2tf32(float x) {
  uint32_t u;
  asm("cvt.rna.tf32.f32 %0, %1;" : "=r"(u) : "f"(x));
  return u;
}
__device__ __forceinline__ void split_tf32(float x, uint32_t& hi, uint32_t& lo) {
  hi = f2tf32(x);
  lo = f2tf32(x - __uint_as_float(hi));
}
__device__ __forceinline__ void mma_tf32(float* c, const uint32_t* a,
                                         uint32_t b0, uint32_t b1) {
  asm volatile(
      "mma.sync.aligned.m16n8k8.row.col.f32.tf32.tf32.f32 "
      "{%0,%1,%2,%3}, {%4,%5,%6,%7}, {%8,%9}, {%0,%1,%2,%3};\n"
      : "+f"(c[0]), "+f"(c[1]), "+f"(c[2]), "+f"(c[3])
      : "r"(a[0]), "r"(a[1]), "r"(a[2]), "r"(a[3]), "r"(b0), "r"(b1));
}

// 3-product split-tf32 score tile: c = Q(16 rows x D) . K(8 cols x D)^T
__device__ __forceinline__ void score_mma(float* c,
                                          const uint32_t* ahi, const uint32_t* alo,
                                          const uint32_t* __restrict__ Kh,
                                          const uint32_t* __restrict__ Kl,
                                          int cb, int t) {
  c[0] = c[1] = c[2] = c[3] = 0.f;
#pragma unroll
  for (int ks = 0; ks < 4; ks++) {
    const int o = cb + ks * 8 + t;
    uint32_t bh0 = Kh[o], bh1 = Kh[o + 4];
    uint32_t bl0 = Kl[o], bl1 = Kl[o + 4];
    mma_tf32(c, ahi + ks * 4, bh0, bh1);
    mma_tf32(c, ahi + ks * 4, bl0, bl1);
    mma_tf32(c, alo + ks * 4, bh0, bh1);
  }
}

__device__ __forceinline__ float score_of(float cr, float nqv, float nkv,
                                          float mskv, float scale) {
  return fmaf(-scale, fmaxf(nqv + nkv - 2.f * cr, 0.f), mskv);
}

// ---------------------------------------------------------------------------
// Projection GEMM (all 4 in one launch, sel = blockIdx.z):
//   out = X[4096,768] @ W[384,768]^T + bias
// sel 0 -> g_q fp32 + norms; sel 1/2 -> K split hi/lo tf32 + norms; sel 3 -> V.
// ---------------------------------------------------------------------------
__global__ __launch_bounds__(256) void proj_kernel(
    const float* __restrict__ X,
    const float* __restrict__ Wq,  const float* __restrict__ bq,
    const float* __restrict__ Wk1, const float* __restrict__ bk1,
    const float* __restrict__ Wk2, const float* __restrict__ bk2,
    const float* __restrict__ Wv,  const float* __restrict__ bv)
{
  __shared__ float As[16][64];
  __shared__ float Bs[16][64];

  const int sel = blockIdx.z;
  const float* W    = (sel == 0) ? Wq : (sel == 1) ? Wk1 : (sel == 2) ? Wk2 : Wv;
  const float* bias = (sel == 0) ? bq : (sel == 1) ? bk1 : (sel == 2) ? bk2 : bv;

  const int tid = threadIdx.x;
  const int tx = tid & 15, ty = tid >> 4;
  const int m0 = blockIdx.y * 64, n0 = blockIdx.x * 64;
  const int lr = tid >> 2, lc = (tid & 3) * 4;

  float acc[4][4];
#pragma unroll
  for (int i = 0; i < 4; i++)
#pragma unroll
    for (int j = 0; j < 4; j++) acc[i][j] = 0.f;

  for (int k0 = 0; k0 < kHid; k0 += 16) {
    __syncthreads();
    float4 av = *(const float4*)&X[(size_t)(m0 + lr) * kHid + k0 + lc];
    As[lc + 0][lr] = av.x; As[lc + 1][lr] = av.y;
    As[lc + 2][lr] = av.z; As[lc + 3][lr] = av.w;
    float4 bvv = *(const float4*)&W[(size_t)(n0 + lr) * kHid + k0 + lc];
    Bs[lc + 0][lr] = bvv.x; Bs[lc + 1][lr] = bvv.y;
    Bs[lc + 2][lr] = bvv.z; Bs[lc + 3][lr] = bvv.w;
    __syncthreads();
#pragma unroll
    for (int kk = 0; kk < 16; kk++) {
      float4 a = *(const float4*)&As[kk][ty * 4];
      float4 b = *(const float4*)&Bs[kk][tx * 4];
      float aa[4] = {a.x, a.y, a.z, a.w};
      float bb[4] = {b.x, b.y, b.z, b.w};
#pragma unroll
      for (int i = 0; i < 4; i++)
#pragma unroll
        for (int j = 0; j < 4; j++)
          acc[i][j] = fmaf(aa[i], bb[j], acc[i][j]);
    }
  }

  float4 bb4 = *(const float4*)&bias[n0 + tx * 4];
  float bvals[4] = {bb4.x, bb4.y, bb4.z, bb4.w};
#pragma unroll
  for (int i = 0; i < 4; i++)
#pragma unroll
    for (int j = 0; j < 4; j++) acc[i][j] += bvals[j];

  const int n = n0 + tx * 4;
  const int h = n >> 5, d = n & 31;

  if (sel == 0 || sel == 3) {
    float* out = (sel == 0) ? g_q : g_v;
#pragma unroll
    for (int i = 0; i < 4; i++) {
      const int m = m0 + ty * 4 + i;
      const int b = m >> 10, s = m & 1023;
      float4 o = make_float4(acc[i][0], acc[i][1], acc[i][2], acc[i][3]);
      *(float4*)&out[(((size_t)b * kH + h) * kS + s) * kD + d] = o;
    }
  } else {
    uint32_t* outh = (sel == 1) ? g_k1h : g_k2h;
    uint32_t* outl = (sel == 1) ? g_k1l : g_k2l;
#pragma unroll
    for (int i = 0; i < 4; i++) {
      const int m = m0 + ty * 4 + i;
      const int b = m >> 10, s = m & 1023;
      uint4 hv, lv;
      split_tf32(acc[i][0], hv.x, lv.x);
      split_tf32(acc[i][1], hv.y, lv.y);
      split_tf32(acc[i][2], hv.z, lv.z);
      split_tf32(acc[i][3], hv.w, lv.w);
      const size_t o = (((size_t)b * kH + h) * kS + s) * kD + d;
      *(uint4*)&outh[o] = hv;
      *(uint4*)&outl[o] = lv;
    }
  }

  if (sel < 3) {
    float* nrm = (sel == 0) ? g_nq : (sel == 1) ? g_nk1 : g_nk2;
    float ps[4];
#pragma unroll
    for (int i = 0; i < 4; i++) {
      ps[i] = 0.f;
#pragma unroll
      for (int j = 0; j < 4; j++) ps[i] = fmaf(acc[i][j], acc[i][j], ps[i]);
    }
#pragma unroll
    for (int i = 0; i < 4; i++) {
#pragma unroll
      for (int o = 1; o < 8; o <<= 1)
        ps[i] += __shfl_xor_sync(0xffffffffu, ps[i], o);
    }
    if ((tx & 7) == 0) {
#pragma unroll
      for (int i = 0; i < 4; i++) {
        const int m = m0 + ty * 4 + i;
        const int b = m >> 10, s = m & 1023;
        nrm[(b * kH + h) * kS + s] = ps[i];
      }
    }
  }
}

// ---------------------------------------------------------------------------
// Fused attention, 2 passes. Block = (128 q rows, one bh). 256 threads.
// Warp w owns score rows 16w..16w+15 via m16n8k8 tf32 fragments.
// ---------------------------------------------------------------------------
__global__ __launch_bounds__(256) void attn_kernel(
    const float* __restrict__ mask, const float* __restrict__ pi,
    float* __restrict__ out_ctx, float* __restrict__ out_probs)
{
  extern __shared__ char smc[];
  float* nqs  = (float*)(smc + OFF_NQ);
  float* nk1s = (float*)(smc + OFF_NK1);
  float* nk2s = (float*)(smc + OFF_NK2);
  float* msk  = (float*)(smc + OFF_MSK);
  float* invs = (float*)(smc + OFF_INV);
  float* Vs   = (float*)(smc + OFF_V);
  uint32_t* K1h = (uint32_t*)(smc + OFF_K1H);
  uint32_t* K1l = (uint32_t*)(smc + OFF_K1L);
  uint32_t* K2h = (uint32_t*)(smc + OFF_K2H);
  uint32_t* K2l = (uint32_t*)(smc + OFF_K2L);
  float* Es   = (float*)(smc + OFF_ES);             // stride 132

  const int tid = threadIdx.x;
  const int w = tid >> 5, lane = tid & 31;
  const int g = lane >> 2, t = lane & 3;
  const int R0 = w * 16 + g, R1 = R0 + 8;

  const int qt = blockIdx.x, bh = blockIdx.y;
  const int b = bh / kH, h = bh % kH;
  const int q0 = qt * 128;
  const int nbase = bh * kS;
  const size_t gbase = (size_t)bh * kS * kD;

  const float pi0 = fminf(fmaxf(pi[h],      1e-6f), 2.0f);
  const float pi1 = fminf(fmaxf(pi[kH + h], 1e-6f), 2.0f);

  // ---- stage Q (aliased onto Es) and build persistent split A fragments ----
  {
    float* qstage = Es;   // [128][33]
    for (int idx = tid; idx < 1024; idx += 256) {
      const int j = idx >> 3, dg = (idx & 7) * 4;
      float4 v = *(const float4*)&g_q[gbase + (size_t)(q0 + j) * kD + dg];
      qstage[j * 33 + dg + 0] = v.x; qstage[j * 33 + dg + 1] = v.y;
      qstage[j * 33 + dg + 2] = v.z; qstage[j * 33 + dg + 3] = v.w;
    }
    if (tid < 128) nqs[tid] = g_nq[nbase + q0 + tid];
  }
  __syncthreads();

  uint32_t ahi[16], alo[16];
  {
    float* qstage = Es;
#pragma unroll
    for (int ks = 0; ks < 4; ks++) {
      float a0 = qstage[R0 * 33 + ks * 8 + t];
      float a1 = qstage[R1 * 33 + ks * 8 + t];
      float a2 = qstage[R0 * 33 + ks * 8 + t + 4];
      float a3 = qstage[R1 * 33 + ks * 8 + t + 4];
      split_tf32(a0, ahi[ks * 4 + 0], alo[ks * 4 + 0]);
      split_tf32(a1, ahi[ks * 4 + 1], alo[ks * 4 + 1]);
      split_tf32(a2, ahi[ks * 4 + 2], alo[ks * 4 + 2]);
      split_tf32(a3, ahi[ks * 4 + 3], alo[ks * 4 + 3]);
    }
  }
  const float nq0 = nqs[R0], nq1 = nqs[R1];
  __syncthreads();

#define LOAD_KT(j0, WITHV)                                                     \
  {                                                                            \
    const size_t gk = gbase + (size_t)(j0) * kD;                               \
    for (int idx = tid; idx < 1024; idx += 256) {                              \
      const int j = idx >> 3, dg = (idx & 7) * 4;                              \
      const size_t go = gk + (size_t)j * kD + dg;                              \
      const int so = j * 36 + dg;                                              \
      *(uint4*)&K1h[so] = *(const uint4*)&g_k1h[go];                           \
      *(uint4*)&K1l[so] = *(const uint4*)&g_k1l[go];                           \
      *(uint4*)&K2h[so] = *(const uint4*)&g_k2h[go];                           \
      *(uint4*)&K2l[so] = *(const uint4*)&g_k2l[go];                           \
      if (WITHV)                                                               \
        *(float4*)&Vs[j * 32 + dg] = *(const float4*)&g_v[go];                 \
    }                                                                          \
    if (tid < 128) {                                                           \
      nk1s[tid] = g_nk1[nbase + (j0) + tid];                                   \
      nk2s[tid] = g_nk2[nbase + (j0) + tid];                                   \
      msk[tid]  = mask[b * kS + (j0) + tid];                                   \
    }                                                                          \
  }

  // ================= pass 1: exact row maxes (no exp) =================
  float m1r0 = -1e30f, m1r1 = -1e30f, m2r0 = -1e30f, m2r1 = -1e30f;
  for (int kt = 0; kt < 8; kt++) {
    __syncthreads();
    LOAD_KT(kt * 128, false)
    __syncthreads();
#pragma unroll 2
    for (int nt = 0; nt < 16; nt++) {
      const int n0 = nt * 8;
      const int cb = (n0 + g) * 36;
      const int col0 = n0 + 2 * t, col1 = col0 + 1;
      const float mk0 = msk[col0], mk1 = msk[col1];
      float c[4];
      score_mma(c, ahi, alo, K1h, K1l, cb, t);
      {
        const float k0v = nk1s[col0], k1v = nk1s[col1];
        m1r0 = fmaxf(m1r0, fmaxf(score_of(c[0], nq0, k0v, mk0, kC1),
                                 score_of(c[1], nq0, k1v, mk1, kC1)));
        m1r1 = fmaxf(m1r1, fmaxf(score_of(c[2], nq1, k0v, mk0, kC1),
                                 score_of(c[3], nq1, k1v, mk1, kC1)));
      }
      score_mma(c, ahi, alo, K2h, K2l, cb, t);
      {
        const float k0v = nk2s[col0], k1v = nk2s[col1];
        m2r0 = fmaxf(m2r0, fmaxf(score_of(c[0], nq0, k0v, mk0, kC2),
                                 score_of(c[1], nq0, k1v, mk1, kC2)));
        m2r1 = fmaxf(m2r1, fmaxf(score_of(c[2], nq1, k0v, mk0, kC2),
                                 score_of(c[3], nq1, k1v, mk1, kC2)));
      }
    }
  }
#pragma unroll
  for (int o = 1; o < 4; o <<= 1) {
    m1r0 = fmaxf(m1r0, __shfl_xor_sync(0xffffffffu, m1r0, o));
    m1r1 = fmaxf(m1r1, __shfl_xor_sync(0xffffffffu, m1r1, o));
    m2r0 = fmaxf(m2r0, __shfl_xor_sync(0xffffffffu, m2r0, o));
    m2r1 = fmaxf(m2r1, __shfl_xor_sync(0xffffffffu, m2r1, o));
  }

  // ========= pass 2: exp + rowsum + ctx + unnormalized probs =========
  float rs0 = 0.f, rs1 = 0.f;
  float cacc[4][4];
#pragma unroll
  for (int i = 0; i < 4; i++)
#pragma unroll
    for (int j = 0; j < 4; j++) cacc[i][j] = 0.f;
  const int cm = (tid >> 3) * 4;   // ctx row group
  const int cd = (tid & 7) * 4;    // ctx d group

  for (int kt = 0; kt < 8; kt++) {
    __syncthreads();
    LOAD_KT(kt * 128, true)
    __syncthreads();
#pragma unroll 2
    for (int nt = 0; nt < 16; nt++) {
      const int n0 = nt * 8;
      const int cb = (n0 + g) * 36;
      const int col0 = n0 + 2 * t, col1 = col0 + 1;
      const float mk0 = msk[col0], mk1 = msk[col1];
      float c1[4], c2[4];
      score_mma(c1, ahi, alo, K1h, K1l, cb, t);
      score_mma(c2, ahi, alo, K2h, K2l, cb, t);
      const float a0 = nk1s[col0], a1 = nk1s[col1];
      const float b0 = nk2s[col0], b1 = nk2s[col1];
      float e00 = pi0 * __expf(score_of(c1[0], nq0, a0, mk0, kC1) - m1r0)
                + pi1 * __expf(score_of(c2[0], nq0, b0, mk0, kC2) - m2r0);
      float e01 = pi0 * __expf(score_of(c1[1], nq0, a1, mk1, kC1) - m1r0)
                + pi1 * __expf(score_of(c2[1], nq0, b1, mk1, kC2) - m2r0);
      float e10 = pi0 * __expf(score_of(c1[2], nq1, a0, mk0, kC1) - m1r1)
                + pi1 * __expf(score_of(c2[2], nq1, b0, mk0, kC2) - m2r1);
      float e11 = pi0 * __expf(score_of(c1[3], nq1, a1, mk1, kC1) - m1r1)
                + pi1 * __expf(score_of(c2[3], nq1, b1, mk1, kC2) - m2r1);
      Es[R0 * 132 + col0] = e00; Es[R0 * 132 + col1] = e01;
      Es[R1 * 132 + col0] = e10; Es[R1 * 132 + col1] = e11;
      rs0 += e00 + e01; rs1 += e10 + e11;
    }
    __syncthreads();
    // unnormalized probs store (float4, coalesced)
    for (int idx = tid; idx < 128 * 32; idx += 256) {
      const int rr = idx >> 5, c4 = (idx & 31) * 4;
      float4 v = *(const float4*)&Es[rr * 132 + c4];
      *(float4*)&out_probs[((size_t)bh * kS + q0 + rr) * kS + kt * 128 + c4] = v;
    }
    // ctx += E @ V  (fp32 FFMA)
#pragma unroll 4
    for (int jj = 0; jj < 128; jj++) {
      float4 bv = *(const float4*)&Vs[jj * 32 + cd];
      float a0 = Es[(cm + 0) * 132 + jj], a1 = Es[(cm + 1) * 132 + jj];
      float a2 = Es[(cm + 2) * 132 + jj], a3 = Es[(cm + 3) * 132 + jj];
      cacc[0][0] = fmaf(a0, bv.x, cacc[0][0]); cacc[0][1] = fmaf(a0, bv.y, cacc[0][1]);
      cacc[0][2] = fmaf(a0, bv.z, cacc[0][2]); cacc[0][3] = fmaf(a0, bv.w, cacc[0][3]);
      cacc[1][0] = fmaf(a1, bv.x, cacc[1][0]); cacc[1][1] = fmaf(a1, bv.y, cacc[1][1]);
      cacc[1][2] = fmaf(a1, bv.z, cacc[1][2]); cacc[1][3] = fmaf(a1, bv.w, cacc[1][3]);
      cacc[2][0] = fmaf(a2, bv.x, cacc[2][0]); cacc[2][1] = fmaf(a2, bv.y, cacc[2][1]);
      cacc[2][2] = fmaf(a2, bv.z, cacc[2][2]); cacc[2][3] = fmaf(a2, bv.w, cacc[2][3]);
      cacc[3][0] = fmaf(a3, bv.x, cacc[3][0]); cacc[3][1] = fmaf(a3, bv.y, cacc[3][1]);
      cacc[3][2] = fmaf(a3, bv.z, cacc[3][2]); cacc[3][3] = fmaf(a3, bv.w, cacc[3][3]);
    }
  }
  // quad-reduce rowsums
#pragma unroll
  for (int o = 1; o < 4; o <<= 1) {
    rs0 += __shfl_xor_sync(0xffffffffu, rs0, o);
    rs1 += __shfl_xor_sync(0xffffffffu, rs1, o);
  }
  const float inv0 = 1.0f / (rs0 + 1e-6f);
  const float inv1 = 1.0f / (rs1 + 1e-6f);
  if (t == 0) {
    invs[R0] = inv0; invs[R1] = inv1;
    g_inv[nbase + q0 + R0] = inv0;
    g_inv[nbase + q0 + R1] = inv1;
  }
  __syncthreads();

  // write normalized ctx
#pragma unroll
  for (int i = 0; i < 4; i++) {
    const int s = q0 + cm + i;
    const float ivv = invs[cm + i];
    float4 o = make_float4(cacc[i][0] * ivv, cacc[i][1] * ivv,
                           cacc[i][2] * ivv, cacc[i][3] * ivv);
    *(float4*)&out_ctx[((size_t)b * kS + s) * kAH + h * kD + cd] = o;
  }
#undef LOAD_KT
}

// ---------------------------------------------------------------------------
// Stream normalize: probs[row][:] *= g_inv[row]. One block per row.
// ---------------------------------------------------------------------------
__global__ __launch_bounds__(256) void norm_probs_kernel(float* __restrict__ probs) {
  const int row = blockIdx.x;                  // bh*kS + s, 0..49151
  const float inv = g_inv[row];
  float4* p = (float4*)(probs + (size_t)row * kS);
  float4 v = p[threadIdx.x];
  v.x *= inv; v.y *= inv; v.z *= inv; v.w *= inv;
  p[threadIdx.x] = v;
}

// ---------------------------------------------------------------------------
extern "C" void kernel_launch(void* const* d_in, const int* in_sizes, int n_in,
                              void* d_out, int out_size) {
  (void)in_sizes; (void)n_in; (void)out_size;
  const float* hs   = (const float*)d_in[0];
  const float* mask = (const float*)d_in[1];
  const float* Wq   = (const float*)d_in[2];
  const float* bq   = (const float*)d_in[3];
  const float* Wk1  = (const float*)d_in[4];
  const float* bk1  = (const float*)d_in[5];
  const float* Wk2  = (const float*)d_in[6];
  const float* bk2  = (const float*)d_in[7];
  const float* Wv   = (const float*)d_in[8];
  const float* bv   = (const float*)d_in[9];
  const float* pi   = (const float*)d_in[10];

  float* out_ctx   = (float*)d_out;
  float* out_probs = out_ctx + (size_t)kB * kS * kAH;

  cudaFuncSetAttribute(attn_kernel, cudaFuncAttributeMaxDynamicSharedMemorySize,
                       kSmemBytes);

  dim3 pgrid(kAH / 64, (kB * kS) / 64, 4);   // (6, 64, 4) = 1536 CTAs
  proj_kernel<<<pgrid, 256>>>(hs, Wq, bq, Wk1, bk1, Wk2, bk2, Wv, bv);
  attn_kernel<<<dim3(kS / 128, kBH), 256, kSmemBytes>>>(
      mask, pi, out_ctx, out_probs);
  norm_probs_kernel<<<kBH * kS, 256>>>(out_probs);
}

// round 7
// speedup vs baseline: 3.0616x; 2.2415x over previous
#include <cuda_runtime.h>
#include <cuda_bf16.h>
#include <cstdint>

// ---------------------------------------------------------------------------
// MGKBertSelfAttention: B=4, S=1024, HID=768, H=12, D=32, AH=384
// out = [ctx (B,S,AH) ; probs (B,H,S,S)]  fp32
// Everything heavy on mma.sync m16n8k16 bf16 with 2-term hi/lo split
// (3-product reconstruction => fp32-equivalent precision, residual ~2^-18).
// ---------------------------------------------------------------------------

namespace {
constexpr int kB = 4, kS = 1024, kHid = 768, kH = 12, kD = 32, kAH = 384;
constexpr int kBH = kB * kH;                       // 48
constexpr float kScaling = 0.17677669529663687f;   // 32^-0.5
constexpr float kC1 = 0.5f * kScaling;
constexpr float kC2 = 0.75f * kScaling;

// attn smem layout (u32 units)
constexpr int U_NQ  = 0;     // 128 f32
constexpr int U_NK1 = 128;
constexpr int U_NK2 = 256;
constexpr int U_MSK = 384;
constexpr int U_K1H = 512;   // K tiles: [128][20] u32 each (stride-20 pad)
constexpr int U_K1L = U_K1H + 2560;
constexpr int U_K2H = U_K1L + 2560;
constexpr int U_K2L = U_K2H + 2560;
constexpr int U_VTH = U_K2L + 2560;   // Vt packed: [32][68] u32
constexpr int U_VTL = U_VTH + 2176;
constexpr int kAttnSmemU32 = U_VTL + 2176;          // 15104 u32
constexpr int kAttnSmemBytes = kAttnSmemU32 * 4;    // 60416 B
}

// Scratch (device globals; allocation is forbidden)
__device__ float    g_q  [kBH * kS * kD];   // fp32 [bh][s][d]
__device__ float    g_v  [kBH * kS * kD];   // fp32 [bh][s][d]
__device__ uint32_t g_k1h[kBH * kS * 16];   // bf16x2 pairs along d
__device__ uint32_t g_k1l[kBH * kS * 16];
__device__ uint32_t g_k2h[kBH * kS * 16];
__device__ uint32_t g_k2l[kBH * kS * 16];
__device__ float    g_nq [kBH * kS];
__device__ float    g_nk1[kBH * kS];
__device__ float    g_nk2[kBH * kS];

// ---------------------------------------------------------------------------
// bf16 split helpers
// ---------------------------------------------------------------------------
__device__ __forceinline__ void split2(float x, float y, uint32_t& h, uint32_t& l) {
  __nv_bfloat16 bx = __float2bfloat16_rn(x);
  __nv_bfloat16 by = __float2bfloat16_rn(y);
  float rx = x - __bfloat162float(bx);
  float ry = y - __bfloat162float(by);
  __nv_bfloat16 lx = __float2bfloat16_rn(rx);
  __nv_bfloat16 ly = __float2bfloat16_rn(ry);
  h = (uint32_t)__bfloat16_as_ushort(bx) | ((uint32_t)__bfloat16_as_ushort(by) << 16);
  l = (uint32_t)__bfloat16_as_ushort(lx) | ((uint32_t)__bfloat16_as_ushort(ly) << 16);
}

__device__ __forceinline__ void mma_bf16(float* c, const uint32_t* a,
                                         uint32_t b0, uint32_t b1) {
  asm volatile(
      "mma.sync.aligned.m16n8k16.row.col.f32.bf16.bf16.f32 "
      "{%0,%1,%2,%3}, {%4,%5,%6,%7}, {%8,%9}, {%0,%1,%2,%3};\n"
      : "+f"(c[0]), "+f"(c[1]), "+f"(c[2]), "+f"(c[3])
      : "r"(a[0]), "r"(a[1]), "r"(a[2]), "r"(a[3]), "r"(b0), "r"(b1));
}

__device__ __forceinline__ float score_of(float cr, float nqv, float nkv,
                                          float mskv, float scale) {
  return fmaf(-scale, fmaxf(nqv + nkv - 2.f * cr, 0.f), mskv);
}

// ---------------------------------------------------------------------------
// Projection GEMM on tensor cores: C[4096,384] = X @ W^T + bias.
// CTA 128(M)x64(N), 256 thr, warp grid 4x2 (warp tile 32x32), K chunks of 32.
// sel = blockIdx.z: 0->g_q fp32 + norms; 1/2 -> split-packed K + norms; 3 -> g_v.
// ---------------------------------------------------------------------------
__global__ __launch_bounds__(256) void proj_kernel(
    const float* __restrict__ X,
    const float* __restrict__ Wq,  const float* __restrict__ bq,
    const float* __restrict__ Wk1, const float* __restrict__ bk1,
    const float* __restrict__ Wk2, const float* __restrict__ bk2,
    const float* __restrict__ Wv,  const float* __restrict__ bv)
{
  __shared__ uint32_t Ah[128 * 20], Al[128 * 20];
  __shared__ uint32_t Bh[64 * 20],  Bl[64 * 20];

  const int sel = blockIdx.z;
  const float* W    = (sel == 0) ? Wq : (sel == 1) ? Wk1 : (sel == 2) ? Wk2 : Wv;
  const float* bias = (sel == 0) ? bq : (sel == 1) ? bk1 : (sel == 2) ? bk2 : bv;

  const int tid = threadIdx.x;
  const int w = tid >> 5, lane = tid & 31;
  const int g = lane >> 2, t = lane & 3;
  const int wm = (w & 3) * 32, wn = (w >> 2) * 32;
  const int m0 = blockIdx.y * 128, n0 = blockIdx.x * 64;

  float c[2][4][4];
#pragma unroll
  for (int i = 0; i < 2; i++)
#pragma unroll
    for (int j = 0; j < 4; j++)
#pragma unroll
      for (int k = 0; k < 4; k++) c[i][j][k] = 0.f;

  const int sq = tid & 7, sr = tid >> 3;          // stage: quad, row-base

  for (int k0 = 0; k0 < kHid; k0 += 32) {
    __syncthreads();
    // stage X[128][32] split-packed
#pragma unroll
    for (int r = sr; r < 128; r += 32) {
      float4 v = *(const float4*)&X[(size_t)(m0 + r) * kHid + k0 + sq * 4];
      uint32_t h0, l0, h1, l1;
      split2(v.x, v.y, h0, l0);
      split2(v.z, v.w, h1, l1);
      Ah[r * 20 + sq * 2] = h0; Ah[r * 20 + sq * 2 + 1] = h1;
      Al[r * 20 + sq * 2] = l0; Al[r * 20 + sq * 2 + 1] = l1;
    }
    // stage W[64][32]
#pragma unroll
    for (int r = sr; r < 64; r += 32) {
      float4 v = *(const float4*)&W[(size_t)(n0 + r) * kHid + k0 + sq * 4];
      uint32_t h0, l0, h1, l1;
      split2(v.x, v.y, h0, l0);
      split2(v.z, v.w, h1, l1);
      Bh[r * 20 + sq * 2] = h0; Bh[r * 20 + sq * 2 + 1] = h1;
      Bl[r * 20 + sq * 2] = l0; Bl[r * 20 + sq * 2 + 1] = l1;
    }
    __syncthreads();

#pragma unroll
    for (int ks = 0; ks < 2; ks++) {
      uint32_t ah[2][4], al[2][4];
#pragma unroll
      for (int tm = 0; tm < 2; tm++) {
        const int base = (wm + tm * 16 + g) * 20 + 8 * ks + t;
        ah[tm][0] = Ah[base];       ah[tm][1] = Ah[base + 160];
        ah[tm][2] = Ah[base + 4];   ah[tm][3] = Ah[base + 164];
        al[tm][0] = Al[base];       al[tm][1] = Al[base + 160];
        al[tm][2] = Al[base + 4];   al[tm][3] = Al[base + 164];
      }
#pragma unroll
      for (int nc = 0; nc < 4; nc++) {
        const int nb = (wn + nc * 8 + g) * 20 + 8 * ks + t;
        uint32_t b0h = Bh[nb], b1h = Bh[nb + 4];
        uint32_t b0l = Bl[nb], b1l = Bl[nb + 4];
#pragma unroll
        for (int tm = 0; tm < 2; tm++) {
          mma_bf16(c[tm][nc], ah[tm], b0h, b1h);
          mma_bf16(c[tm][nc], ah[tm], b0l, b1l);
          mma_bf16(c[tm][nc], al[tm], b0h, b1h);
        }
      }
    }
  }

  // ---- epilogue: bias, norms, typed stores ----
  const int head = (n0 + wn) >> 5;
#pragma unroll
  for (int nc = 0; nc < 4; nc++) {
    const float bb0 = bias[n0 + wn + nc * 8 + 2 * t];
    const float bb1 = bias[n0 + wn + nc * 8 + 2 * t + 1];
#pragma unroll
    for (int tm = 0; tm < 2; tm++) {
      c[tm][nc][0] += bb0; c[tm][nc][1] += bb1;
      c[tm][nc][2] += bb0; c[tm][nc][3] += bb1;
    }
  }

  if (sel < 3) {
    float* nrm = (sel == 0) ? g_nq : (sel == 1) ? g_nk1 : g_nk2;
    float ps[2][2] = {{0.f, 0.f}, {0.f, 0.f}};
#pragma unroll
    for (int tm = 0; tm < 2; tm++)
#pragma unroll
      for (int nc = 0; nc < 4; nc++) {
        ps[tm][0] = fmaf(c[tm][nc][0], c[tm][nc][0],
                    fmaf(c[tm][nc][1], c[tm][nc][1], ps[tm][0]));
        ps[tm][1] = fmaf(c[tm][nc][2], c[tm][nc][2],
                    fmaf(c[tm][nc][3], c[tm][nc][3], ps[tm][1]));
      }
#pragma unroll
    for (int tm = 0; tm < 2; tm++)
#pragma unroll
      for (int hh = 0; hh < 2; hh++) {
#pragma unroll
        for (int o = 1; o < 4; o <<= 1)
          ps[tm][hh] += __shfl_xor_sync(0xffffffffu, ps[tm][hh], o);
      }
    if (t == 0) {
#pragma unroll
      for (int tm = 0; tm < 2; tm++)
#pragma unroll
        for (int hh = 0; hh < 2; hh++) {
          const int r = m0 + wm + tm * 16 + g + hh * 8;
          const int b = r >> 10, s = r & 1023;
          nrm[(b * kH + head) * kS + s] = ps[tm][hh];
        }
    }
  }

  if (sel == 0 || sel == 3) {
    float* out = (sel == 0) ? g_q : g_v;
#pragma unroll
    for (int tm = 0; tm < 2; tm++)
#pragma unroll
      for (int nc = 0; nc < 4; nc++) {
        const int d = nc * 8 + 2 * t;
        const int r0 = m0 + wm + tm * 16 + g;
        {
          const int b = r0 >> 10, s = r0 & 1023;
          *(float2*)&out[(((size_t)b * kH + head) * kS + s) * kD + d] =
              make_float2(c[tm][nc][0], c[tm][nc][1]);
        }
        {
          const int r1 = r0 + 8;
          const int b = r1 >> 10, s = r1 & 1023;
          *(float2*)&out[(((size_t)b * kH + head) * kS + s) * kD + d] =
              make_float2(c[tm][nc][2], c[tm][nc][3]);
        }
      }
  } else {
    uint32_t* outh = (sel == 1) ? g_k1h : g_k2h;
    uint32_t* outl = (sel == 1) ? g_k1l : g_k2l;
#pragma unroll
    for (int tm = 0; tm < 2; tm++)
#pragma unroll
      for (int nc = 0; nc < 4; nc++) {
        const int p = nc * 4 + t;   // pair index (d = 2p)
        const int r0 = m0 + wm + tm * 16 + g;
        uint32_t h, l;
        {
          const int b = r0 >> 10, s = r0 & 1023;
          split2(c[tm][nc][0], c[tm][nc][1], h, l);
          const size_t o = ((size_t)(b * kH + head) * kS + s) * 16 + p;
          outh[o] = h; outl[o] = l;
        }
        {
          const int r1 = r0 + 8;
          const int b = r1 >> 10, s = r1 & 1023;
          split2(c[tm][nc][2], c[tm][nc][3], h, l);
          const size_t o = ((size_t)(b * kH + head) * kS + s) * 16 + p;
          outh[o] = h; outl[o] = l;
        }
      }
  }
}

// ---------------------------------------------------------------------------
// Fused attention, 2 passes, all-tensor. Block = (128 q rows, one bh), 256 thr.
// Warp w owns q rows 16w..16w+15. Pass 1: max + online rowsums.
// Pass 2: normalized probs from registers + E@V on tensor pipe.
// ---------------------------------------------------------------------------
__device__ __forceinline__ void score6(float* c,
                                       const uint32_t aqh[2][4],
                                       const uint32_t aql[2][4],
                                       const uint32_t* __restrict__ Kh,
                                       const uint32_t* __restrict__ Kl,
                                       int nb) {
  c[0] = c[1] = c[2] = c[3] = 0.f;
#pragma unroll
  for (int ks = 0; ks < 2; ks++) {
    uint32_t b0h = Kh[nb + 8 * ks], b1h = Kh[nb + 8 * ks + 4];
    uint32_t b0l = Kl[nb + 8 * ks], b1l = Kl[nb + 8 * ks + 4];
    mma_bf16(c, aqh[ks], b0h, b1h);
    mma_bf16(c, aqh[ks], b0l, b1l);
    mma_bf16(c, aql[ks], b0h, b1h);
  }
}

__global__ __launch_bounds__(256, 2) void attn_kernel(
    const float* __restrict__ mask, const float* __restrict__ pi,
    float* __restrict__ out_ctx, float* __restrict__ out_probs)
{
  extern __shared__ uint32_t su[];
  float* nqs  = (float*)(su + U_NQ);
  float* nk1s = (float*)(su + U_NK1);
  float* nk2s = (float*)(su + U_NK2);
  float* msk  = (float*)(su + U_MSK);
  uint32_t* K1h = su + U_K1H;
  uint32_t* K1l = su + U_K1L;
  uint32_t* K2h = su + U_K2H;
  uint32_t* K2l = su + U_K2L;
  uint32_t* Vth = su + U_VTH;
  uint32_t* Vtl = su + U_VTL;

  const int tid = threadIdx.x;
  const int w = tid >> 5, lane = tid & 31;
  const int g = lane >> 2, t = lane & 3;
  const int R0 = w * 16 + g, R1 = R0 + 8;

  const int qt = blockIdx.x, bh = blockIdx.y;
  const int b = bh / kH, h = bh % kH;
  const int q0 = qt * 128;
  const int nbase = bh * kS;
  const size_t gbase = (size_t)bh * kS * kD;

  const float pi0 = fminf(fmaxf(pi[h],      1e-6f), 2.0f);
  const float pi1 = fminf(fmaxf(pi[kH + h], 1e-6f), 2.0f);

  // ---- stage Q fp32 (aliases K region), build persistent split A fragments ----
  {
    float* qst = (float*)(su + U_K1H);   // [128][33]
    for (int i = tid; i < 1024; i += 256) {
      const int j = i >> 3, dg = (i & 7) * 4;
      float4 v = *(const float4*)&g_q[gbase + (size_t)(q0 + j) * kD + dg];
      qst[j * 33 + dg + 0] = v.x; qst[j * 33 + dg + 1] = v.y;
      qst[j * 33 + dg + 2] = v.z; qst[j * 33 + dg + 3] = v.w;
    }
    if (tid < 128) nqs[tid] = g_nq[nbase + q0 + tid];
  }
  __syncthreads();

  uint32_t aqh[2][4], aql[2][4];
  {
    float* qst = (float*)(su + U_K1H);
#pragma unroll
    for (int ks = 0; ks < 2; ks++) {
      const int d0 = 16 * ks + 2 * t;
      split2(qst[R0 * 33 + d0],     qst[R0 * 33 + d0 + 1], aqh[ks][0], aql[ks][0]);
      split2(qst[R1 * 33 + d0],     qst[R1 * 33 + d0 + 1], aqh[ks][1], aql[ks][1]);
      split2(qst[R0 * 33 + d0 + 8], qst[R0 * 33 + d0 + 9], aqh[ks][2], aql[ks][2]);
      split2(qst[R1 * 33 + d0 + 8], qst[R1 * 33 + d0 + 9], aqh[ks][3], aql[ks][3]);
    }
  }
  const float nq0 = nqs[R0], nq1 = nqs[R1];
  __syncthreads();

#define LOAD_K(j0)                                                            \
  {                                                                           \
    for (int i = tid; i < 512; i += 256) {                                    \
      const int j = i >> 2, pg = (i & 3) * 4;                                 \
      const size_t go = (size_t)(nbase + (j0) + j) * 16 + pg;                 \
      const int so = j * 20 + pg;                                             \
      *(uint4*)&K1h[so] = *(const uint4*)&g_k1h[go];                          \
      *(uint4*)&K1l[so] = *(const uint4*)&g_k1l[go];                          \
      *(uint4*)&K2h[so] = *(const uint4*)&g_k2h[go];                          \
      *(uint4*)&K2l[so] = *(const uint4*)&g_k2l[go];                          \
    }                                                                         \
    if (tid < 128) {                                                          \
      nk1s[tid] = g_nk1[nbase + (j0) + tid];                                  \
      nk2s[tid] = g_nk2[nbase + (j0) + tid];                                  \
      msk[tid]  = mask[b * kS + (j0) + tid];                                  \
    }                                                                         \
  }

  // ================= pass 1: exact maxes + online rescaled rowsums ==========
  float m1a = -1e30f, m1b = -1e30f, m2a = -1e30f, m2b = -1e30f;
  float l1a = 0.f, l1b = 0.f, l2a = 0.f, l2b = 0.f;

  for (int kt = 0; kt < 8; kt++) {
    __syncthreads();
    LOAD_K(kt * 128)
    __syncthreads();
#pragma unroll 2
    for (int nt = 0; nt < 16; nt++) {
      const int nb = (nt * 8 + g) * 20 + t;
      const int col0 = nt * 8 + 2 * t, col1 = col0 + 1;
      const float mk0 = msk[col0], mk1 = msk[col1];
      float c1[4], c2[4];
      score6(c1, aqh, aql, K1h, K1l, nb);
      score6(c2, aqh, aql, K2h, K2l, nb);
      const float a0 = nk1s[col0], a1 = nk1s[col1];
      const float b0 = nk2s[col0], b1 = nk2s[col1];
      {
        float s0 = score_of(c1[0], nq0, a0, mk0, kC1);
        float s1 = score_of(c1[1], nq0, a1, mk1, kC1);
        float mn = fmaxf(m1a, fmaxf(s0, s1));
        l1a = l1a * __expf(m1a - mn) + __expf(s0 - mn) + __expf(s1 - mn);
        m1a = mn;
      }
      {
        float s0 = score_of(c1[2], nq1, a0, mk0, kC1);
        float s1 = score_of(c1[3], nq1, a1, mk1, kC1);
        float mn = fmaxf(m1b, fmaxf(s0, s1));
        l1b = l1b * __expf(m1b - mn) + __expf(s0 - mn) + __expf(s1 - mn);
        m1b = mn;
      }
      {
        float s0 = score_of(c2[0], nq0, b0, mk0, kC2);
        float s1 = score_of(c2[1], nq0, b1, mk1, kC2);
        float mn = fmaxf(m2a, fmaxf(s0, s1));
        l2a = l2a * __expf(m2a - mn) + __expf(s0 - mn) + __expf(s1 - mn);
        m2a = mn;
      }
      {
        float s0 = score_of(c2[2], nq1, b0, mk0, kC2);
        float s1 = score_of(c2[3], nq1, b1, mk1, kC2);
        float mn = fmaxf(m2b, fmaxf(s0, s1));
        l2b = l2b * __expf(m2b - mn) + __expf(s0 - mn) + __expf(s1 - mn);
        m2b = mn;
      }
    }
  }
  // quad combine (m,l) pairs
#pragma unroll
  for (int o = 1; o < 4; o <<= 1) {
    {
      float mo = __shfl_xor_sync(0xffffffffu, m1a, o);
      float lo = __shfl_xor_sync(0xffffffffu, l1a, o);
      float mn = fmaxf(m1a, mo);
      l1a = l1a * __expf(m1a - mn) + lo * __expf(mo - mn); m1a = mn;
    }
    {
      float mo = __shfl_xor_sync(0xffffffffu, m1b, o);
      float lo = __shfl_xor_sync(0xffffffffu, l1b, o);
      float mn = fmaxf(m1b, mo);
      l1b = l1b * __expf(m1b - mn) + lo * __expf(mo - mn); m1b = mn;
    }
    {
      float mo = __shfl_xor_sync(0xffffffffu, m2a, o);
      float lo = __shfl_xor_sync(0xffffffffu, l2a, o);
      float mn = fmaxf(m2a, mo);
      l2a = l2a * __expf(m2a - mn) + lo * __expf(mo - mn); m2a = mn;
    }
    {
      float mo = __shfl_xor_sync(0xffffffffu, m2b, o);
      float lo = __shfl_xor_sync(0xffffffffu, l2b, o);
      float mn = fmaxf(m2b, mo);
      l2b = l2b * __expf(m2b - mn) + lo * __expf(mo - mn); m2b = mn;
    }
  }
  const float inv0 = 1.0f / (pi0 * l1a + pi1 * l2a + 1e-6f);
  const float inv1 = 1.0f / (pi0 * l1b + pi1 * l2b + 1e-6f);

  // ============ pass 2: normalized probs + E@V on tensor pipe ============
  float cctx[4][4];
#pragma unroll
  for (int i = 0; i < 4; i++)
#pragma unroll
    for (int j = 0; j < 4; j++) cctx[i][j] = 0.f;

  uint32_t eh[4], el[4];

  for (int kt = 0; kt < 8; kt++) {
    __syncthreads();
    LOAD_K(kt * 128)
    // V transpose-pack: Vt[d][jp] = (bf16(V[2jp][d]), bf16(V[2jp+1][d])) split
    for (int i = tid; i < 2048; i += 256) {
      const int jp = i >> 5, d = i & 31;
      const size_t vo = gbase + (size_t)(kt * 128 + 2 * jp) * kD + d;
      float v0 = g_v[vo], v1 = g_v[vo + kD];
      uint32_t hh, ll;
      split2(v0, v1, hh, ll);
      Vth[d * 68 + jp] = hh;
      Vtl[d * 68 + jp] = ll;
    }
    __syncthreads();

#pragma unroll 2
    for (int nt = 0; nt < 16; nt++) {
      const int nb = (nt * 8 + g) * 20 + t;
      const int col0 = nt * 8 + 2 * t;
      const float mk0 = msk[col0], mk1 = msk[col0 + 1];
      float c1[4], c2[4];
      score6(c1, aqh, aql, K1h, K1l, nb);
      score6(c2, aqh, aql, K2h, K2l, nb);
      const float a0 = nk1s[col0], a1 = nk1s[col0 + 1];
      const float b0 = nk2s[col0], b1 = nk2s[col0 + 1];
      float p00 = (pi0 * __expf(score_of(c1[0], nq0, a0, mk0, kC1) - m1a)
                 + pi1 * __expf(score_of(c2[0], nq0, b0, mk0, kC2) - m2a)) * inv0;
      float p01 = (pi0 * __expf(score_of(c1[1], nq0, a1, mk1, kC1) - m1a)
                 + pi1 * __expf(score_of(c2[1], nq0, b1, mk1, kC2) - m2a)) * inv0;
      float p10 = (pi0 * __expf(score_of(c1[2], nq1, a0, mk0, kC1) - m1b)
                 + pi1 * __expf(score_of(c2[2], nq1, b0, mk0, kC2) - m2b)) * inv1;
      float p11 = (pi0 * __expf(score_of(c1[3], nq1, a1, mk1, kC1) - m1b)
                 + pi1 * __expf(score_of(c2[3], nq1, b1, mk1, kC2) - m2b)) * inv1;

      // normalized probs straight from registers
      const size_t pb = ((size_t)bh * kS + q0 + R0) * kS + kt * 128 + col0;
      *(float2*)&out_probs[pb] = make_float2(p00, p01);
      *(float2*)&out_probs[pb + 8 * kS] = make_float2(p10, p11);

      // E fragment accumulation (A-layout is exactly these lanes/pairs)
      if ((nt & 1) == 0) {
        split2(p00, p01, eh[0], el[0]);
        split2(p10, p11, eh[1], el[1]);
      } else {
        split2(p00, p01, eh[2], el[2]);
        split2(p10, p11, eh[3], el[3]);
        const int ks = nt >> 1;
#pragma unroll
        for (int nd = 0; nd < 4; nd++) {
          const int vb = (nd * 8 + g) * 68 + 8 * ks + t;
          uint32_t b0h = Vth[vb], b1h = Vth[vb + 4];
          uint32_t b0l = Vtl[vb], b1l = Vtl[vb + 4];
          mma_bf16(cctx[nd], eh, b0h, b1h);
          mma_bf16(cctx[nd], eh, b0l, b1l);
          mma_bf16(cctx[nd], el, b0h, b1h);
        }
      }
    }
  }

  // ctx store (already normalized since E carried inv)
#pragma unroll
  for (int nd = 0; nd < 4; nd++) {
    const int d = nd * 8 + 2 * t;
    *(float2*)&out_ctx[((size_t)b * kS + q0 + R0) * kAH + h * kD + d] =
        make_float2(cctx[nd][0], cctx[nd][1]);
    *(float2*)&out_ctx[((size_t)b * kS + q0 + R1) * kAH + h * kD + d] =
        make_float2(cctx[nd][2], cctx[nd][3]);
  }
#undef LOAD_K
}

// ---------------------------------------------------------------------------
extern "C" void kernel_launch(void* const* d_in, const int* in_sizes, int n_in,
                              void* d_out, int out_size) {
  (void)in_sizes; (void)n_in; (void)out_size;
  const float* hs   = (const float*)d_in[0];
  const float* mask = (const float*)d_in[1];
  const float* Wq   = (const float*)d_in[2];
  const float* bq   = (const float*)d_in[3];
  const float* Wk1  = (const float*)d_in[4];
  const float* bk1  = (const float*)d_in[5];
  const float* Wk2  = (const float*)d_in[6];
  const float* bk2  = (const float*)d_in[7];
  const float* Wv   = (const float*)d_in[8];
  const float* bv   = (const float*)d_in[9];
  const float* pi   = (const float*)d_in[10];

  float* out_ctx   = (float*)d_out;
  float* out_probs = out_ctx + (size_t)kB * kS * kAH;

  cudaFuncSetAttribute(attn_kernel, cudaFuncAttributeMaxDynamicSharedMemorySize,
                       kAttnSmemBytes);

  dim3 pgrid(kAH / 64, (kB * kS) / 128, 4);   // (6, 32, 4) = 768 CTAs
  proj_kernel<<<pgrid, 256>>>(hs, Wq, bq, Wk1, bk1, Wk2, bk2, Wv, bv);
  attn_kernel<<<dim3(kS / 128, kBH), 256, kAttnSmemBytes>>>(
      mask, pi, out_ctx, out_probs);
}

// round 8
// speedup vs baseline: 3.3627x; 1.0984x over previous
#include <cuda_runtime.h>
#include <cuda_bf16.h>
#include <cstdint>

// ---------------------------------------------------------------------------
// MGKBertSelfAttention: B=4, S=1024, HID=768, H=12, D=32, AH=384
// out = [ctx (B,S,AH) ; probs (B,H,S,S)]  fp32
// Everything heavy on mma.sync m16n8k16 bf16 with 2-term hi/lo split
// (3-product reconstruction => fp32-equivalent precision, residual ~2^-18).
// R8: single-wave occupancy (3 CTAs/SM) + fixed-reference pass-1 rowsums.
// ---------------------------------------------------------------------------

namespace {
constexpr int kB = 4, kS = 1024, kHid = 768, kH = 12, kD = 32, kAH = 384;
constexpr int kBH = kB * kH;                       // 48
constexpr float kScaling = 0.17677669529663687f;   // 32^-0.5
constexpr float kC1 = 0.5f * kScaling;
constexpr float kC2 = 0.75f * kScaling;

// attn smem layout (u32 units)
constexpr int U_NQ  = 0;     // 128 f32
constexpr int U_NK1 = 128;
constexpr int U_NK2 = 256;
constexpr int U_MSK = 384;
constexpr int U_K1H = 512;   // K tiles: [128][20] u32 each (stride-20 pad)
constexpr int U_K1L = U_K1H + 2560;
constexpr int U_K2H = U_K1L + 2560;
constexpr int U_K2L = U_K2H + 2560;
constexpr int U_VTH = U_K2L + 2560;   // Vt packed: [32][68] u32
constexpr int U_VTL = U_VTH + 2176;
constexpr int kAttnSmemU32 = U_VTL + 2176;          // 15104 u32
constexpr int kAttnSmemBytes = kAttnSmemU32 * 4;    // 60416 B
}

// Scratch (device globals; allocation is forbidden)
__device__ float    g_q  [kBH * kS * kD];   // fp32 [bh][s][d]
__device__ float    g_v  [kBH * kS * kD];   // fp32 [bh][s][d]
__device__ uint32_t g_k1h[kBH * kS * 16];   // bf16x2 pairs along d
__device__ uint32_t g_k1l[kBH * kS * 16];
__device__ uint32_t g_k2h[kBH * kS * 16];
__device__ uint32_t g_k2l[kBH * kS * 16];
__device__ float    g_nq [kBH * kS];
__device__ float    g_nk1[kBH * kS];
__device__ float    g_nk2[kBH * kS];

// ---------------------------------------------------------------------------
// bf16 split helpers
// ---------------------------------------------------------------------------
__device__ __forceinline__ void split2(float x, float y, uint32_t& h, uint32_t& l) {
  __nv_bfloat16 bx = __float2bfloat16_rn(x);
  __nv_bfloat16 by = __float2bfloat16_rn(y);
  float rx = x - __bfloat162float(bx);
  float ry = y - __bfloat162float(by);
  __nv_bfloat16 lx = __float2bfloat16_rn(rx);
  __nv_bfloat16 ly = __float2bfloat16_rn(ry);
  h = (uint32_t)__bfloat16_as_ushort(bx) | ((uint32_t)__bfloat16_as_ushort(by) << 16);
  l = (uint32_t)__bfloat16_as_ushort(lx) | ((uint32_t)__bfloat16_as_ushort(ly) << 16);
}

__device__ __forceinline__ void mma_bf16(float* c, const uint32_t* a,
                                         uint32_t b0, uint32_t b1) {
  asm volatile(
      "mma.sync.aligned.m16n8k16.row.col.f32.bf16.bf16.f32 "
      "{%0,%1,%2,%3}, {%4,%5,%6,%7}, {%8,%9}, {%0,%1,%2,%3};\n"
      : "+f"(c[0]), "+f"(c[1]), "+f"(c[2]), "+f"(c[3])
      : "r"(a[0]), "r"(a[1]), "r"(a[2]), "r"(a[3]), "r"(b0), "r"(b1));
}

__device__ __forceinline__ float score_of(float cr, float nqv, float nkv,
                                          float mskv, float scale) {
  return fmaf(-scale, fmaxf(nqv + nkv - 2.f * cr, 0.f), mskv);
}

// ---------------------------------------------------------------------------
// Projection GEMM on tensor cores: C[4096,384] = X @ W^T + bias.
// CTA 128(M)x64(N), 256 thr, warp grid 4x2 (warp tile 32x32), K chunks of 32.
// sel = blockIdx.z: 0->g_q fp32 + norms; 1/2 -> split-packed K + norms; 3 -> g_v.
// ---------------------------------------------------------------------------
__global__ __launch_bounds__(256) void proj_kernel(
    const float* __restrict__ X,
    const float* __restrict__ Wq,  const float* __restrict__ bq,
    const float* __restrict__ Wk1, const float* __restrict__ bk1,
    const float* __restrict__ Wk2, const float* __restrict__ bk2,
    const float* __restrict__ Wv,  const float* __restrict__ bv)
{
  __shared__ uint32_t Ah[128 * 20], Al[128 * 20];
  __shared__ uint32_t Bh[64 * 20],  Bl[64 * 20];

  const int sel = blockIdx.z;
  const float* W    = (sel == 0) ? Wq : (sel == 1) ? Wk1 : (sel == 2) ? Wk2 : Wv;
  const float* bias = (sel == 0) ? bq : (sel == 1) ? bk1 : (sel == 2) ? bk2 : bv;

  const int tid = threadIdx.x;
  const int w = tid >> 5, lane = tid & 31;
  const int g = lane >> 2, t = lane & 3;
  const int wm = (w & 3) * 32, wn = (w >> 2) * 32;
  const int m0 = blockIdx.y * 128, n0 = blockIdx.x * 64;

  float c[2][4][4];
#pragma unroll
  for (int i = 0; i < 2; i++)
#pragma unroll
    for (int j = 0; j < 4; j++)
#pragma unroll
      for (int k = 0; k < 4; k++) c[i][j][k] = 0.f;

  const int sq = tid & 7, sr = tid >> 3;          // stage: quad, row-base

  for (int k0 = 0; k0 < kHid; k0 += 32) {
    __syncthreads();
    // stage X[128][32] split-packed
#pragma unroll
    for (int r = sr; r < 128; r += 32) {
      float4 v = *(const float4*)&X[(size_t)(m0 + r) * kHid + k0 + sq * 4];
      uint32_t h0, l0, h1, l1;
      split2(v.x, v.y, h0, l0);
      split2(v.z, v.w, h1, l1);
      Ah[r * 20 + sq * 2] = h0; Ah[r * 20 + sq * 2 + 1] = h1;
      Al[r * 20 + sq * 2] = l0; Al[r * 20 + sq * 2 + 1] = l1;
    }
    // stage W[64][32]
#pragma unroll
    for (int r = sr; r < 64; r += 32) {
      float4 v = *(const float4*)&W[(size_t)(n0 + r) * kHid + k0 + sq * 4];
      uint32_t h0, l0, h1, l1;
      split2(v.x, v.y, h0, l0);
      split2(v.z, v.w, h1, l1);
      Bh[r * 20 + sq * 2] = h0; Bh[r * 20 + sq * 2 + 1] = h1;
      Bl[r * 20 + sq * 2] = l0; Bl[r * 20 + sq * 2 + 1] = l1;
    }
    __syncthreads();

#pragma unroll
    for (int ks = 0; ks < 2; ks++) {
      uint32_t ah[2][4], al[2][4];
#pragma unroll
      for (int tm = 0; tm < 2; tm++) {
        const int base = (wm + tm * 16 + g) * 20 + 8 * ks + t;
        ah[tm][0] = Ah[base];       ah[tm][1] = Ah[base + 160];
        ah[tm][2] = Ah[base + 4];   ah[tm][3] = Ah[base + 164];
        al[tm][0] = Al[base];       al[tm][1] = Al[base + 160];
        al[tm][2] = Al[base + 4];   al[tm][3] = Al[base + 164];
      }
#pragma unroll
      for (int nc = 0; nc < 4; nc++) {
        const int nb = (wn + nc * 8 + g) * 20 + 8 * ks + t;
        uint32_t b0h = Bh[nb], b1h = Bh[nb + 4];
        uint32_t b0l = Bl[nb], b1l = Bl[nb + 4];
#pragma unroll
        for (int tm = 0; tm < 2; tm++) {
          mma_bf16(c[tm][nc], ah[tm], b0h, b1h);
          mma_bf16(c[tm][nc], ah[tm], b0l, b1l);
          mma_bf16(c[tm][nc], al[tm], b0h, b1h);
        }
      }
    }
  }

  // ---- epilogue: bias, norms, typed stores ----
  const int head = (n0 + wn) >> 5;
#pragma unroll
  for (int nc = 0; nc < 4; nc++) {
    const float bb0 = bias[n0 + wn + nc * 8 + 2 * t];
    const float bb1 = bias[n0 + wn + nc * 8 + 2 * t + 1];
#pragma unroll
    for (int tm = 0; tm < 2; tm++) {
      c[tm][nc][0] += bb0; c[tm][nc][1] += bb1;
      c[tm][nc][2] += bb0; c[tm][nc][3] += bb1;
    }
  }

  if (sel < 3) {
    float* nrm = (sel == 0) ? g_nq : (sel == 1) ? g_nk1 : g_nk2;
    float ps[2][2] = {{0.f, 0.f}, {0.f, 0.f}};
#pragma unroll
    for (int tm = 0; tm < 2; tm++)
#pragma unroll
      for (int nc = 0; nc < 4; nc++) {
        ps[tm][0] = fmaf(c[tm][nc][0], c[tm][nc][0],
                    fmaf(c[tm][nc][1], c[tm][nc][1], ps[tm][0]));
        ps[tm][1] = fmaf(c[tm][nc][2], c[tm][nc][2],
                    fmaf(c[tm][nc][3], c[tm][nc][3], ps[tm][1]));
      }
#pragma unroll
    for (int tm = 0; tm < 2; tm++)
#pragma unroll
      for (int hh = 0; hh < 2; hh++) {
#pragma unroll
        for (int o = 1; o < 4; o <<= 1)
          ps[tm][hh] += __shfl_xor_sync(0xffffffffu, ps[tm][hh], o);
      }
    if (t == 0) {
#pragma unroll
      for (int tm = 0; tm < 2; tm++)
#pragma unroll
        for (int hh = 0; hh < 2; hh++) {
          const int r = m0 + wm + tm * 16 + g + hh * 8;
          const int b = r >> 10, s = r & 1023;
          nrm[(b * kH + head) * kS + s] = ps[tm][hh];
        }
    }
  }

  if (sel == 0 || sel == 3) {
    float* out = (sel == 0) ? g_q : g_v;
#pragma unroll
    for (int tm = 0; tm < 2; tm++)
#pragma unroll
      for (int nc = 0; nc < 4; nc++) {
        const int d = nc * 8 + 2 * t;
        const int r0 = m0 + wm + tm * 16 + g;
        {
          const int b = r0 >> 10, s = r0 & 1023;
          *(float2*)&out[(((size_t)b * kH + head) * kS + s) * kD + d] =
              make_float2(c[tm][nc][0], c[tm][nc][1]);
        }
        {
          const int r1 = r0 + 8;
          const int b = r1 >> 10, s = r1 & 1023;
          *(float2*)&out[(((size_t)b * kH + head) * kS + s) * kD + d] =
              make_float2(c[tm][nc][2], c[tm][nc][3]);
        }
      }
  } else {
    uint32_t* outh = (sel == 1) ? g_k1h : g_k2h;
    uint32_t* outl = (sel == 1) ? g_k1l : g_k2l;
#pragma unroll
    for (int tm = 0; tm < 2; tm++)
#pragma unroll
      for (int nc = 0; nc < 4; nc++) {
        const int p = nc * 4 + t;   // pair index (d = 2p)
        const int r0 = m0 + wm + tm * 16 + g;
        uint32_t h, l;
        {
          const int b = r0 >> 10, s = r0 & 1023;
          split2(c[tm][nc][0], c[tm][nc][1], h, l);
          const size_t o = ((size_t)(b * kH + head) * kS + s) * 16 + p;
          outh[o] = h; outl[o] = l;
        }
        {
          const int r1 = r0 + 8;
          const int b = r1 >> 10, s = r1 & 1023;
          split2(c[tm][nc][2], c[tm][nc][3], h, l);
          const size_t o = ((size_t)(b * kH + head) * kS + s) * 16 + p;
          outh[o] = h; outl[o] = l;
        }
      }
  }
}

// ---------------------------------------------------------------------------
// Fused attention, 2 passes, all-tensor. Block = (128 q rows, one bh), 256 thr.
// Pass 1: exact maxes + fixed-reference (unshifted) rowsums, no rescale chain.
// Pass 2: normalized probs from registers + E@V on tensor pipe.
// 3 CTAs/SM -> whole grid (384) resident in one wave.
// ---------------------------------------------------------------------------
__device__ __forceinline__ void score6(float* c,
                                       const uint32_t aqh[2][4],
                                       const uint32_t aql[2][4],
                                       const uint32_t* __restrict__ Kh,
                                       const uint32_t* __restrict__ Kl,
                                       int nb) {
  c[0] = c[1] = c[2] = c[3] = 0.f;
#pragma unroll
  for (int ks = 0; ks < 2; ks++) {
    uint32_t b0h = Kh[nb + 8 * ks], b1h = Kh[nb + 8 * ks + 4];
    uint32_t b0l = Kl[nb + 8 * ks], b1l = Kl[nb + 8 * ks + 4];
    mma_bf16(c, aqh[ks], b0h, b1h);
    mma_bf16(c, aqh[ks], b0l, b1l);
    mma_bf16(c, aql[ks], b0h, b1h);
  }
}

__global__ __launch_bounds__(256, 3) void attn_kernel(
    const float* __restrict__ mask, const float* __restrict__ pi,
    float* __restrict__ out_ctx, float* __restrict__ out_probs)
{
  extern __shared__ uint32_t su[];
  float* nqs  = (float*)(su + U_NQ);
  float* nk1s = (float*)(su + U_NK1);
  float* nk2s = (float*)(su + U_NK2);
  float* msk  = (float*)(su + U_MSK);
  uint32_t* K1h = su + U_K1H;
  uint32_t* K1l = su + U_K1L;
  uint32_t* K2h = su + U_K2H;
  uint32_t* K2l = su + U_K2L;
  uint32_t* Vth = su + U_VTH;
  uint32_t* Vtl = su + U_VTL;

  const int tid = threadIdx.x;
  const int w = tid >> 5, lane = tid & 31;
  const int g = lane >> 2, t = lane & 3;
  const int R0 = w * 16 + g, R1 = R0 + 8;

  const int qt = blockIdx.x, bh = blockIdx.y;
  const int b = bh / kH, h = bh % kH;
  const int q0 = qt * 128;
  const int nbase = bh * kS;
  const size_t gbase = (size_t)bh * kS * kD;

  const float pi0 = fminf(fmaxf(pi[h],      1e-6f), 2.0f);
  const float pi1 = fminf(fmaxf(pi[kH + h], 1e-6f), 2.0f);

  // ---- stage Q fp32 (aliases K region), build persistent split A fragments ----
  {
    float* qst = (float*)(su + U_K1H);   // [128][33]
    for (int i = tid; i < 1024; i += 256) {
      const int j = i >> 3, dg = (i & 7) * 4;
      float4 v = *(const float4*)&g_q[gbase + (size_t)(q0 + j) * kD + dg];
      qst[j * 33 + dg + 0] = v.x; qst[j * 33 + dg + 1] = v.y;
      qst[j * 33 + dg + 2] = v.z; qst[j * 33 + dg + 3] = v.w;
    }
    if (tid < 128) nqs[tid] = g_nq[nbase + q0 + tid];
  }
  __syncthreads();

  uint32_t aqh[2][4], aql[2][4];
  {
    float* qst = (float*)(su + U_K1H);
#pragma unroll
    for (int ks = 0; ks < 2; ks++) {
      const int d0 = 16 * ks + 2 * t;
      split2(qst[R0 * 33 + d0],     qst[R0 * 33 + d0 + 1], aqh[ks][0], aql[ks][0]);
      split2(qst[R1 * 33 + d0],     qst[R1 * 33 + d0 + 1], aqh[ks][1], aql[ks][1]);
      split2(qst[R0 * 33 + d0 + 8], qst[R0 * 33 + d0 + 9], aqh[ks][2], aql[ks][2]);
      split2(qst[R1 * 33 + d0 + 8], qst[R1 * 33 + d0 + 9], aqh[ks][3], aql[ks][3]);
    }
  }
  const float nq0 = nqs[R0], nq1 = nqs[R1];
  __syncthreads();

#define LOAD_K(j0)                                                            \
  {                                                                           \
    for (int i = tid; i < 512; i += 256) {                                    \
      const int j = i >> 2, pg = (i & 3) * 4;                                 \
      const size_t go = (size_t)(nbase + (j0) + j) * 16 + pg;                 \
      const int so = j * 20 + pg;                                             \
      *(uint4*)&K1h[so] = *(const uint4*)&g_k1h[go];                          \
      *(uint4*)&K1l[so] = *(const uint4*)&g_k1l[go];                          \
      *(uint4*)&K2h[so] = *(const uint4*)&g_k2h[go];                          \
      *(uint4*)&K2l[so] = *(const uint4*)&g_k2l[go];                          \
    }                                                                         \
    if (tid < 128) {                                                          \
      nk1s[tid] = g_nk1[nbase + (j0) + tid];                                  \
      nk2s[tid] = g_nk2[nbase + (j0) + tid];                                  \
      msk[tid]  = mask[b * kS + (j0) + tid];                                  \
    }                                                                         \
  }

  // ====== pass 1: exact maxes + fixed-reference (unshifted) rowsums ======
  // mask == additive bias; scores <= max(mask) and dist >= 0 keep exp(s) in
  // range, so sums relative to 0 are safe and need no rescale chain.
  float m1a = -1e30f, m1b = -1e30f, m2a = -1e30f, m2b = -1e30f;
  float l1a = 0.f, l1b = 0.f, l2a = 0.f, l2b = 0.f;

  for (int kt = 0; kt < 8; kt++) {
    __syncthreads();
    LOAD_K(kt * 128)
    __syncthreads();
#pragma unroll 2
    for (int nt = 0; nt < 16; nt++) {
      const int nb = (nt * 8 + g) * 20 + t;
      const int col0 = nt * 8 + 2 * t, col1 = col0 + 1;
      const float mk0 = msk[col0], mk1 = msk[col1];
      float c1[4], c2[4];
      score6(c1, aqh, aql, K1h, K1l, nb);
      score6(c2, aqh, aql, K2h, K2l, nb);
      const float a0 = nk1s[col0], a1 = nk1s[col1];
      const float b0 = nk2s[col0], b1 = nk2s[col1];
      {
        float s0 = score_of(c1[0], nq0, a0, mk0, kC1);
        float s1 = score_of(c1[1], nq0, a1, mk1, kC1);
        m1a = fmaxf(m1a, fmaxf(s0, s1));
        l1a += __expf(s0) + __expf(s1);
      }
      {
        float s0 = score_of(c1[2], nq1, a0, mk0, kC1);
        float s1 = score_of(c1[3], nq1, a1, mk1, kC1);
        m1b = fmaxf(m1b, fmaxf(s0, s1));
        l1b += __expf(s0) + __expf(s1);
      }
      {
        float s0 = score_of(c2[0], nq0, b0, mk0, kC2);
        float s1 = score_of(c2[1], nq0, b1, mk1, kC2);
        m2a = fmaxf(m2a, fmaxf(s0, s1));
        l2a += __expf(s0) + __expf(s1);
      }
      {
        float s0 = score_of(c2[2], nq1, b0, mk0, kC2);
        float s1 = score_of(c2[3], nq1, b1, mk1, kC2);
        m2b = fmaxf(m2b, fmaxf(s0, s1));
        l2b += __expf(s0) + __expf(s1);
      }
    }
  }
  // quad combine: plain sum + max (no rescale needed, fixed reference)
#pragma unroll
  for (int o = 1; o < 4; o <<= 1) {
    m1a = fmaxf(m1a, __shfl_xor_sync(0xffffffffu, m1a, o));
    m1b = fmaxf(m1b, __shfl_xor_sync(0xffffffffu, m1b, o));
    m2a = fmaxf(m2a, __shfl_xor_sync(0xffffffffu, m2a, o));
    m2b = fmaxf(m2b, __shfl_xor_sync(0xffffffffu, m2b, o));
    l1a += __shfl_xor_sync(0xffffffffu, l1a, o);
    l1b += __shfl_xor_sync(0xffffffffu, l1b, o);
    l2a += __shfl_xor_sync(0xffffffffu, l2a, o);
    l2b += __shfl_xor_sync(0xffffffffu, l2b, o);
  }
  // shifted-sum reconstruction: sum_shifted = pi0*e^{-m1}*l1 + pi1*e^{-m2}*l2
  const float inv0 = 1.0f / (pi0 * __expf(-m1a) * l1a +
                             pi1 * __expf(-m2a) * l2a + 1e-6f);
  const float inv1 = 1.0f / (pi0 * __expf(-m1b) * l1b +
                             pi1 * __expf(-m2b) * l2b + 1e-6f);

  // ============ pass 2: normalized probs + E@V on tensor pipe ============
  float cctx[4][4];
#pragma unroll
  for (int i = 0; i < 4; i++)
#pragma unroll
    for (int j = 0; j < 4; j++) cctx[i][j] = 0.f;

  uint32_t eh[4], el[4];

  for (int kt = 0; kt < 8; kt++) {
    __syncthreads();
    LOAD_K(kt * 128)
    // V transpose-pack: Vt[d][jp] = (bf16(V[2jp][d]), bf16(V[2jp+1][d])) split
    for (int i = tid; i < 2048; i += 256) {
      const int jp = i >> 5, d = i & 31;
      const size_t vo = gbase + (size_t)(kt * 128 + 2 * jp) * kD + d;
      float v0 = g_v[vo], v1 = g_v[vo + kD];
      uint32_t hh, ll;
      split2(v0, v1, hh, ll);
      Vth[d * 68 + jp] = hh;
      Vtl[d * 68 + jp] = ll;
    }
    __syncthreads();

#pragma unroll 2
    for (int nt = 0; nt < 16; nt++) {
      const int nb = (nt * 8 + g) * 20 + t;
      const int col0 = nt * 8 + 2 * t;
      const float mk0 = msk[col0], mk1 = msk[col0 + 1];
      float c1[4], c2[4];
      score6(c1, aqh, aql, K1h, K1l, nb);
      score6(c2, aqh, aql, K2h, K2l, nb);
      const float a0 = nk1s[col0], a1 = nk1s[col0 + 1];
      const float b0 = nk2s[col0], b1 = nk2s[col0 + 1];
      float p00 = (pi0 * __expf(score_of(c1[0], nq0, a0, mk0, kC1) - m1a)
                 + pi1 * __expf(score_of(c2[0], nq0, b0, mk0, kC2) - m2a)) * inv0;
      float p01 = (pi0 * __expf(score_of(c1[1], nq0, a1, mk1, kC1) - m1a)
                 + pi1 * __expf(score_of(c2[1], nq0, b1, mk1, kC2) - m2a)) * inv0;
      float p10 = (pi0 * __expf(score_of(c1[2], nq1, a0, mk0, kC1) - m1b)
                 + pi1 * __expf(score_of(c2[2], nq1, b0, mk0, kC2) - m2b)) * inv1;
      float p11 = (pi0 * __expf(score_of(c1[3], nq1, a1, mk1, kC1) - m1b)
                 + pi1 * __expf(score_of(c2[3], nq1, b1, mk1, kC2) - m2b)) * inv1;

      // normalized probs straight from registers (streaming stores)
      const size_t pb = ((size_t)bh * kS + q0 + R0) * kS + kt * 128 + col0;
      __stcs((float2*)&out_probs[pb], make_float2(p00, p01));
      __stcs((float2*)&out_probs[pb + 8 * kS], make_float2(p10, p11));

      // E fragment accumulation (A-layout is exactly these lanes/pairs)
      if ((nt & 1) == 0) {
        split2(p00, p01, eh[0], el[0]);
        split2(p10, p11, eh[1], el[1]);
      } else {
        split2(p00, p01, eh[2], el[2]);
        split2(p10, p11, eh[3], el[3]);
        const int ks = nt >> 1;
#pragma unroll
        for (int nd = 0; nd < 4; nd++) {
          const int vb = (nd * 8 + g) * 68 + 8 * ks + t;
          uint32_t b0h = Vth[vb], b1h = Vth[vb + 4];
          uint32_t b0l = Vtl[vb], b1l = Vtl[vb + 4];
          mma_bf16(cctx[nd], eh, b0h, b1h);
          mma_bf16(cctx[nd], eh, b0l, b1l);
          mma_bf16(cctx[nd], el, b0h, b1h);
        }
      }
    }
  }

  // ctx store (already normalized since E carried inv)
#pragma unroll
  for (int nd = 0; nd < 4; nd++) {
    const int d = nd * 8 + 2 * t;
    *(float2*)&out_ctx[((size_t)b * kS + q0 + R0) * kAH + h * kD + d] =
        make_float2(cctx[nd][0], cctx[nd][1]);
    *(float2*)&out_ctx[((size_t)b * kS + q0 + R1) * kAH + h * kD + d] =
        make_float2(cctx[nd][2], cctx[nd][3]);
  }
#undef LOAD_K
}

// ---------------------------------------------------------------------------
extern "C" void kernel_launch(void* const* d_in, const int* in_sizes, int n_in,
                              void* d_out, int out_size) {
  (void)in_sizes; (void)n_in; (void)out_size;
  const float* hs   = (const float*)d_in[0];
  const float* mask = (const float*)d_in[1];
  const float* Wq   = (const float*)d_in[2];
  const float* bq   = (const float*)d_in[3];
  const float* Wk1  = (const float*)d_in[4];
  const float* bk1  = (const float*)d_in[5];
  const float* Wk2  = (const float*)d_in[6];
  const float* bk2  = (const float*)d_in[7];
  const float* Wv   = (const float*)d_in[8];
  const float* bv   = (const float*)d_in[9];
  const float* pi   = (const float*)d_in[10];

  float* out_ctx   = (float*)d_out;
  float* out_probs = out_ctx + (size_t)kB * kS * kAH;

  cudaFuncSetAttribute(attn_kernel, cudaFuncAttributeMaxDynamicSharedMemorySize,
                       kAttnSmemBytes);

  dim3 pgrid(kAH / 64, (kB * kS) / 128, 4);   // (6, 32, 4) = 768 CTAs
  proj_kernel<<<pgrid, 256>>>(hs, Wq, bq, Wk1, bk1, Wk2, bk2, Wv, bv);
  attn_kernel<<<dim3(kS / 128, kBH), 256, kAttnSmemBytes>>>(
      mask, pi, out_ctx, out_probs);
}

// round 9
// speedup vs baseline: 3.4204x; 1.0171x over previous
#include <cuda_runtime.h>
#include <cuda_bf16.h>
#include <cstdint>

// ---------------------------------------------------------------------------
// MGKBertSelfAttention: B=4, S=1024, HID=768, H=12, D=32, AH=384
// out = [ctx (B,S,AH) ; probs (B,H,S,S)]  fp32
// mma.sync m16n8k16 bf16, 2-term hi/lo split (3-product, fp32-equiv precision).
// R9: fragment-major permuted K/V layouts -> LDS.128/.64 fragment loads.
// ---------------------------------------------------------------------------

namespace {
constexpr int kB = 4, kS = 1024, kHid = 768, kH = 12, kD = 32, kAH = 384;
constexpr int kBH = kB * kH;                       // 48
constexpr float kScaling = 0.17677669529663687f;   // 32^-0.5
constexpr float kC1 = 0.5f * kScaling;
constexpr float kC2 = 0.75f * kScaling;

// attn smem layout (u32 units)
constexpr int U_NQ  = 0;     // 128 f32
constexpr int U_NK1 = 128;
constexpr int U_NK2 = 256;
constexpr int U_MSK = 384;
constexpr int U_K1H = 512;   // K tiles: [128][16] u32, fragment-permuted rows
constexpr int U_K1L = U_K1H + 2048;
constexpr int U_K2H = U_K1L + 2048;
constexpr int U_K2L = U_K2H + 2048;
constexpr int U_VTH = U_K2L + 2048;   // Vt packed: [32][72] u32 (pair-permuted)
constexpr int U_VTL = U_VTH + 2304;
constexpr int kAttnSmemU32 = U_VTL + 2304;          // 13312 u32
constexpr int kAttnSmemBytes = kAttnSmemU32 * 4;    // 53248 B
}

// Scratch (device globals; allocation is forbidden)
__device__ float    g_q  [kBH * kS * kD];   // fp32 [bh][s][d]
__device__ float    g_v  [kBH * kS * kD];   // fp32 [bh][s][d]
__device__ uint32_t g_k1h[kBH * kS * 16];   // bf16x2 pairs, fragment-permuted
__device__ uint32_t g_k1l[kBH * kS * 16];
__device__ uint32_t g_k2h[kBH * kS * 16];
__device__ uint32_t g_k2l[kBH * kS * 16];
__device__ float    g_nq [kBH * kS];
__device__ float    g_nk1[kBH * kS];
__device__ float    g_nk2[kBH * kS];

// ---------------------------------------------------------------------------
// bf16 split helpers
// ---------------------------------------------------------------------------
__device__ __forceinline__ void split2(float x, float y, uint32_t& h, uint32_t& l) {
  __nv_bfloat16 bx = __float2bfloat16_rn(x);
  __nv_bfloat16 by = __float2bfloat16_rn(y);
  float rx = x - __bfloat162float(bx);
  float ry = y - __bfloat162float(by);
  __nv_bfloat16 lx = __float2bfloat16_rn(rx);
  __nv_bfloat16 ly = __float2bfloat16_rn(ry);
  h = (uint32_t)__bfloat16_as_ushort(bx) | ((uint32_t)__bfloat16_as_ushort(by) << 16);
  l = (uint32_t)__bfloat16_as_ushort(lx) | ((uint32_t)__bfloat16_as_ushort(ly) << 16);
}

__device__ __forceinline__ void mma_bf16(float* c, const uint32_t* a,
                                         uint32_t b0, uint32_t b1) {
  asm volatile(
      "mma.sync.aligned.m16n8k16.row.col.f32.bf16.bf16.f32 "
      "{%0,%1,%2,%3}, {%4,%5,%6,%7}, {%8,%9}, {%0,%1,%2,%3};\n"
      : "+f"(c[0]), "+f"(c[1]), "+f"(c[2]), "+f"(c[3])
      : "r"(a[0]), "r"(a[1]), "r"(a[2]), "r"(a[3]), "r"(b0), "r"(b1));
}

__device__ __forceinline__ float score_of(float cr, float nqv, float nkv,
                                          float mskv, float scale) {
  return fmaf(-scale, fmaxf(nqv + nkv - 2.f * cr, 0.f), mskv);
}

// ---------------------------------------------------------------------------
// Projection GEMM on tensor cores: C[4096,384] = X @ W^T + bias.
// CTA 128(M)x64(N), 256 thr, warp grid 4x2 (warp tile 32x32), K chunks of 32.
// sel = blockIdx.z: 0->g_q fp32 + norms; 1/2 -> split-packed K + norms; 3 -> g_v.
// ---------------------------------------------------------------------------
__global__ __launch_bounds__(256) void proj_kernel(
    const float* __restrict__ X,
    const float* __restrict__ Wq,  const float* __restrict__ bq,
    const float* __restrict__ Wk1, const float* __restrict__ bk1,
    const float* __restrict__ Wk2, const float* __restrict__ bk2,
    const float* __restrict__ Wv,  const float* __restrict__ bv)
{
  __shared__ uint32_t Ah[128 * 20], Al[128 * 20];
  __shared__ uint32_t Bh[64 * 20],  Bl[64 * 20];

  const int sel = blockIdx.z;
  const float* W    = (sel == 0) ? Wq : (sel == 1) ? Wk1 : (sel == 2) ? Wk2 : Wv;
  const float* bias = (sel == 0) ? bq : (sel == 1) ? bk1 : (sel == 2) ? bk2 : bv;

  const int tid = threadIdx.x;
  const int w = tid >> 5, lane = tid & 31;
  const int g = lane >> 2, t = lane & 3;
  const int wm = (w & 3) * 32, wn = (w >> 2) * 32;
  const int m0 = blockIdx.y * 128, n0 = blockIdx.x * 64;

  float c[2][4][4];
#pragma unroll
  for (int i = 0; i < 2; i++)
#pragma unroll
    for (int j = 0; j < 4; j++)
#pragma unroll
      for (int k = 0; k < 4; k++) c[i][j][k] = 0.f;

  const int sq = tid & 7, sr = tid >> 3;          // stage: quad, row-base

  for (int k0 = 0; k0 < kHid; k0 += 32) {
    __syncthreads();
    // stage X[128][32] split-packed
#pragma unroll
    for (int r = sr; r < 128; r += 32) {
      float4 v = *(const float4*)&X[(size_t)(m0 + r) * kHid + k0 + sq * 4];
      uint32_t h0, l0, h1, l1;
      split2(v.x, v.y, h0, l0);
      split2(v.z, v.w, h1, l1);
      Ah[r * 20 + sq * 2] = h0; Ah[r * 20 + sq * 2 + 1] = h1;
      Al[r * 20 + sq * 2] = l0; Al[r * 20 + sq * 2 + 1] = l1;
    }
    // stage W[64][32]
#pragma unroll
    for (int r = sr; r < 64; r += 32) {
      float4 v = *(const float4*)&W[(size_t)(n0 + r) * kHid + k0 + sq * 4];
      uint32_t h0, l0, h1, l1;
      split2(v.x, v.y, h0, l0);
      split2(v.z, v.w, h1, l1);
      Bh[r * 20 + sq * 2] = h0; Bh[r * 20 + sq * 2 + 1] = h1;
      Bl[r * 20 + sq * 2] = l0; Bl[r * 20 + sq * 2 + 1] = l1;
    }
    __syncthreads();

#pragma unroll
    for (int ks = 0; ks < 2; ks++) {
      uint32_t ah[2][4], al[2][4];
#pragma unroll
      for (int tm = 0; tm < 2; tm++) {
        const int base = (wm + tm * 16 + g) * 20 + 8 * ks + t;
        ah[tm][0] = Ah[base];       ah[tm][1] = Ah[base + 160];
        ah[tm][2] = Ah[base + 4];   ah[tm][3] = Ah[base + 164];
        al[tm][0] = Al[base];       al[tm][1] = Al[base + 160];
        al[tm][2] = Al[base + 4];   al[tm][3] = Al[base + 164];
      }
#pragma unroll
      for (int nc = 0; nc < 4; nc++) {
        const int nb = (wn + nc * 8 + g) * 20 + 8 * ks + t;
        uint32_t b0h = Bh[nb], b1h = Bh[nb + 4];
        uint32_t b0l = Bl[nb], b1l = Bl[nb + 4];
#pragma unroll
        for (int tm = 0; tm < 2; tm++) {
          mma_bf16(c[tm][nc], ah[tm], b0h, b1h);
          mma_bf16(c[tm][nc], ah[tm], b0l, b1l);
          mma_bf16(c[tm][nc], al[tm], b0h, b1h);
        }
      }
    }
  }

  // ---- epilogue: bias, norms, typed stores ----
  const int head = (n0 + wn) >> 5;
#pragma unroll
  for (int nc = 0; nc < 4; nc++) {
    const float bb0 = bias[n0 + wn + nc * 8 + 2 * t];
    const float bb1 = bias[n0 + wn + nc * 8 + 2 * t + 1];
#pragma unroll
    for (int tm = 0; tm < 2; tm++) {
      c[tm][nc][0] += bb0; c[tm][nc][1] += bb1;
      c[tm][nc][2] += bb0; c[tm][nc][3] += bb1;
    }
  }

  if (sel < 3) {
    float* nrm = (sel == 0) ? g_nq : (sel == 1) ? g_nk1 : g_nk2;
    float ps[2][2] = {{0.f, 0.f}, {0.f, 0.f}};
#pragma unroll
    for (int tm = 0; tm < 2; tm++)
#pragma unroll
      for (int nc = 0; nc < 4; nc++) {
        ps[tm][0] = fmaf(c[tm][nc][0], c[tm][nc][0],
                    fmaf(c[tm][nc][1], c[tm][nc][1], ps[tm][0]));
        ps[tm][1] = fmaf(c[tm][nc][2], c[tm][nc][2],
                    fmaf(c[tm][nc][3], c[tm][nc][3], ps[tm][1]));
      }
#pragma unroll
    for (int tm = 0; tm < 2; tm++)
#pragma unroll
      for (int hh = 0; hh < 2; hh++) {
#pragma unroll
        for (int o = 1; o < 4; o <<= 1)
          ps[tm][hh] += __shfl_xor_sync(0xffffffffu, ps[tm][hh], o);
      }
    if (t == 0) {
#pragma unroll
      for (int tm = 0; tm < 2; tm++)
#pragma unroll
        for (int hh = 0; hh < 2; hh++) {
          const int r = m0 + wm + tm * 16 + g + hh * 8;
          const int b = r >> 10, s = r & 1023;
          nrm[(b * kH + head) * kS + s] = ps[tm][hh];
        }
    }
  }

  if (sel == 0 || sel == 3) {
    float* out = (sel == 0) ? g_q : g_v;
#pragma unroll
    for (int tm = 0; tm < 2; tm++)
#pragma unroll
      for (int nc = 0; nc < 4; nc++) {
        const int d = nc * 8 + 2 * t;
        const int r0 = m0 + wm + tm * 16 + g;
        {
          const int b = r0 >> 10, s = r0 & 1023;
          *(float2*)&out[(((size_t)b * kH + head) * kS + s) * kD + d] =
              make_float2(c[tm][nc][0], c[tm][nc][1]);
        }
        {
          const int r1 = r0 + 8;
          const int b = r1 >> 10, s = r1 & 1023;
          *(float2*)&out[(((size_t)b * kH + head) * kS + s) * kD + d] =
              make_float2(c[tm][nc][2], c[tm][nc][3]);
        }
      }
  } else {
    uint32_t* outh = (sel == 1) ? g_k1h : g_k2h;
    uint32_t* outl = (sel == 1) ? g_k1l : g_k2l;
    // fragment-permuted position: pair p=nc*4+t stored at t*4+nc so the
    // attention kernel's per-thread fragment {t,t+4,t+8,t+12} is one uint4.
#pragma unroll
    for (int tm = 0; tm < 2; tm++)
#pragma unroll
      for (int nc = 0; nc < 4; nc++) {
        const int pos = t * 4 + nc;
        const int r0 = m0 + wm + tm * 16 + g;
        uint32_t h, l;
        {
          const int b = r0 >> 10, s = r0 & 1023;
          split2(c[tm][nc][0], c[tm][nc][1], h, l);
          const size_t o = ((size_t)(b * kH + head) * kS + s) * 16 + pos;
          outh[o] = h; outl[o] = l;
        }
        {
          const int r1 = r0 + 8;
          const int b = r1 >> 10, s = r1 & 1023;
          split2(c[tm][nc][2], c[tm][nc][3], h, l);
          const size_t o = ((size_t)(b * kH + head) * kS + s) * 16 + pos;
          outh[o] = h; outl[o] = l;
        }
      }
  }
}

// ---------------------------------------------------------------------------
// Fused attention, 2 passes, all-tensor. Block = (128 q rows, one bh), 256 thr.
// Fragment loads are LDS.128 (K) / LDS.64 (V) via permuted layouts.
// ---------------------------------------------------------------------------
__device__ __forceinline__ void score6(float* c,
                                       const uint32_t aqh[2][4],
                                       const uint32_t aql[2][4],
                                       const uint32_t* __restrict__ Kh,
                                       const uint32_t* __restrict__ Kl,
                                       int rb) {
  uint4 fh = *(const uint4*)&Kh[rb];
  uint4 fl = *(const uint4*)&Kl[rb];
  c[0] = c[1] = c[2] = c[3] = 0.f;
  mma_bf16(c, aqh[0], fh.x, fh.y);
  mma_bf16(c, aqh[0], fl.x, fl.y);
  mma_bf16(c, aql[0], fh.x, fh.y);
  mma_bf16(c, aqh[1], fh.z, fh.w);
  mma_bf16(c, aqh[1], fl.z, fl.w);
  mma_bf16(c, aql[1], fh.z, fh.w);
}

__global__ __launch_bounds__(256, 3) void attn_kernel(
    const float* __restrict__ mask, const float* __restrict__ pi,
    float* __restrict__ out_ctx, float* __restrict__ out_probs)
{
  extern __shared__ uint32_t su[];
  float* nqs  = (float*)(su + U_NQ);
  float* nk1s = (float*)(su + U_NK1);
  float* nk2s = (float*)(su + U_NK2);
  float* msk  = (float*)(su + U_MSK);
  uint32_t* K1h = su + U_K1H;
  uint32_t* K1l = su + U_K1L;
  uint32_t* K2h = su + U_K2H;
  uint32_t* K2l = su + U_K2L;
  uint32_t* Vth = su + U_VTH;
  uint32_t* Vtl = su + U_VTL;

  const int tid = threadIdx.x;
  const int w = tid >> 5, lane = tid & 31;
  const int g = lane >> 2, t = lane & 3;
  const int R0 = w * 16 + g, R1 = R0 + 8;

  const int qt = blockIdx.x, bh = blockIdx.y;
  const int b = bh / kH, h = bh % kH;
  const int q0 = qt * 128;
  const int nbase = bh * kS;
  const size_t gbase = (size_t)bh * kS * kD;

  const float pi0 = fminf(fmaxf(pi[h],      1e-6f), 2.0f);
  const float pi1 = fminf(fmaxf(pi[kH + h], 1e-6f), 2.0f);
  const float lp0 = __logf(pi0), lp1 = __logf(pi1);

  // ---- stage Q fp32 (aliases K region), build persistent split A fragments ----
  {
    float* qst = (float*)(su + U_K1H);   // [128][33]
    for (int i = tid; i < 1024; i += 256) {
      const int j = i >> 3, dg = (i & 7) * 4;
      float4 v = *(const float4*)&g_q[gbase + (size_t)(q0 + j) * kD + dg];
      qst[j * 33 + dg + 0] = v.x; qst[j * 33 + dg + 1] = v.y;
      qst[j * 33 + dg + 2] = v.z; qst[j * 33 + dg + 3] = v.w;
    }
    if (tid < 128) nqs[tid] = g_nq[nbase + q0 + tid];
  }
  __syncthreads();

  uint32_t aqh[2][4], aql[2][4];
  {
    float* qst = (float*)(su + U_K1H);
#pragma unroll
    for (int ks = 0; ks < 2; ks++) {
      const int d0 = 16 * ks + 2 * t;
      split2(qst[R0 * 33 + d0],     qst[R0 * 33 + d0 + 1], aqh[ks][0], aql[ks][0]);
      split2(qst[R1 * 33 + d0],     qst[R1 * 33 + d0 + 1], aqh[ks][1], aql[ks][1]);
      split2(qst[R0 * 33 + d0 + 8], qst[R0 * 33 + d0 + 9], aqh[ks][2], aql[ks][2]);
      split2(qst[R1 * 33 + d0 + 8], qst[R1 * 33 + d0 + 9], aqh[ks][3], aql[ks][3]);
    }
  }
  const float nq0 = nqs[R0], nq1 = nqs[R1];
  __syncthreads();

  // K tile copy: layout identical in global and smem (16 u32 rows, permuted).
#define LOAD_K(j0)                                                            \
  {                                                                           \
    const size_t gw = (size_t)(nbase + (j0)) * 16;                            \
    for (int i = tid * 4; i < 2048; i += 1024) {                              \
      *(uint4*)&K1h[i] = *(const uint4*)&g_k1h[gw + i];                       \
      *(uint4*)&K1l[i] = *(const uint4*)&g_k1l[gw + i];                       \
      *(uint4*)&K2h[i] = *(const uint4*)&g_k2h[gw + i];                       \
      *(uint4*)&K2l[i] = *(const uint4*)&g_k2l[gw + i];                       \
    }                                                                         \
    if (tid < 128) {                                                          \
      nk1s[tid] = g_nk1[nbase + (j0) + tid];                                  \
      nk2s[tid] = g_nk2[nbase + (j0) + tid];                                  \
      msk[tid]  = mask[b * kS + (j0) + tid];                                  \
    }                                                                         \
  }

  // ====== pass 1: exact maxes + fixed-reference (unshifted) rowsums ======
  float m1a = -1e30f, m1b = -1e30f, m2a = -1e30f, m2b = -1e30f;
  float l1a = 0.f, l1b = 0.f, l2a = 0.f, l2b = 0.f;

  for (int kt = 0; kt < 8; kt++) {
    __syncthreads();
    LOAD_K(kt * 128)
    __syncthreads();
#pragma unroll 2
    for (int nt = 0; nt < 16; nt++) {
      const int rb = ((nt * 8 + g) << 4) + t * 4;
      const int col0 = nt * 8 + 2 * t;
      const float2 mkv  = *(const float2*)&msk[col0];
      const float2 nk1v = *(const float2*)&nk1s[col0];
      const float2 nk2v = *(const float2*)&nk2s[col0];
      float c1[4], c2[4];
      score6(c1, aqh, aql, K1h, K1l, rb);
      score6(c2, aqh, aql, K2h, K2l, rb);
      {
        float s0 = score_of(c1[0], nq0, nk1v.x, mkv.x, kC1);
        float s1 = score_of(c1[1], nq0, nk1v.y, mkv.y, kC1);
        m1a = fmaxf(m1a, fmaxf(s0, s1));
        l1a += __expf(s0) + __expf(s1);
      }
      {
        float s0 = score_of(c1[2], nq1, nk1v.x, mkv.x, kC1);
        float s1 = score_of(c1[3], nq1, nk1v.y, mkv.y, kC1);
        m1b = fmaxf(m1b, fmaxf(s0, s1));
        l1b += __expf(s0) + __expf(s1);
      }
      {
        float s0 = score_of(c2[0], nq0, nk2v.x, mkv.x, kC2);
        float s1 = score_of(c2[1], nq0, nk2v.y, mkv.y, kC2);
        m2a = fmaxf(m2a, fmaxf(s0, s1));
        l2a += __expf(s0) + __expf(s1);
      }
      {
        float s0 = score_of(c2[2], nq1, nk2v.x, mkv.x, kC2);
        float s1 = score_of(c2[3], nq1, nk2v.y, mkv.y, kC2);
        m2b = fmaxf(m2b, fmaxf(s0, s1));
        l2b += __expf(s0) + __expf(s1);
      }
    }
  }
  // quad combine: plain sum + max (fixed reference, no rescale)
#pragma unroll
  for (int o = 1; o < 4; o <<= 1) {
    m1a = fmaxf(m1a, __shfl_xor_sync(0xffffffffu, m1a, o));
    m1b = fmaxf(m1b, __shfl_xor_sync(0xffffffffu, m1b, o));
    m2a = fmaxf(m2a, __shfl_xor_sync(0xffffffffu, m2a, o));
    m2b = fmaxf(m2b, __shfl_xor_sync(0xffffffffu, m2b, o));
    l1a += __shfl_xor_sync(0xffffffffu, l1a, o);
    l1b += __shfl_xor_sync(0xffffffffu, l1b, o);
    l2a += __shfl_xor_sync(0xffffffffu, l2a, o);
    l2b += __shfl_xor_sync(0xffffffffu, l2b, o);
  }
  const float inv0 = 1.0f / (pi0 * __expf(-m1a) * l1a +
                             pi1 * __expf(-m2a) * l2a + 1e-6f);
  const float inv1 = 1.0f / (pi0 * __expf(-m1b) * l1b +
                             pi1 * __expf(-m2b) * l2b + 1e-6f);
  // fold ln(pi) into the exp arguments for pass 2
  const float z1a = lp0 - m1a, z1b = lp0 - m1b;
  const float z2a = lp1 - m2a, z2b = lp1 - m2b;

  // ============ pass 2: normalized probs + E@V on tensor pipe ============
  float cctx[4][4];
#pragma unroll
  for (int i = 0; i < 4; i++)
#pragma unroll
    for (int j = 0; j < 4; j++) cctx[i][j] = 0.f;

  uint32_t eh[4], el[4];

  for (int kt = 0; kt < 8; kt++) {
    __syncthreads();
    LOAD_K(kt * 128)
    // V transpose-pack, pair-permuted within 8-groups for uint2 fragment loads
    for (int i = tid; i < 2048; i += 256) {
      const int jp = i >> 5, d = i & 31;
      const size_t vo = gbase + (size_t)(kt * 128 + 2 * jp) * kD + d;
      float v0 = g_v[vo], v1 = g_v[vo + kD];
      uint32_t hh, ll;
      split2(v0, v1, hh, ll);
      const int pos = (jp & ~7) + ((jp & 3) << 1) + ((jp >> 2) & 1);
      Vth[d * 72 + pos] = hh;
      Vtl[d * 72 + pos] = ll;
    }
    __syncthreads();

#pragma unroll 2
    for (int nt = 0; nt < 16; nt++) {
      const int rb = ((nt * 8 + g) << 4) + t * 4;
      const int col0 = nt * 8 + 2 * t;
      const float2 mkv  = *(const float2*)&msk[col0];
      const float2 nk1v = *(const float2*)&nk1s[col0];
      const float2 nk2v = *(const float2*)&nk2s[col0];
      float c1[4], c2[4];
      score6(c1, aqh, aql, K1h, K1l, rb);
      score6(c2, aqh, aql, K2h, K2l, rb);
      float p00 = (__expf(score_of(c1[0], nq0, nk1v.x, mkv.x, kC1) + z1a)
                 + __expf(score_of(c2[0], nq0, nk2v.x, mkv.x, kC2) + z2a)) * inv0;
      float p01 = (__expf(score_of(c1[1], nq0, nk1v.y, mkv.y, kC1) + z1a)
                 + __expf(score_of(c2[1], nq0, nk2v.y, mkv.y, kC2) + z2a)) * inv0;
      float p10 = (__expf(score_of(c1[2], nq1, nk1v.x, mkv.x, kC1) + z1b)
                 + __expf(score_of(c2[2], nq1, nk2v.x, mkv.x, kC2) + z2b)) * inv1;
      float p11 = (__expf(score_of(c1[3], nq1, nk1v.y, mkv.y, kC1) + z1b)
                 + __expf(score_of(c2[3], nq1, nk2v.y, mkv.y, kC2) + z2b)) * inv1;

      // normalized probs straight from registers (streaming stores)
      const size_t pb = ((size_t)bh * kS + q0 + R0) * kS + kt * 128 + col0;
      __stcs((float2*)&out_probs[pb], make_float2(p00, p01));
      __stcs((float2*)&out_probs[pb + 8 * kS], make_float2(p10, p11));

      // E fragment accumulation (A-layout is exactly these lanes/pairs)
      if ((nt & 1) == 0) {
        split2(p00, p01, eh[0], el[0]);
        split2(p10, p11, eh[1], el[1]);
      } else {
        split2(p00, p01, eh[2], el[2]);
        split2(p10, p11, eh[3], el[3]);
        const int ks = nt >> 1;
#pragma unroll
        for (int nd = 0; nd < 4; nd++) {
          const int vb = (nd * 8 + g) * 72 + 8 * ks + 2 * t;
          uint2 vh = *(const uint2*)&Vth[vb];
          uint2 vl = *(const uint2*)&Vtl[vb];
          mma_bf16(cctx[nd], eh, vh.x, vh.y);
          mma_bf16(cctx[nd], eh, vl.x, vl.y);
          mma_bf16(cctx[nd], el, vh.x, vh.y);
        }
      }
    }
  }

  // ctx store (already normalized since E carried inv)
#pragma unroll
  for (int nd = 0; nd < 4; nd++) {
    const int d = nd * 8 + 2 * t;
    *(float2*)&out_ctx[((size_t)b * kS + q0 + R0) * kAH + h * kD + d] =
        make_float2(cctx[nd][0], cctx[nd][1]);
    *(float2*)&out_ctx[((size_t)b * kS + q0 + R1) * kAH + h * kD + d] =
        make_float2(cctx[nd][2], cctx[nd][3]);
  }
#undef LOAD_K
}

// ---------------------------------------------------------------------------
extern "C" void kernel_launch(void* const* d_in, const int* in_sizes, int n_in,
                              void* d_out, int out_size) {
  (void)in_sizes; (void)n_in; (void)out_size;
  const float* hs   = (const float*)d_in[0];
  const float* mask = (const float*)d_in[1];
  const float* Wq   = (const float*)d_in[2];
  const float* bq   = (const float*)d_in[3];
  const float* Wk1  = (const float*)d_in[4];
  const float* bk1  = (const float*)d_in[5];
  const float* Wk2  = (const float*)d_in[6];
  const float* bk2  = (const float*)d_in[7];
  const float* Wv   = (const float*)d_in[8];
  const float* bv   = (const float*)d_in[9];
  const float* pi   = (const float*)d_in[10];

  float* out_ctx   = (float*)d_out;
  float* out_probs = out_ctx + (size_t)kB * kS * kAH;

  cudaFuncSetAttribute(attn_kernel, cudaFuncAttributeMaxDynamicSharedMemorySize,
                       kAttnSmemBytes);

  dim3 pgrid(kAH / 64, (kB * kS) / 128, 4);   // (6, 32, 4) = 768 CTAs
  proj_kernel<<<pgrid, 256>>>(hs, Wq, bq, Wk1, bk1, Wk2, bk2, Wv, bv);
  attn_kernel<<<dim3(kS / 128, kBH), 256, kAttnSmemBytes>>>(
      mask, pi, out_ctx, out_probs);
}

// round 10
// speedup vs baseline: 3.7992x; 1.1107x over previous
#include <cuda_runtime.h>
#include <cuda_bf16.h>
#include <cstdint>

// ---------------------------------------------------------------------------
// MGKBertSelfAttention: B=4, S=1024, HID=768, H=12, D=32, AH=384
// out = [ctx (B,S,AH) ; probs (B,H,S,S)]  fp32
// mma.sync m16n8k16 bf16, 2-term hi/lo split (3-product, fp32-equiv precision).
// R10: log2-domain softmax + affine-folded score constants (persistent colc).
// ---------------------------------------------------------------------------

namespace {
constexpr int kB = 4, kS = 1024, kHid = 768, kH = 12, kD = 32, kAH = 384;
constexpr int kBH = kB * kH;                       // 48
constexpr float kScaling = 0.17677669529663687f;   // 32^-0.5
constexpr float kC1 = 0.5f * kScaling;
constexpr float kC2 = 0.75f * kScaling;
constexpr float kLog2e = 1.4426950408889634f;
constexpr float kC1L = kC1 * kLog2e;               // c1 in log2 domain
constexpr float kC2L = kC2 * kLog2e;
constexpr float kTC1 = 2.0f * kC1L;
constexpr float kTC2 = 2.0f * kC2L;

// attn smem layout (u32 units)
constexpr int U_COLC1 = 0;            // 1024 f32: mask*log2e - c1l*nk1 (all cols)
constexpr int U_COLC2 = 1024;         // 1024 f32
constexpr int U_K1H   = 2048;         // K tiles: [128][16] u32, fragment-permuted
constexpr int U_K1L   = U_K1H + 2048;
constexpr int U_K2H   = U_K1L + 2048;
constexpr int U_K2L   = U_K2H + 2048;
constexpr int U_VTH   = U_K2L + 2048; // Vt packed: [32][72] u32 (pair-permuted)
constexpr int U_VTL   = U_VTH + 2304;
constexpr int kAttnSmemU32 = U_VTL + 2304;          // 14912 u32
constexpr int kAttnSmemBytes = kAttnSmemU32 * 4;    // 59648 B (x3 = 179 KB OK)
}

// Scratch (device globals; allocation is forbidden)
__device__ float    g_q  [kBH * kS * kD];   // fp32 [bh][s][d]
__device__ float    g_v  [kBH * kS * kD];   // fp32 [bh][s][d]
__device__ uint32_t g_k1h[kBH * kS * 16];   // bf16x2 pairs, fragment-permuted
__device__ uint32_t g_k1l[kBH * kS * 16];
__device__ uint32_t g_k2h[kBH * kS * 16];
__device__ uint32_t g_k2l[kBH * kS * 16];
__device__ float    g_nq [kBH * kS];
__device__ float    g_nk1[kBH * kS];
__device__ float    g_nk2[kBH * kS];

// ---------------------------------------------------------------------------
// helpers
// ---------------------------------------------------------------------------
__device__ __forceinline__ float ex2(float x) {
  float r;
  asm("ex2.approx.f32 %0, %1;" : "=f"(r) : "f"(x));
  return r;
}
__device__ __forceinline__ void split2(float x, float y, uint32_t& h, uint32_t& l) {
  __nv_bfloat16 bx = __float2bfloat16_rn(x);
  __nv_bfloat16 by = __float2bfloat16_rn(y);
  float rx = x - __bfloat162float(bx);
  float ry = y - __bfloat162float(by);
  __nv_bfloat16 lx = __float2bfloat16_rn(rx);
  __nv_bfloat16 ly = __float2bfloat16_rn(ry);
  h = (uint32_t)__bfloat16_as_ushort(bx) | ((uint32_t)__bfloat16_as_ushort(by) << 16);
  l = (uint32_t)__bfloat16_as_ushort(lx) | ((uint32_t)__bfloat16_as_ushort(ly) << 16);
}

__device__ __forceinline__ void mma_bf16(float* c, const uint32_t* a,
                                         uint32_t b0, uint32_t b1) {
  asm volatile(
      "mma.sync.aligned.m16n8k16.row.col.f32.bf16.bf16.f32 "
      "{%0,%1,%2,%3}, {%4,%5,%6,%7}, {%8,%9}, {%0,%1,%2,%3};\n"
      : "+f"(c[0]), "+f"(c[1]), "+f"(c[2]), "+f"(c[3])
      : "r"(a[0]), "r"(a[1]), "r"(a[2]), "r"(a[3]), "r"(b0), "r"(b1));
}

// ---------------------------------------------------------------------------
// Projection GEMM on tensor cores: C[4096,384] = X @ W^T + bias.
// (unchanged from R9)
// ---------------------------------------------------------------------------
__global__ __launch_bounds__(256) void proj_kernel(
    const float* __restrict__ X,
    const float* __restrict__ Wq,  const float* __restrict__ bq,
    const float* __restrict__ Wk1, const float* __restrict__ bk1,
    const float* __restrict__ Wk2, const float* __restrict__ bk2,
    const float* __restrict__ Wv,  const float* __restrict__ bv)
{
  __shared__ uint32_t Ah[128 * 20], Al[128 * 20];
  __shared__ uint32_t Bh[64 * 20],  Bl[64 * 20];

  const int sel = blockIdx.z;
  const float* W    = (sel == 0) ? Wq : (sel == 1) ? Wk1 : (sel == 2) ? Wk2 : Wv;
  const float* bias = (sel == 0) ? bq : (sel == 1) ? bk1 : (sel == 2) ? bk2 : bv;

  const int tid = threadIdx.x;
  const int w = tid >> 5, lane = tid & 31;
  const int g = lane >> 2, t = lane & 3;
  const int wm = (w & 3) * 32, wn = (w >> 2) * 32;
  const int m0 = blockIdx.y * 128, n0 = blockIdx.x * 64;

  float c[2][4][4];
#pragma unroll
  for (int i = 0; i < 2; i++)
#pragma unroll
    for (int j = 0; j < 4; j++)
#pragma unroll
      for (int k = 0; k < 4; k++) c[i][j][k] = 0.f;

  const int sq = tid & 7, sr = tid >> 3;

  for (int k0 = 0; k0 < kHid; k0 += 32) {
    __syncthreads();
#pragma unroll
    for (int r = sr; r < 128; r += 32) {
      float4 v = *(const float4*)&X[(size_t)(m0 + r) * kHid + k0 + sq * 4];
      uint32_t h0, l0, h1, l1;
      split2(v.x, v.y, h0, l0);
      split2(v.z, v.w, h1, l1);
      Ah[r * 20 + sq * 2] = h0; Ah[r * 20 + sq * 2 + 1] = h1;
      Al[r * 20 + sq * 2] = l0; Al[r * 20 + sq * 2 + 1] = l1;
    }
#pragma unroll
    for (int r = sr; r < 64; r += 32) {
      float4 v = *(const float4*)&W[(size_t)(n0 + r) * kHid + k0 + sq * 4];
      uint32_t h0, l0, h1, l1;
      split2(v.x, v.y, h0, l0);
      split2(v.z, v.w, h1, l1);
      Bh[r * 20 + sq * 2] = h0; Bh[r * 20 + sq * 2 + 1] = h1;
      Bl[r * 20 + sq * 2] = l0; Bl[r * 20 + sq * 2 + 1] = l1;
    }
    __syncthreads();

#pragma unroll
    for (int ks = 0; ks < 2; ks++) {
      uint32_t ah[2][4], al[2][4];
#pragma unroll
      for (int tm = 0; tm < 2; tm++) {
        const int base = (wm + tm * 16 + g) * 20 + 8 * ks + t;
        ah[tm][0] = Ah[base];       ah[tm][1] = Ah[base + 160];
        ah[tm][2] = Ah[base + 4];   ah[tm][3] = Ah[base + 164];
        al[tm][0] = Al[base];       al[tm][1] = Al[base + 160];
        al[tm][2] = Al[base + 4];   al[tm][3] = Al[base + 164];
      }
#pragma unroll
      for (int nc = 0; nc < 4; nc++) {
        const int nb = (wn + nc * 8 + g) * 20 + 8 * ks + t;
        uint32_t b0h = Bh[nb], b1h = Bh[nb + 4];
        uint32_t b0l = Bl[nb], b1l = Bl[nb + 4];
#pragma unroll
        for (int tm = 0; tm < 2; tm++) {
          mma_bf16(c[tm][nc], ah[tm], b0h, b1h);
          mma_bf16(c[tm][nc], ah[tm], b0l, b1l);
          mma_bf16(c[tm][nc], al[tm], b0h, b1h);
        }
      }
    }
  }

  const int head = (n0 + wn) >> 5;
#pragma unroll
  for (int nc = 0; nc < 4; nc++) {
    const float bb0 = bias[n0 + wn + nc * 8 + 2 * t];
    const float bb1 = bias[n0 + wn + nc * 8 + 2 * t + 1];
#pragma unroll
    for (int tm = 0; tm < 2; tm++) {
      c[tm][nc][0] += bb0; c[tm][nc][1] += bb1;
      c[tm][nc][2] += bb0; c[tm][nc][3] += bb1;
    }
  }

  if (sel < 3) {
    float* nrm = (sel == 0) ? g_nq : (sel == 1) ? g_nk1 : g_nk2;
    float ps[2][2] = {{0.f, 0.f}, {0.f, 0.f}};
#pragma unroll
    for (int tm = 0; tm < 2; tm++)
#pragma unroll
      for (int nc = 0; nc < 4; nc++) {
        ps[tm][0] = fmaf(c[tm][nc][0], c[tm][nc][0],
                    fmaf(c[tm][nc][1], c[tm][nc][1], ps[tm][0]));
        ps[tm][1] = fmaf(c[tm][nc][2], c[tm][nc][2],
                    fmaf(c[tm][nc][3], c[tm][nc][3], ps[tm][1]));
      }
#pragma unroll
    for (int tm = 0; tm < 2; tm++)
#pragma unroll
      for (int hh = 0; hh < 2; hh++) {
#pragma unroll
        for (int o = 1; o < 4; o <<= 1)
          ps[tm][hh] += __shfl_xor_sync(0xffffffffu, ps[tm][hh], o);
      }
    if (t == 0) {
#pragma unroll
      for (int tm = 0; tm < 2; tm++)
#pragma unroll
        for (int hh = 0; hh < 2; hh++) {
          const int r = m0 + wm + tm * 16 + g + hh * 8;
          const int b = r >> 10, s = r & 1023;
          nrm[(b * kH + head) * kS + s] = ps[tm][hh];
        }
    }
  }

  if (sel == 0 || sel == 3) {
    float* out = (sel == 0) ? g_q : g_v;
#pragma unroll
    for (int tm = 0; tm < 2; tm++)
#pragma unroll
      for (int nc = 0; nc < 4; nc++) {
        const int d = nc * 8 + 2 * t;
        const int r0 = m0 + wm + tm * 16 + g;
        {
          const int b = r0 >> 10, s = r0 & 1023;
          *(float2*)&out[(((size_t)b * kH + head) * kS + s) * kD + d] =
              make_float2(c[tm][nc][0], c[tm][nc][1]);
        }
        {
          const int r1 = r0 + 8;
          const int b = r1 >> 10, s = r1 & 1023;
          *(float2*)&out[(((size_t)b * kH + head) * kS + s) * kD + d] =
              make_float2(c[tm][nc][2], c[tm][nc][3]);
        }
      }
  } else {
    uint32_t* outh = (sel == 1) ? g_k1h : g_k2h;
    uint32_t* outl = (sel == 1) ? g_k1l : g_k2l;
#pragma unroll
    for (int tm = 0; tm < 2; tm++)
#pragma unroll
      for (int nc = 0; nc < 4; nc++) {
        const int pos = t * 4 + nc;
        const int r0 = m0 + wm + tm * 16 + g;
        uint32_t h, l;
        {
          const int b = r0 >> 10, s = r0 & 1023;
          split2(c[tm][nc][0], c[tm][nc][1], h, l);
          const size_t o = ((size_t)(b * kH + head) * kS + s) * 16 + pos;
          outh[o] = h; outl[o] = l;
        }
        {
          const int r1 = r0 + 8;
          const int b = r1 >> 10, s = r1 & 1023;
          split2(c[tm][nc][2], c[tm][nc][3], h, l);
          const size_t o = ((size_t)(b * kH + head) * kS + s) * 16 + pos;
          outh[o] = h; outl[o] = l;
        }
      }
  }
}

// ---------------------------------------------------------------------------
// Fused attention, 2 passes, all-tensor, log2-domain softmax.
// Block = (128 q rows, one bh), 256 threads.
// score' (log2 units) = fma(2*c1l, cross, colc[col] + rq_row)
// ---------------------------------------------------------------------------
__device__ __forceinline__ void score6(float* c,
                                       const uint32_t aqh[2][4],
                                       const uint32_t aql[2][4],
                                       const uint32_t* __restrict__ Kh,
                                       const uint32_t* __restrict__ Kl,
                                       int rb) {
  uint4 fh = *(const uint4*)&Kh[rb];
  uint4 fl = *(const uint4*)&Kl[rb];
  c[0] = c[1] = c[2] = c[3] = 0.f;
  mma_bf16(c, aqh[0], fh.x, fh.y);
  mma_bf16(c, aqh[0], fl.x, fl.y);
  mma_bf16(c, aql[0], fh.x, fh.y);
  mma_bf16(c, aqh[1], fh.z, fh.w);
  mma_bf16(c, aqh[1], fl.z, fl.w);
  mma_bf16(c, aql[1], fh.z, fh.w);
}

__global__ __launch_bounds__(256, 3) void attn_kernel(
    const float* __restrict__ mask, const float* __restrict__ pi,
    float* __restrict__ out_ctx, float* __restrict__ out_probs)
{
  extern __shared__ uint32_t su[];
  float* colc1 = (float*)(su + U_COLC1);
  float* colc2 = (float*)(su + U_COLC2);
  uint32_t* K1h = su + U_K1H;
  uint32_t* K1l = su + U_K1L;
  uint32_t* K2h = su + U_K2H;
  uint32_t* K2l = su + U_K2L;
  uint32_t* Vth = su + U_VTH;
  uint32_t* Vtl = su + U_VTL;

  const int tid = threadIdx.x;
  const int w = tid >> 5, lane = tid & 31;
  const int g = lane >> 2, t = lane & 3;
  const int R0 = w * 16 + g, R1 = R0 + 8;

  const int qt = blockIdx.x, bh = blockIdx.y;
  const int b = bh / kH, h = bh % kH;
  const int q0 = qt * 128;
  const int nbase = bh * kS;
  const size_t gbase = (size_t)bh * kS * kD;

  const float pi0 = fminf(fmaxf(pi[h],      1e-6f), 2.0f);
  const float pi1 = fminf(fmaxf(pi[kH + h], 1e-6f), 2.0f);
  const float lp0 = __log2f(pi0), lp1 = __log2f(pi1);

  // ---- persistent per-column constants for ALL 1024 cols ----
  for (int i = tid; i < kS; i += 256) {
    const float mk = mask[b * kS + i] * kLog2e;
    colc1[i] = fmaf(-kC1L, g_nk1[nbase + i], mk);
    colc2[i] = fmaf(-kC2L, g_nk2[nbase + i], mk);
  }

  // ---- stage Q fp32 (aliases K region), build persistent split A fragments ----
  {
    float* qst = (float*)(su + U_K1H);   // [128][33]
    for (int i = tid; i < 1024; i += 256) {
      const int j = i >> 3, dg = (i & 7) * 4;
      float4 v = *(const float4*)&g_q[gbase + (size_t)(q0 + j) * kD + dg];
      qst[j * 33 + dg + 0] = v.x; qst[j * 33 + dg + 1] = v.y;
      qst[j * 33 + dg + 2] = v.z; qst[j * 33 + dg + 3] = v.w;
    }
  }
  __syncthreads();

  uint32_t aqh[2][4], aql[2][4];
  {
    float* qst = (float*)(su + U_K1H);
#pragma unroll
    for (int ks = 0; ks < 2; ks++) {
      const int d0 = 16 * ks + 2 * t;
      split2(qst[R0 * 33 + d0],     qst[R0 * 33 + d0 + 1], aqh[ks][0], aql[ks][0]);
      split2(qst[R1 * 33 + d0],     qst[R1 * 33 + d0 + 1], aqh[ks][1], aql[ks][1]);
      split2(qst[R0 * 33 + d0 + 8], qst[R0 * 33 + d0 + 9], aqh[ks][2], aql[ks][2]);
      split2(qst[R1 * 33 + d0 + 8], qst[R1 * 33 + d0 + 9], aqh[ks][3], aql[ks][3]);
    }
  }
  // per-thread row constants (log2 domain)
  const float nq0 = g_nq[nbase + q0 + R0];
  const float nq1 = g_nq[nbase + q0 + R1];
  const float rq1a = -kC1L * nq0, rq1b = -kC1L * nq1;
  const float rq2a = -kC2L * nq0, rq2b = -kC2L * nq1;
  __syncthreads();

#define LOAD_K(j0)                                                            \
  {                                                                           \
    const size_t gw = (size_t)(nbase + (j0)) * 16;                            \
    for (int i = tid * 4; i < 2048; i += 1024) {                              \
      *(uint4*)&K1h[i] = *(const uint4*)&g_k1h[gw + i];                       \
      *(uint4*)&K1l[i] = *(const uint4*)&g_k1l[gw + i];                       \
      *(uint4*)&K2h[i] = *(const uint4*)&g_k2h[gw + i];                       \
      *(uint4*)&K2l[i] = *(const uint4*)&g_k2l[gw + i];                       \
    }                                                                         \
  }

  // ====== pass 1: exact maxes + fixed-reference rowsums (log2 domain) ======
  float m1a = -1e30f, m1b = -1e30f, m2a = -1e30f, m2b = -1e30f;
  float l1a = 0.f, l1b = 0.f, l2a = 0.f, l2b = 0.f;

  for (int kt = 0; kt < 8; kt++) {
    __syncthreads();
    LOAD_K(kt * 128)
    __syncthreads();
#pragma unroll 2
    for (int nt = 0; nt < 16; nt++) {
      const int rb = ((nt * 8 + g) << 4) + t * 4;
      const int col = kt * 128 + nt * 8 + 2 * t;
      const float2 cc1 = *(const float2*)&colc1[col];
      const float2 cc2 = *(const float2*)&colc2[col];
      float c1[4], c2[4];
      score6(c1, aqh, aql, K1h, K1l, rb);
      score6(c2, aqh, aql, K2h, K2l, rb);
      {
        float s0 = fmaf(kTC1, c1[0], cc1.x + rq1a);
        float s1 = fmaf(kTC1, c1[1], cc1.y + rq1a);
        m1a = fmaxf(m1a, fmaxf(s0, s1));
        l1a += ex2(s0) + ex2(s1);
      }
      {
        float s0 = fmaf(kTC1, c1[2], cc1.x + rq1b);
        float s1 = fmaf(kTC1, c1[3], cc1.y + rq1b);
        m1b = fmaxf(m1b, fmaxf(s0, s1));
        l1b += ex2(s0) + ex2(s1);
      }
      {
        float s0 = fmaf(kTC2, c2[0], cc2.x + rq2a);
        float s1 = fmaf(kTC2, c2[1], cc2.y + rq2a);
        m2a = fmaxf(m2a, fmaxf(s0, s1));
        l2a += ex2(s0) + ex2(s1);
      }
      {
        float s0 = fmaf(kTC2, c2[2], cc2.x + rq2b);
        float s1 = fmaf(kTC2, c2[3], cc2.y + rq2b);
        m2b = fmaxf(m2b, fmaxf(s0, s1));
        l2b += ex2(s0) + ex2(s1);
      }
    }
  }
#pragma unroll
  for (int o = 1; o < 4; o <<= 1) {
    m1a = fmaxf(m1a, __shfl_xor_sync(0xffffffffu, m1a, o));
    m1b = fmaxf(m1b, __shfl_xor_sync(0xffffffffu, m1b, o));
    m2a = fmaxf(m2a, __shfl_xor_sync(0xffffffffu, m2a, o));
    m2b = fmaxf(m2b, __shfl_xor_sync(0xffffffffu, m2b, o));
    l1a += __shfl_xor_sync(0xffffffffu, l1a, o);
    l1b += __shfl_xor_sync(0xffffffffu, l1b, o);
    l2a += __shfl_xor_sync(0xffffffffu, l2a, o);
    l2b += __shfl_xor_sync(0xffffffffu, l2b, o);
  }
  // denom = pi0*2^{-m1}*l1 + pi1*2^{-m2}*l2 + 1e-6
  const float inv0 = 1.0f / (pi0 * ex2(-m1a) * l1a +
                             pi1 * ex2(-m2a) * l2a + 1e-6f);
  const float inv1 = 1.0f / (pi0 * ex2(-m1b) * l1b +
                             pi1 * ex2(-m2b) * l2b + 1e-6f);
  // pass-2 row constants: fold log2(pi) - m into rq
  const float rq1a2 = rq1a + lp0 - m1a, rq1b2 = rq1b + lp0 - m1b;
  const float rq2a2 = rq2a + lp1 - m2a, rq2b2 = rq2b + lp1 - m2b;

  // ============ pass 2: normalized probs + E@V on tensor pipe ============
  float cctx[4][4];
#pragma unroll
  for (int i = 0; i < 4; i++)
#pragma unroll
    for (int j = 0; j < 4; j++) cctx[i][j] = 0.f;

  uint32_t eh[4], el[4];

  for (int kt = 0; kt < 8; kt++) {
    __syncthreads();
    LOAD_K(kt * 128)
    // V transpose-pack, pair-permuted within 8-groups for uint2 fragment loads
    for (int i = tid; i < 2048; i += 256) {
      const int jp = i >> 5, d = i & 31;
      const size_t vo = gbase + (size_t)(kt * 128 + 2 * jp) * kD + d;
      float v0 = g_v[vo], v1 = g_v[vo + kD];
      uint32_t hh, ll;
      split2(v0, v1, hh, ll);
      const int pos = (jp & ~7) + ((jp & 3) << 1) + ((jp >> 2) & 1);
      Vth[d * 72 + pos] = hh;
      Vtl[d * 72 + pos] = ll;
    }
    __syncthreads();

#pragma unroll 2
    for (int nt = 0; nt < 16; nt++) {
      const int rb = ((nt * 8 + g) << 4) + t * 4;
      const int col = kt * 128 + nt * 8 + 2 * t;
      const float2 cc1 = *(const float2*)&colc1[col];
      const float2 cc2 = *(const float2*)&colc2[col];
      float c1[4], c2[4];
      score6(c1, aqh, aql, K1h, K1l, rb);
      score6(c2, aqh, aql, K2h, K2l, rb);
      float p00 = (ex2(fmaf(kTC1, c1[0], cc1.x + rq1a2))
                 + ex2(fmaf(kTC2, c2[0], cc2.x + rq2a2))) * inv0;
      float p01 = (ex2(fmaf(kTC1, c1[1], cc1.y + rq1a2))
                 + ex2(fmaf(kTC2, c2[1], cc2.y + rq2a2))) * inv0;
      float p10 = (ex2(fmaf(kTC1, c1[2], cc1.x + rq1b2))
                 + ex2(fmaf(kTC2, c2[2], cc2.x + rq2b2))) * inv1;
      float p11 = (ex2(fmaf(kTC1, c1[3], cc1.y + rq1b2))
                 + ex2(fmaf(kTC2, c2[3], cc2.y + rq2b2))) * inv1;

      // normalized probs straight from registers (streaming stores)
      const size_t pb = ((size_t)bh * kS + q0 + R0) * kS + col;
      __stcs((float2*)&out_probs[pb], make_float2(p00, p01));
      __stcs((float2*)&out_probs[pb + 8 * kS], make_float2(p10, p11));

      // E fragment accumulation (A-layout is exactly these lanes/pairs)
      if ((nt & 1) == 0) {
        split2(p00, p01, eh[0], el[0]);
        split2(p10, p11, eh[1], el[1]);
      } else {
        split2(p00, p01, eh[2], el[2]);
        split2(p10, p11, eh[3], el[3]);
        const int ks = nt >> 1;
#pragma unroll
        for (int nd = 0; nd < 4; nd++) {
          const int vb = (nd * 8 + g) * 72 + 8 * ks + 2 * t;
          uint2 vh = *(const uint2*)&Vth[vb];
          uint2 vl = *(const uint2*)&Vtl[vb];
          mma_bf16(cctx[nd], eh, vh.x, vh.y);
          mma_bf16(cctx[nd], eh, vl.x, vl.y);
          mma_bf16(cctx[nd], el, vh.x, vh.y);
        }
      }
    }
  }

  // ctx store (already normalized since E carried inv)
#pragma unroll
  for (int nd = 0; nd < 4; nd++) {
    const int d = nd * 8 + 2 * t;
    *(float2*)&out_ctx[((size_t)b * kS + q0 + R0) * kAH + h * kD + d] =
        make_float2(cctx[nd][0], cctx[nd][1]);
    *(float2*)&out_ctx[((size_t)b * kS + q0 + R1) * kAH + h * kD + d] =
        make_float2(cctx[nd][2], cctx[nd][3]);
  }
#undef LOAD_K
}

// ---------------------------------------------------------------------------
extern "C" void kernel_launch(void* const* d_in, const int* in_sizes, int n_in,
                              void* d_out, int out_size) {
  (void)in_sizes; (void)n_in; (void)out_size;
  const float* hs   = (const float*)d_in[0];
  const float* mask = (const float*)d_in[1];
  const float* Wq   = (const float*)d_in[2];
  const float* bq   = (const float*)d_in[3];
  const float* Wk1  = (const float*)d_in[4];
  const float* bk1  = (const float*)d_in[5];
  const float* Wk2  = (const float*)d_in[6];
  const float* bk2  = (const float*)d_in[7];
  const float* Wv   = (const float*)d_in[8];
  const float* bv   = (const float*)d_in[9];
  const float* pi   = (const float*)d_in[10];

  float* out_ctx   = (float*)d_out;
  float* out_probs = out_ctx + (size_t)kB * kS * kAH;

  cudaFuncSetAttribute(attn_kernel, cudaFuncAttributeMaxDynamicSharedMemorySize,
                       kAttnSmemBytes);

  dim3 pgrid(kAH / 64, (kB * kS) / 128, 4);   // (6, 32, 4) = 768 CTAs
  proj_kernel<<<pgrid, 256>>>(hs, Wq, bq, Wk1, bk1, Wk2, bk2, Wv, bv);
  attn_kernel<<<dim3(kS / 128, kBH), 256, kAttnSmemBytes>>>(
      mask, pi, out_ctx, out_probs);
}

// round 11
// speedup vs baseline: 3.9014x; 1.0269x over previous
#include <cuda_runtime.h>
#include <cuda_bf16.h>
#include <cstdint>

// ---------------------------------------------------------------------------
// MGKBertSelfAttention: B=4, S=1024, HID=768, H=12, D=32, AH=384
// out = [ctx (B,S,AH) ; probs (B,H,S,S)]  fp32
// mma.sync m16n8k16 bf16, 2-term hi/lo split (3-product, fp32-equiv precision).
// R11: V split/transpose/permute hoisted into proj (attn V stage = raw copy).
// ---------------------------------------------------------------------------

namespace {
constexpr int kB = 4, kS = 1024, kHid = 768, kH = 12, kD = 32, kAH = 384;
constexpr int kBH = kB * kH;                       // 48
constexpr float kScaling = 0.17677669529663687f;   // 32^-0.5
constexpr float kC1 = 0.5f * kScaling;
constexpr float kC2 = 0.75f * kScaling;
constexpr float kLog2e = 1.4426950408889634f;
constexpr float kC1L = kC1 * kLog2e;               // c1 in log2 domain
constexpr float kC2L = kC2 * kLog2e;
constexpr float kTC1 = 2.0f * kC1L;
constexpr float kTC2 = 2.0f * kC2L;

// attn smem layout (u32 units)
constexpr int U_COLC1 = 0;            // 1024 f32: mask*log2e - c1l*nk1 (all cols)
constexpr int U_COLC2 = 1024;         // 1024 f32
constexpr int U_K1H   = 2048;         // K tiles: [128][16] u32, fragment-permuted
constexpr int U_K1L   = U_K1H + 2048;
constexpr int U_K2H   = U_K1L + 2048;
constexpr int U_K2L   = U_K2H + 2048;
constexpr int U_VTH   = U_K2L + 2048; // Vt packed: [32][72] u32 (pair-permuted)
constexpr int U_VTL   = U_VTH + 2304;
constexpr int kAttnSmemU32 = U_VTL + 2304;          // 14912 u32
constexpr int kAttnSmemBytes = kAttnSmemU32 * 4;    // 59648 B (x3 = 179 KB OK)
}

// Scratch (device globals; allocation is forbidden)
__device__ float    g_q  [kBH * kS * kD];   // fp32 [bh][s][d]
__device__ uint32_t g_k1h[kBH * kS * 16];   // bf16x2 pairs, fragment-permuted
__device__ uint32_t g_k1l[kBH * kS * 16];
__device__ uint32_t g_k2h[kBH * kS * 16];
__device__ uint32_t g_k2l[kBH * kS * 16];
__device__ uint32_t g_vth[kBH * 8 * kD * 64];  // V attn-ready: [bh][kt][d][64]
__device__ uint32_t g_vtl[kBH * 8 * kD * 64];
__device__ float    g_nq [kBH * kS];
__device__ float    g_nk1[kBH * kS];
__device__ float    g_nk2[kBH * kS];

// ---------------------------------------------------------------------------
// helpers
// ---------------------------------------------------------------------------
__device__ __forceinline__ float ex2(float x) {
  float r;
  asm("ex2.approx.f32 %0, %1;" : "=f"(r) : "f"(x));
  return r;
}
__device__ __forceinline__ void split2(float x, float y, uint32_t& h, uint32_t& l) {
  __nv_bfloat16 bx = __float2bfloat16_rn(x);
  __nv_bfloat16 by = __float2bfloat16_rn(y);
  float rx = x - __bfloat162float(bx);
  float ry = y - __bfloat162float(by);
  __nv_bfloat16 lx = __float2bfloat16_rn(rx);
  __nv_bfloat16 ly = __float2bfloat16_rn(ry);
  h = (uint32_t)__bfloat16_as_ushort(bx) | ((uint32_t)__bfloat16_as_ushort(by) << 16);
  l = (uint32_t)__bfloat16_as_ushort(lx) | ((uint32_t)__bfloat16_as_ushort(ly) << 16);
}

__device__ __forceinline__ void mma_bf16(float* c, const uint32_t* a,
                                         uint32_t b0, uint32_t b1) {
  asm volatile(
      "mma.sync.aligned.m16n8k16.row.col.f32.bf16.bf16.f32 "
      "{%0,%1,%2,%3}, {%4,%5,%6,%7}, {%8,%9}, {%0,%1,%2,%3};\n"
      : "+f"(c[0]), "+f"(c[1]), "+f"(c[2]), "+f"(c[3])
      : "r"(a[0]), "r"(a[1]), "r"(a[2]), "r"(a[3]), "r"(b0), "r"(b1));
}

// ---------------------------------------------------------------------------
// Projection GEMM on tensor cores: C[4096,384] = X @ W^T + bias.
// sel 0 -> g_q + norms; 1/2 -> split-packed K + norms;
// sel 3 -> V split/transposed/permuted attn-ready tiles (g_vth/g_vtl).
// ---------------------------------------------------------------------------
__global__ __launch_bounds__(256) void proj_kernel(
    const float* __restrict__ X,
    const float* __restrict__ Wq,  const float* __restrict__ bq,
    const float* __restrict__ Wk1, const float* __restrict__ bk1,
    const float* __restrict__ Wk2, const float* __restrict__ bk2,
    const float* __restrict__ Wv,  const float* __restrict__ bv)
{
  __shared__ uint32_t Ah[128 * 20], Al[128 * 20];
  __shared__ uint32_t Bh[64 * 20],  Bl[64 * 20];

  const int sel = blockIdx.z;
  const float* W    = (sel == 0) ? Wq : (sel == 1) ? Wk1 : (sel == 2) ? Wk2 : Wv;
  const float* bias = (sel == 0) ? bq : (sel == 1) ? bk1 : (sel == 2) ? bk2 : bv;

  const int tid = threadIdx.x;
  const int w = tid >> 5, lane = tid & 31;
  const int g = lane >> 2, t = lane & 3;
  const int wm = (w & 3) * 32, wn = (w >> 2) * 32;
  const int m0 = blockIdx.y * 128, n0 = blockIdx.x * 64;

  float c[2][4][4];
#pragma unroll
  for (int i = 0; i < 2; i++)
#pragma unroll
    for (int j = 0; j < 4; j++)
#pragma unroll
      for (int k = 0; k < 4; k++) c[i][j][k] = 0.f;

  const int sq = tid & 7, sr = tid >> 3;

  for (int k0 = 0; k0 < kHid; k0 += 32) {
    __syncthreads();
#pragma unroll
    for (int r = sr; r < 128; r += 32) {
      float4 v = *(const float4*)&X[(size_t)(m0 + r) * kHid + k0 + sq * 4];
      uint32_t h0, l0, h1, l1;
      split2(v.x, v.y, h0, l0);
      split2(v.z, v.w, h1, l1);
      Ah[r * 20 + sq * 2] = h0; Ah[r * 20 + sq * 2 + 1] = h1;
      Al[r * 20 + sq * 2] = l0; Al[r * 20 + sq * 2 + 1] = l1;
    }
#pragma unroll
    for (int r = sr; r < 64; r += 32) {
      float4 v = *(const float4*)&W[(size_t)(n0 + r) * kHid + k0 + sq * 4];
      uint32_t h0, l0, h1, l1;
      split2(v.x, v.y, h0, l0);
      split2(v.z, v.w, h1, l1);
      Bh[r * 20 + sq * 2] = h0; Bh[r * 20 + sq * 2 + 1] = h1;
      Bl[r * 20 + sq * 2] = l0; Bl[r * 20 + sq * 2 + 1] = l1;
    }
    __syncthreads();

#pragma unroll
    for (int ks = 0; ks < 2; ks++) {
      uint32_t ah[2][4], al[2][4];
#pragma unroll
      for (int tm = 0; tm < 2; tm++) {
        const int base = (wm + tm * 16 + g) * 20 + 8 * ks + t;
        ah[tm][0] = Ah[base];       ah[tm][1] = Ah[base + 160];
        ah[tm][2] = Ah[base + 4];   ah[tm][3] = Ah[base + 164];
        al[tm][0] = Al[base];       al[tm][1] = Al[base + 160];
        al[tm][2] = Al[base + 4];   al[tm][3] = Al[base + 164];
      }
#pragma unroll
      for (int nc = 0; nc < 4; nc++) {
        const int nb = (wn + nc * 8 + g) * 20 + 8 * ks + t;
        uint32_t b0h = Bh[nb], b1h = Bh[nb + 4];
        uint32_t b0l = Bl[nb], b1l = Bl[nb + 4];
#pragma unroll
        for (int tm = 0; tm < 2; tm++) {
          mma_bf16(c[tm][nc], ah[tm], b0h, b1h);
          mma_bf16(c[tm][nc], ah[tm], b0l, b1l);
          mma_bf16(c[tm][nc], al[tm], b0h, b1h);
        }
      }
    }
  }

  const int head = (n0 + wn) >> 5;
#pragma unroll
  for (int nc = 0; nc < 4; nc++) {
    const float bb0 = bias[n0 + wn + nc * 8 + 2 * t];
    const float bb1 = bias[n0 + wn + nc * 8 + 2 * t + 1];
#pragma unroll
    for (int tm = 0; tm < 2; tm++) {
      c[tm][nc][0] += bb0; c[tm][nc][1] += bb1;
      c[tm][nc][2] += bb0; c[tm][nc][3] += bb1;
    }
  }

  if (sel < 3) {
    // norms
    float* nrm = (sel == 0) ? g_nq : (sel == 1) ? g_nk1 : g_nk2;
    float ps[2][2] = {{0.f, 0.f}, {0.f, 0.f}};
#pragma unroll
    for (int tm = 0; tm < 2; tm++)
#pragma unroll
      for (int nc = 0; nc < 4; nc++) {
        ps[tm][0] = fmaf(c[tm][nc][0], c[tm][nc][0],
                    fmaf(c[tm][nc][1], c[tm][nc][1], ps[tm][0]));
        ps[tm][1] = fmaf(c[tm][nc][2], c[tm][nc][2],
                    fmaf(c[tm][nc][3], c[tm][nc][3], ps[tm][1]));
      }
#pragma unroll
    for (int tm = 0; tm < 2; tm++)
#pragma unroll
      for (int hh = 0; hh < 2; hh++) {
#pragma unroll
        for (int o = 1; o < 4; o <<= 1)
          ps[tm][hh] += __shfl_xor_sync(0xffffffffu, ps[tm][hh], o);
      }
    if (t == 0) {
#pragma unroll
      for (int tm = 0; tm < 2; tm++)
#pragma unroll
        for (int hh = 0; hh < 2; hh++) {
          const int r = m0 + wm + tm * 16 + g + hh * 8;
          const int b = r >> 10, s = r & 1023;
          nrm[(b * kH + head) * kS + s] = ps[tm][hh];
        }
    }
  }

  if (sel == 0) {
#pragma unroll
    for (int tm = 0; tm < 2; tm++)
#pragma unroll
      for (int nc = 0; nc < 4; nc++) {
        const int d = nc * 8 + 2 * t;
        const int r0 = m0 + wm + tm * 16 + g;
        {
          const int b = r0 >> 10, s = r0 & 1023;
          *(float2*)&g_q[(((size_t)b * kH + head) * kS + s) * kD + d] =
              make_float2(c[tm][nc][0], c[tm][nc][1]);
        }
        {
          const int r1 = r0 + 8;
          const int b = r1 >> 10, s = r1 & 1023;
          *(float2*)&g_q[(((size_t)b * kH + head) * kS + s) * kD + d] =
              make_float2(c[tm][nc][2], c[tm][nc][3]);
        }
      }
  } else if (sel < 3) {
    uint32_t* outh = (sel == 1) ? g_k1h : g_k2h;
    uint32_t* outl = (sel == 1) ? g_k1l : g_k2l;
#pragma unroll
    for (int tm = 0; tm < 2; tm++)
#pragma unroll
      for (int nc = 0; nc < 4; nc++) {
        const int pos = t * 4 + nc;
        const int r0 = m0 + wm + tm * 16 + g;
        uint32_t h, l;
        {
          const int b = r0 >> 10, s = r0 & 1023;
          split2(c[tm][nc][0], c[tm][nc][1], h, l);
          const size_t o = ((size_t)(b * kH + head) * kS + s) * 16 + pos;
          outh[o] = h; outl[o] = l;
        }
        {
          const int r1 = r0 + 8;
          const int b = r1 >> 10, s = r1 & 1023;
          split2(c[tm][nc][2], c[tm][nc][3], h, l);
          const size_t o = ((size_t)(b * kH + head) * kS + s) * 16 + pos;
          outh[o] = h; outl[o] = l;
        }
      }
  } else {
    // V: build attn-ready split/transposed/permuted tiles.
    // Pair rows (s even, s+1): row s+1 lives in lane group g+1 -> shfl down 4.
#pragma unroll
    for (int tm = 0; tm < 2; tm++)
#pragma unroll
      for (int nc = 0; nc < 4; nc++)
#pragma unroll
        for (int hh = 0; hh < 2; hh++) {
          float v0 = c[tm][nc][hh * 2];       // col d,   row r
          float v1 = c[tm][nc][hh * 2 + 1];   // col d+1, row r
          float v0o = __shfl_down_sync(0xffffffffu, v0, 4);  // row r+1
          float v1o = __shfl_down_sync(0xffffffffu, v1, 4);
          if ((g & 1) == 0) {
            const int m = m0 + wm + tm * 16 + g + hh * 8;  // even s
            const int b = m >> 10, s = m & 1023;
            const int kt = s >> 7;
            const int jp = (s & 127) >> 1;
            const int pos = (jp & ~7) + ((jp & 3) << 1) + ((jp >> 2) & 1);
            const int d = nc * 8 + 2 * t;
            const size_t base = ((size_t)(b * kH + head) * 8 + kt) * kD;
            uint32_t h0, l0, h1, l1;
            split2(v0, v0o, h0, l0);
            split2(v1, v1o, h1, l1);
            g_vth[(base + d) * 64 + pos] = h0;
            g_vtl[(base + d) * 64 + pos] = l0;
            g_vth[(base + d + 1) * 64 + pos] = h1;
            g_vtl[(base + d + 1) * 64 + pos] = l1;
          }
        }
  }
}

// ---------------------------------------------------------------------------
// Fused attention, 2 passes, all-tensor, log2-domain softmax.
// Block = (128 q rows, one bh), 256 threads. V stage = raw uint4 copy.
// ---------------------------------------------------------------------------
__device__ __forceinline__ void score6(float* c,
                                       const uint32_t aqh[2][4],
                                       const uint32_t aql[2][4],
                                       const uint32_t* __restrict__ Kh,
                                       const uint32_t* __restrict__ Kl,
                                       int rb) {
  uint4 fh = *(const uint4*)&Kh[rb];
  uint4 fl = *(const uint4*)&Kl[rb];
  c[0] = c[1] = c[2] = c[3] = 0.f;
  mma_bf16(c, aqh[0], fh.x, fh.y);
  mma_bf16(c, aqh[0], fl.x, fl.y);
  mma_bf16(c, aql[0], fh.x, fh.y);
  mma_bf16(c, aqh[1], fh.z, fh.w);
  mma_bf16(c, aqh[1], fl.z, fl.w);
  mma_bf16(c, aql[1], fh.z, fh.w);
}

__global__ __launch_bounds__(256, 3) void attn_kernel(
    const float* __restrict__ mask, const float* __restrict__ pi,
    float* __restrict__ out_ctx, float* __restrict__ out_probs)
{
  extern __shared__ uint32_t su[];
  float* colc1 = (float*)(su + U_COLC1);
  float* colc2 = (float*)(su + U_COLC2);
  uint32_t* K1h = su + U_K1H;
  uint32_t* K1l = su + U_K1L;
  uint32_t* K2h = su + U_K2H;
  uint32_t* K2l = su + U_K2L;
  uint32_t* Vth = su + U_VTH;
  uint32_t* Vtl = su + U_VTL;

  const int tid = threadIdx.x;
  const int w = tid >> 5, lane = tid & 31;
  const int g = lane >> 2, t = lane & 3;
  const int R0 = w * 16 + g, R1 = R0 + 8;

  const int qt = blockIdx.x, bh = blockIdx.y;
  const int b = bh / kH, h = bh % kH;
  const int q0 = qt * 128;
  const int nbase = bh * kS;
  const size_t gbase = (size_t)bh * kS * kD;

  const float pi0 = fminf(fmaxf(pi[h],      1e-6f), 2.0f);
  const float pi1 = fminf(fmaxf(pi[kH + h], 1e-6f), 2.0f);
  const float lp0 = __log2f(pi0), lp1 = __log2f(pi1);

  // ---- persistent per-column constants for ALL 1024 cols ----
  for (int i = tid; i < kS; i += 256) {
    const float mk = mask[b * kS + i] * kLog2e;
    colc1[i] = fmaf(-kC1L, g_nk1[nbase + i], mk);
    colc2[i] = fmaf(-kC2L, g_nk2[nbase + i], mk);
  }

  // ---- stage Q fp32 (aliases K region), build persistent split A fragments ----
  {
    float* qst = (float*)(su + U_K1H);   // [128][33]
    for (int i = tid; i < 1024; i += 256) {
      const int j = i >> 3, dg = (i & 7) * 4;
      float4 v = *(const float4*)&g_q[gbase + (size_t)(q0 + j) * kD + dg];
      qst[j * 33 + dg + 0] = v.x; qst[j * 33 + dg + 1] = v.y;
      qst[j * 33 + dg + 2] = v.z; qst[j * 33 + dg + 3] = v.w;
    }
  }
  __syncthreads();

  uint32_t aqh[2][4], aql[2][4];
  {
    float* qst = (float*)(su + U_K1H);
#pragma unroll
    for (int ks = 0; ks < 2; ks++) {
      const int d0 = 16 * ks + 2 * t;
      split2(qst[R0 * 33 + d0],     qst[R0 * 33 + d0 + 1], aqh[ks][0], aql[ks][0]);
      split2(qst[R1 * 33 + d0],     qst[R1 * 33 + d0 + 1], aqh[ks][1], aql[ks][1]);
      split2(qst[R0 * 33 + d0 + 8], qst[R0 * 33 + d0 + 9], aqh[ks][2], aql[ks][2]);
      split2(qst[R1 * 33 + d0 + 8], qst[R1 * 33 + d0 + 9], aqh[ks][3], aql[ks][3]);
    }
  }
  // per-thread row constants (log2 domain)
  const float nq0 = g_nq[nbase + q0 + R0];
  const float nq1 = g_nq[nbase + q0 + R1];
  const float rq1a = -kC1L * nq0, rq1b = -kC1L * nq1;
  const float rq2a = -kC2L * nq0, rq2b = -kC2L * nq1;
  __syncthreads();

#define LOAD_K(j0)                                                            \
  {                                                                           \
    const size_t gw = (size_t)(nbase + (j0)) * 16;                            \
    for (int i = tid * 4; i < 2048; i += 1024) {                              \
      *(uint4*)&K1h[i] = *(const uint4*)&g_k1h[gw + i];                       \
      *(uint4*)&K1l[i] = *(const uint4*)&g_k1l[gw + i];                       \
      *(uint4*)&K2h[i] = *(const uint4*)&g_k2h[gw + i];                       \
      *(uint4*)&K2l[i] = *(const uint4*)&g_k2l[gw + i];                       \
    }                                                                         \
  }

  // ====== pass 1: exact maxes + fixed-reference rowsums (log2 domain) ======
  float m1a = -1e30f, m1b = -1e30f, m2a = -1e30f, m2b = -1e30f;
  float l1a = 0.f, l1b = 0.f, l2a = 0.f, l2b = 0.f;

  for (int kt = 0; kt < 8; kt++) {
    __syncthreads();
    LOAD_K(kt * 128)
    __syncthreads();
#pragma unroll 2
    for (int nt = 0; nt < 16; nt++) {
      const int rb = ((nt * 8 + g) << 4) + t * 4;
      const int col = kt * 128 + nt * 8 + 2 * t;
      const float2 cc1 = *(const float2*)&colc1[col];
      const float2 cc2 = *(const float2*)&colc2[col];
      float c1[4], c2[4];
      score6(c1, aqh, aql, K1h, K1l, rb);
      score6(c2, aqh, aql, K2h, K2l, rb);
      {
        float s0 = fmaf(kTC1, c1[0], cc1.x + rq1a);
        float s1 = fmaf(kTC1, c1[1], cc1.y + rq1a);
        m1a = fmaxf(m1a, fmaxf(s0, s1));
        l1a += ex2(s0) + ex2(s1);
      }
      {
        float s0 = fmaf(kTC1, c1[2], cc1.x + rq1b);
        float s1 = fmaf(kTC1, c1[3], cc1.y + rq1b);
        m1b = fmaxf(m1b, fmaxf(s0, s1));
        l1b += ex2(s0) + ex2(s1);
      }
      {
        float s0 = fmaf(kTC2, c2[0], cc2.x + rq2a);
        float s1 = fmaf(kTC2, c2[1], cc2.y + rq2a);
        m2a = fmaxf(m2a, fmaxf(s0, s1));
        l2a += ex2(s0) + ex2(s1);
      }
      {
        float s0 = fmaf(kTC2, c2[2], cc2.x + rq2b);
        float s1 = fmaf(kTC2, c2[3], cc2.y + rq2b);
        m2b = fmaxf(m2b, fmaxf(s0, s1));
        l2b += ex2(s0) + ex2(s1);
      }
    }
  }
#pragma unroll
  for (int o = 1; o < 4; o <<= 1) {
    m1a = fmaxf(m1a, __shfl_xor_sync(0xffffffffu, m1a, o));
    m1b = fmaxf(m1b, __shfl_xor_sync(0xffffffffu, m1b, o));
    m2a = fmaxf(m2a, __shfl_xor_sync(0xffffffffu, m2a, o));
    m2b = fmaxf(m2b, __shfl_xor_sync(0xffffffffu, m2b, o));
    l1a += __shfl_xor_sync(0xffffffffu, l1a, o);
    l1b += __shfl_xor_sync(0xffffffffu, l1b, o);
    l2a += __shfl_xor_sync(0xffffffffu, l2a, o);
    l2b += __shfl_xor_sync(0xffffffffu, l2b, o);
  }
  const float inv0 = 1.0f / (pi0 * ex2(-m1a) * l1a +
                             pi1 * ex2(-m2a) * l2a + 1e-6f);
  const float inv1 = 1.0f / (pi0 * ex2(-m1b) * l1b +
                             pi1 * ex2(-m2b) * l2b + 1e-6f);
  const float rq1a2 = rq1a + lp0 - m1a, rq1b2 = rq1b + lp0 - m1b;
  const float rq2a2 = rq2a + lp1 - m2a, rq2b2 = rq2b + lp1 - m2b;

  // ============ pass 2: normalized probs + E@V on tensor pipe ============
  float cctx[4][4];
#pragma unroll
  for (int i = 0; i < 4; i++)
#pragma unroll
    for (int j = 0; j < 4; j++) cctx[i][j] = 0.f;

  uint32_t eh[4], el[4];

  for (int kt = 0; kt < 8; kt++) {
    __syncthreads();
    LOAD_K(kt * 128)
    // V tiles are pre-split/transposed/permuted in global: raw copy.
    {
      const size_t vg = ((size_t)bh * 8 + kt) * (kD * 64);
      for (int i = tid; i < 512; i += 256) {
        const int row = i >> 4, c4 = (i & 15) << 2;
        *(uint4*)&Vth[row * 72 + c4] = *(const uint4*)&g_vth[vg + (row << 6) + c4];
        *(uint4*)&Vtl[row * 72 + c4] = *(const uint4*)&g_vtl[vg + (row << 6) + c4];
      }
    }
    __syncthreads();

#pragma unroll 2
    for (int nt = 0; nt < 16; nt++) {
      const int rb = ((nt * 8 + g) << 4) + t * 4;
      const int col = kt * 128 + nt * 8 + 2 * t;
      const float2 cc1 = *(const float2*)&colc1[col];
      const float2 cc2 = *(const float2*)&colc2[col];
      float c1[4], c2[4];
      score6(c1, aqh, aql, K1h, K1l, rb);
      score6(c2, aqh, aql, K2h, K2l, rb);
      float p00 = (ex2(fmaf(kTC1, c1[0], cc1.x + rq1a2))
                 + ex2(fmaf(kTC2, c2[0], cc2.x + rq2a2))) * inv0;
      float p01 = (ex2(fmaf(kTC1, c1[1], cc1.y + rq1a2))
                 + ex2(fmaf(kTC2, c2[1], cc2.y + rq2a2))) * inv0;
      float p10 = (ex2(fmaf(kTC1, c1[2], cc1.x + rq1b2))
                 + ex2(fmaf(kTC2, c2[2], cc2.x + rq2b2))) * inv1;
      float p11 = (ex2(fmaf(kTC1, c1[3], cc1.y + rq1b2))
                 + ex2(fmaf(kTC2, c2[3], cc2.y + rq2b2))) * inv1;

      // normalized probs straight from registers (streaming stores)
      const size_t pb = ((size_t)bh * kS + q0 + R0) * kS + col;
      __stcs((float2*)&out_probs[pb], make_float2(p00, p01));
      __stcs((float2*)&out_probs[pb + 8 * kS], make_float2(p10, p11));

      // E fragment accumulation (A-layout is exactly these lanes/pairs)
      if ((nt & 1) == 0) {
        split2(p00, p01, eh[0], el[0]);
        split2(p10, p11, eh[1], el[1]);
      } else {
        split2(p00, p01, eh[2], el[2]);
        split2(p10, p11, eh[3], el[3]);
        const int ks = nt >> 1;
#pragma unroll
        for (int nd = 0; nd < 4; nd++) {
          const int vb = (nd * 8 + g) * 72 + 8 * ks + 2 * t;
          uint2 vh = *(const uint2*)&Vth[vb];
          uint2 vl = *(const uint2*)&Vtl[vb];
          mma_bf16(cctx[nd], eh, vh.x, vh.y);
          mma_bf16(cctx[nd], eh, vl.x, vl.y);
          mma_bf16(cctx[nd], el, vh.x, vh.y);
        }
      }
    }
  }

  // ctx store (already normalized since E carried inv)
#pragma unroll
  for (int nd = 0; nd < 4; nd++) {
    const int d = nd * 8 + 2 * t;
    *(float2*)&out_ctx[((size_t)b * kS + q0 + R0) * kAH + h * kD + d] =
        make_float2(cctx[nd][0], cctx[nd][1]);
    *(float2*)&out_ctx[((size_t)b * kS + q0 + R1) * kAH + h * kD + d] =
        make_float2(cctx[nd][2], cctx[nd][3]);
  }
#undef LOAD_K
}

// ---------------------------------------------------------------------------
extern "C" void kernel_launch(void* const* d_in, const int* in_sizes, int n_in,
                              void* d_out, int out_size) {
  (void)in_sizes; (void)n_in; (void)out_size;
  const float* hs   = (const float*)d_in[0];
  const float* mask = (const float*)d_in[1];
  const float* Wq   = (const float*)d_in[2];
  const float* bq   = (const float*)d_in[3];
  const float* Wk1  = (const float*)d_in[4];
  const float* bk1  = (const float*)d_in[5];
  const float* Wk2  = (const float*)d_in[6];
  const float* bk2  = (const float*)d_in[7];
  const float* Wv   = (const float*)d_in[8];
  const float* bv   = (const float*)d_in[9];
  const float* pi   = (const float*)d_in[10];

  float* out_ctx   = (float*)d_out;
  float* out_probs = out_ctx + (size_t)kB * kS * kAH;

  cudaFuncSetAttribute(attn_kernel, cudaFuncAttributeMaxDynamicSharedMemorySize,
                       kAttnSmemBytes);

  dim3 pgrid(kAH / 64, (kB * kS) / 128, 4);   // (6, 32, 4) = 768 CTAs
  proj_kernel<<<pgrid, 256>>>(hs, Wq, bq, Wk1, bk1, Wk2, bk2, Wv, bv);
  attn_kernel<<<dim3(kS / 128, kBH), 256, kAttnSmemBytes>>>(
      mask, pi, out_ctx, out_probs);
}

// round 12
// speedup vs baseline: 4.2689x; 1.0942x over previous
#include <cuda_runtime.h>
#include <cuda_bf16.h>
#include <cstdint>

// ---------------------------------------------------------------------------
// MGKBertSelfAttention: B=4, S=1024, HID=768, H=12, D=32, AH=384
// out = [ctx (B,S,AH) ; probs (B,H,S,S)]  fp32
// mma.sync m16n8k16 bf16, 2-term hi/lo split (3-product, fp32-equiv precision).
// R12: smem-free streaming proj fed by pre-split fragment-major X/W operands.
// ---------------------------------------------------------------------------

namespace {
constexpr int kB = 4, kS = 1024, kHid = 768, kH = 12, kD = 32, kAH = 384;
constexpr int kBH = kB * kH;                       // 48
constexpr float kScaling = 0.17677669529663687f;   // 32^-0.5
constexpr float kC1 = 0.5f * kScaling;
constexpr float kC2 = 0.75f * kScaling;
constexpr float kLog2e = 1.4426950408889634f;
constexpr float kC1L = kC1 * kLog2e;
constexpr float kC2L = kC2 * kLog2e;
constexpr float kTC1 = 2.0f * kC1L;
constexpr float kTC2 = 2.0f * kC2L;

constexpr int kMB = (kB * kS) / 16;   // 256 m-blocks (16 rows)
constexpr int kKC = kHid / 16;        // 48 k-chunks
constexpr int kNB = kAH / 8;          // 48 n-blocks (8 cols)

// attn smem layout (u32 units)
constexpr int U_COLC1 = 0;
constexpr int U_COLC2 = 1024;
constexpr int U_K1H   = 2048;
constexpr int U_K1L   = U_K1H + 2048;
constexpr int U_K2H   = U_K1L + 2048;
constexpr int U_K2L   = U_K2H + 2048;
constexpr int U_VTH   = U_K2L + 2048;
constexpr int U_VTL   = U_VTH + 2304;
constexpr int kAttnSmemU32 = U_VTL + 2304;
constexpr int kAttnSmemBytes = kAttnSmemU32 * 4;    // 59648 B
}

// Scratch (device globals; allocation is forbidden)
__device__ float    g_q  [kBH * kS * kD];
__device__ uint32_t g_k1h[kBH * kS * 16];
__device__ uint32_t g_k1l[kBH * kS * 16];
__device__ uint32_t g_k2h[kBH * kS * 16];
__device__ uint32_t g_k2l[kBH * kS * 16];
__device__ uint32_t g_vth[kBH * 8 * kD * 64];
__device__ uint32_t g_vtl[kBH * 8 * kD * 64];
__device__ float    g_nq [kBH * kS];
__device__ float    g_nk1[kBH * kS];
__device__ float    g_nk2[kBH * kS];
// fragment-major pre-split operands
__device__ uint32_t g_xfh[kMB * kKC * 32 * 4];        // 1.57M u32
__device__ uint32_t g_xfl[kMB * kKC * 32 * 4];
__device__ uint32_t g_wfh[4 * kNB * kKC * 32 * 2];    // 590K u32
__device__ uint32_t g_wfl[4 * kNB * kKC * 32 * 2];

// ---------------------------------------------------------------------------
// helpers
// ---------------------------------------------------------------------------
__device__ __forceinline__ float ex2(float x) {
  float r;
  asm("ex2.approx.f32 %0, %1;" : "=f"(r) : "f"(x));
  return r;
}
__device__ __forceinline__ void split2(float x, float y, uint32_t& h, uint32_t& l) {
  __nv_bfloat16 bx = __float2bfloat16_rn(x);
  __nv_bfloat16 by = __float2bfloat16_rn(y);
  float rx = x - __bfloat162float(bx);
  float ry = y - __bfloat162float(by);
  __nv_bfloat16 lx = __float2bfloat16_rn(rx);
  __nv_bfloat16 ly = __float2bfloat16_rn(ry);
  h = (uint32_t)__bfloat16_as_ushort(bx) | ((uint32_t)__bfloat16_as_ushort(by) << 16);
  l = (uint32_t)__bfloat16_as_ushort(lx) | ((uint32_t)__bfloat16_as_ushort(ly) << 16);
}
__device__ __forceinline__ void mma_bf16(float* c, const uint32_t* a,
                                         uint32_t b0, uint32_t b1) {
  asm volatile(
      "mma.sync.aligned.m16n8k16.row.col.f32.bf16.bf16.f32 "
      "{%0,%1,%2,%3}, {%4,%5,%6,%7}, {%8,%9}, {%0,%1,%2,%3};\n"
      : "+f"(c[0]), "+f"(c[1]), "+f"(c[2]), "+f"(c[3])
      : "r"(a[0]), "r"(a[1]), "r"(a[2]), "r"(a[3]), "r"(b0), "r"(b1));
}

// ---------------------------------------------------------------------------
// Pre-split kernel: build fragment-major hi/lo operands for X and all 4 W.
// One warp per (mb,kc) X-fragment block or per (sel,nb,kc) W-fragment block.
// ---------------------------------------------------------------------------
__global__ __launch_bounds__(256) void presplit_kernel(
    const float* __restrict__ X,
    const float* __restrict__ Wq, const float* __restrict__ Wk1,
    const float* __restrict__ Wk2, const float* __restrict__ Wv)
{
  const int wg = blockIdx.x * 8 + (threadIdx.x >> 5);
  const int lane = threadIdx.x & 31;
  const int g = lane >> 2, t = lane & 3;

  if (wg < kMB * kKC) {
    // X fragment block
    const int mb = wg / kKC, kc = wg % kKC;
    const float* p0 = X + (size_t)(mb * 16 + g) * kHid + kc * 16 + 2 * t;
    const float* p1 = p0 + 8 * kHid;
    float2 v00 = *(const float2*)p0;        // (row g,   pair t)
    float2 v01 = *(const float2*)(p0 + 8);  // (row g,   pair t+4)
    float2 v10 = *(const float2*)p1;        // (row g+8, pair t)
    float2 v11 = *(const float2*)(p1 + 8);  // (row g+8, pair t+4)
    uint4 hv, lv;
    split2(v00.x, v00.y, hv.x, lv.x);
    split2(v10.x, v10.y, hv.y, lv.y);
    split2(v01.x, v01.y, hv.z, lv.z);
    split2(v11.x, v11.y, hv.w, lv.w);
    const size_t o = ((size_t)wg * 32 + lane) * 4;
    *(uint4*)&g_xfh[o] = hv;
    *(uint4*)&g_xfl[o] = lv;
  } else {
    const int r = wg - kMB * kKC;           // [0, 4*kNB*kKC)
    if (r >= 4 * kNB * kKC) return;
    const int sel = r / (kNB * kKC);
    const int rr = r % (kNB * kKC);
    const int nb = rr / kKC, kc = rr % kKC;
    const float* W = (sel == 0) ? Wq : (sel == 1) ? Wk1 : (sel == 2) ? Wk2 : Wv;
    const float* p = W + (size_t)(nb * 8 + g) * kHid + kc * 16 + 2 * t;
    float2 v0 = *(const float2*)p;          // (col n, pair t)
    float2 v1 = *(const float2*)(p + 8);    // (col n, pair t+4)
    uint32_t h0, l0, h1, l1;
    split2(v0.x, v0.y, h0, l0);
    split2(v1.x, v1.y, h1, l1);
    const size_t o = ((size_t)r * 32 + lane) * 2;
    g_wfh[o] = h0; g_wfh[o + 1] = h1;
    g_wfl[o] = l0; g_wfl[o + 1] = l1;
  }
}

// ---------------------------------------------------------------------------
// Streaming projection GEMM: no smem, no barriers. CTA 128x64, warps 4x2.
// Fragments loaded directly from pre-split global (L2-resident).
// ---------------------------------------------------------------------------
__global__ __launch_bounds__(256) void proj_kernel(
    const float* __restrict__ bq, const float* __restrict__ bk1,
    const float* __restrict__ bk2, const float* __restrict__ bv)
{
  const int sel = blockIdx.z;
  const float* bias = (sel == 0) ? bq : (sel == 1) ? bk1 : (sel == 2) ? bk2 : bv;

  const int tid = threadIdx.x;
  const int w = tid >> 5, lane = tid & 31;
  const int g = lane >> 2, t = lane & 3;
  const int wm = (w & 3) * 32, wn = (w >> 2) * 32;
  const int m0 = blockIdx.y * 128, n0 = blockIdx.x * 64;

  // fragment base offsets (u32 units)
  const int mb0 = (m0 + wm) >> 4;           // tm adds +1
  const int nb0 = (n0 + wn) >> 3;           // nc adds +1 each
  const size_t xbase0 = (((size_t)mb0 * kKC) * 32 + lane) * 4;
  const size_t xbase1 = ((((size_t)mb0 + 1) * kKC) * 32 + lane) * 4;
  const size_t wsel = (size_t)sel * kNB * kKC * 64;
  size_t wbase[4];
#pragma unroll
  for (int nc = 0; nc < 4; nc++)
    wbase[nc] = wsel + (((size_t)(nb0 + nc) * kKC) * 32 + lane) * 2;

  float c[2][4][4];
#pragma unroll
  for (int i = 0; i < 2; i++)
#pragma unroll
    for (int j = 0; j < 4; j++)
#pragma unroll
      for (int k = 0; k < 4; k++) c[i][j][k] = 0.f;

#pragma unroll 2
  for (int kc = 0; kc < kKC; kc++) {
    uint4 ah[2], al[2];
    ah[0] = *(const uint4*)&g_xfh[xbase0 + (size_t)kc * 128];
    al[0] = *(const uint4*)&g_xfl[xbase0 + (size_t)kc * 128];
    ah[1] = *(const uint4*)&g_xfh[xbase1 + (size_t)kc * 128];
    al[1] = *(const uint4*)&g_xfl[xbase1 + (size_t)kc * 128];
#pragma unroll
    for (int nc = 0; nc < 4; nc++) {
      const size_t wo = wbase[nc] + (size_t)kc * 64;
      uint2 bh = *(const uint2*)&g_wfh[wo];
      uint2 bl = *(const uint2*)&g_wfl[wo];
#pragma unroll
      for (int tm = 0; tm < 2; tm++) {
        mma_bf16(c[tm][nc], (const uint32_t*)&ah[tm], bh.x, bh.y);
        mma_bf16(c[tm][nc], (const uint32_t*)&ah[tm], bl.x, bl.y);
        mma_bf16(c[tm][nc], (const uint32_t*)&al[tm], bh.x, bh.y);
      }
    }
  }

  // ---- epilogue (identical semantics to R11) ----
  const int head = (n0 + wn) >> 5;
#pragma unroll
  for (int nc = 0; nc < 4; nc++) {
    const float bb0 = bias[n0 + wn + nc * 8 + 2 * t];
    const float bb1 = bias[n0 + wn + nc * 8 + 2 * t + 1];
#pragma unroll
    for (int tm = 0; tm < 2; tm++) {
      c[tm][nc][0] += bb0; c[tm][nc][1] += bb1;
      c[tm][nc][2] += bb0; c[tm][nc][3] += bb1;
    }
  }

  if (sel < 3) {
    float* nrm = (sel == 0) ? g_nq : (sel == 1) ? g_nk1 : g_nk2;
    float ps[2][2] = {{0.f, 0.f}, {0.f, 0.f}};
#pragma unroll
    for (int tm = 0; tm < 2; tm++)
#pragma unroll
      for (int nc = 0; nc < 4; nc++) {
        ps[tm][0] = fmaf(c[tm][nc][0], c[tm][nc][0],
                    fmaf(c[tm][nc][1], c[tm][nc][1], ps[tm][0]));
        ps[tm][1] = fmaf(c[tm][nc][2], c[tm][nc][2],
                    fmaf(c[tm][nc][3], c[tm][nc][3], ps[tm][1]));
      }
#pragma unroll
    for (int tm = 0; tm < 2; tm++)
#pragma unroll
      for (int hh = 0; hh < 2; hh++) {
#pragma unroll
        for (int o = 1; o < 4; o <<= 1)
          ps[tm][hh] += __shfl_xor_sync(0xffffffffu, ps[tm][hh], o);
      }
    if (t == 0) {
#pragma unroll
      for (int tm = 0; tm < 2; tm++)
#pragma unroll
        for (int hh = 0; hh < 2; hh++) {
          const int r = m0 + wm + tm * 16 + g + hh * 8;
          const int b = r >> 10, s = r & 1023;
          nrm[(b * kH + head) * kS + s] = ps[tm][hh];
        }
    }
  }

  if (sel == 0) {
#pragma unroll
    for (int tm = 0; tm < 2; tm++)
#pragma unroll
      for (int nc = 0; nc < 4; nc++) {
        const int d = nc * 8 + 2 * t;
        const int r0 = m0 + wm + tm * 16 + g;
        {
          const int b = r0 >> 10, s = r0 & 1023;
          *(float2*)&g_q[(((size_t)b * kH + head) * kS + s) * kD + d] =
              make_float2(c[tm][nc][0], c[tm][nc][1]);
        }
        {
          const int r1 = r0 + 8;
          const int b = r1 >> 10, s = r1 & 1023;
          *(float2*)&g_q[(((size_t)b * kH + head) * kS + s) * kD + d] =
              make_float2(c[tm][nc][2], c[tm][nc][3]);
        }
      }
  } else if (sel < 3) {
    uint32_t* outh = (sel == 1) ? g_k1h : g_k2h;
    uint32_t* outl = (sel == 1) ? g_k1l : g_k2l;
#pragma unroll
    for (int tm = 0; tm < 2; tm++)
#pragma unroll
      for (int nc = 0; nc < 4; nc++) {
        const int pos = t * 4 + nc;
        const int r0 = m0 + wm + tm * 16 + g;
        uint32_t h, l;
        {
          const int b = r0 >> 10, s = r0 & 1023;
          split2(c[tm][nc][0], c[tm][nc][1], h, l);
          const size_t o = ((size_t)(b * kH + head) * kS + s) * 16 + pos;
          outh[o] = h; outl[o] = l;
        }
        {
          const int r1 = r0 + 8;
          const int b = r1 >> 10, s = r1 & 1023;
          split2(c[tm][nc][2], c[tm][nc][3], h, l);
          const size_t o = ((size_t)(b * kH + head) * kS + s) * 16 + pos;
          outh[o] = h; outl[o] = l;
        }
      }
  } else {
    // V: attn-ready split/transposed/permuted tiles
#pragma unroll
    for (int tm = 0; tm < 2; tm++)
#pragma unroll
      for (int nc = 0; nc < 4; nc++)
#pragma unroll
        for (int hh = 0; hh < 2; hh++) {
          float v0 = c[tm][nc][hh * 2];
          float v1 = c[tm][nc][hh * 2 + 1];
          float v0o = __shfl_down_sync(0xffffffffu, v0, 4);
          float v1o = __shfl_down_sync(0xffffffffu, v1, 4);
          if ((g & 1) == 0) {
            const int m = m0 + wm + tm * 16 + g + hh * 8;
            const int b = m >> 10, s = m & 1023;
            const int kt = s >> 7;
            const int jp = (s & 127) >> 1;
            const int pos = (jp & ~7) + ((jp & 3) << 1) + ((jp >> 2) & 1);
            const int d = nc * 8 + 2 * t;
            const size_t base = ((size_t)(b * kH + head) * 8 + kt) * kD;
            uint32_t h0, l0, h1, l1;
            split2(v0, v0o, h0, l0);
            split2(v1, v1o, h1, l1);
            g_vth[(base + d) * 64 + pos] = h0;
            g_vtl[(base + d) * 64 + pos] = l0;
            g_vth[(base + d + 1) * 64 + pos] = h1;
            g_vtl[(base + d + 1) * 64 + pos] = l1;
          }
        }
  }
}

// ---------------------------------------------------------------------------
// Fused attention (unchanged from R11).
// ---------------------------------------------------------------------------
__device__ __forceinline__ void score6(float* c,
                                       const uint32_t aqh[2][4],
                                       const uint32_t aql[2][4],
                                       const uint32_t* __restrict__ Kh,
                                       const uint32_t* __restrict__ Kl,
                                       int rb) {
  uint4 fh = *(const uint4*)&Kh[rb];
  uint4 fl = *(const uint4*)&Kl[rb];
  c[0] = c[1] = c[2] = c[3] = 0.f;
  mma_bf16(c, aqh[0], fh.x, fh.y);
  mma_bf16(c, aqh[0], fl.x, fl.y);
  mma_bf16(c, aql[0], fh.x, fh.y);
  mma_bf16(c, aqh[1], fh.z, fh.w);
  mma_bf16(c, aqh[1], fl.z, fl.w);
  mma_bf16(c, aql[1], fh.z, fh.w);
}

__global__ __launch_bounds__(256, 3) void attn_kernel(
    const float* __restrict__ mask, const float* __restrict__ pi,
    float* __restrict__ out_ctx, float* __restrict__ out_probs)
{
  extern __shared__ uint32_t su[];
  float* colc1 = (float*)(su + U_COLC1);
  float* colc2 = (float*)(su + U_COLC2);
  uint32_t* K1h = su + U_K1H;
  uint32_t* K1l = su + U_K1L;
  uint32_t* K2h = su + U_K2H;
  uint32_t* K2l = su + U_K2L;
  uint32_t* Vth = su + U_VTH;
  uint32_t* Vtl = su + U_VTL;

  const int tid = threadIdx.x;
  const int w = tid >> 5, lane = tid & 31;
  const int g = lane >> 2, t = lane & 3;
  const int R0 = w * 16 + g, R1 = R0 + 8;

  const int qt = blockIdx.x, bh = blockIdx.y;
  const int b = bh / kH, h = bh % kH;
  const int q0 = qt * 128;
  const int nbase = bh * kS;
  const size_t gbase = (size_t)bh * kS * kD;

  const float pi0 = fminf(fmaxf(pi[h],      1e-6f), 2.0f);
  const float pi1 = fminf(fmaxf(pi[kH + h], 1e-6f), 2.0f);
  const float lp0 = __log2f(pi0), lp1 = __log2f(pi1);

  for (int i = tid; i < kS; i += 256) {
    const float mk = mask[b * kS + i] * kLog2e;
    colc1[i] = fmaf(-kC1L, g_nk1[nbase + i], mk);
    colc2[i] = fmaf(-kC2L, g_nk2[nbase + i], mk);
  }

  {
    float* qst = (float*)(su + U_K1H);
    for (int i = tid; i < 1024; i += 256) {
      const int j = i >> 3, dg = (i & 7) * 4;
      float4 v = *(const float4*)&g_q[gbase + (size_t)(q0 + j) * kD + dg];
      qst[j * 33 + dg + 0] = v.x; qst[j * 33 + dg + 1] = v.y;
      qst[j * 33 + dg + 2] = v.z; qst[j * 33 + dg + 3] = v.w;
    }
  }
  __syncthreads();

  uint32_t aqh[2][4], aql[2][4];
  {
    float* qst = (float*)(su + U_K1H);
#pragma unroll
    for (int ks = 0; ks < 2; ks++) {
      const int d0 = 16 * ks + 2 * t;
      split2(qst[R0 * 33 + d0],     qst[R0 * 33 + d0 + 1], aqh[ks][0], aql[ks][0]);
      split2(qst[R1 * 33 + d0],     qst[R1 * 33 + d0 + 1], aqh[ks][1], aql[ks][1]);
      split2(qst[R0 * 33 + d0 + 8], qst[R0 * 33 + d0 + 9], aqh[ks][2], aql[ks][2]);
      split2(qst[R1 * 33 + d0 + 8], qst[R1 * 33 + d0 + 9], aqh[ks][3], aql[ks][3]);
    }
  }
  const float nq0 = g_nq[nbase + q0 + R0];
  const float nq1 = g_nq[nbase + q0 + R1];
  const float rq1a = -kC1L * nq0, rq1b = -kC1L * nq1;
  const float rq2a = -kC2L * nq0, rq2b = -kC2L * nq1;
  __syncthreads();

#define LOAD_K(j0)                                                            \
  {                                                                           \
    const size_t gw = (size_t)(nbase + (j0)) * 16;                            \
    for (int i = tid * 4; i < 2048; i += 1024) {                              \
      *(uint4*)&K1h[i] = *(const uint4*)&g_k1h[gw + i];                       \
      *(uint4*)&K1l[i] = *(const uint4*)&g_k1l[gw + i];                       \
      *(uint4*)&K2h[i] = *(const uint4*)&g_k2h[gw + i];                       \
      *(uint4*)&K2l[i] = *(const uint4*)&g_k2l[gw + i];                       \
    }                                                                         \
  }

  // ====== pass 1 ======
  float m1a = -1e30f, m1b = -1e30f, m2a = -1e30f, m2b = -1e30f;
  float l1a = 0.f, l1b = 0.f, l2a = 0.f, l2b = 0.f;

  for (int kt = 0; kt < 8; kt++) {
    __syncthreads();
    LOAD_K(kt * 128)
    __syncthreads();
#pragma unroll 2
    for (int nt = 0; nt < 16; nt++) {
      const int rb = ((nt * 8 + g) << 4) + t * 4;
      const int col = kt * 128 + nt * 8 + 2 * t;
      const float2 cc1 = *(const float2*)&colc1[col];
      const float2 cc2 = *(const float2*)&colc2[col];
      float c1[4], c2[4];
      score6(c1, aqh, aql, K1h, K1l, rb);
      score6(c2, aqh, aql, K2h, K2l, rb);
      {
        float s0 = fmaf(kTC1, c1[0], cc1.x + rq1a);
        float s1 = fmaf(kTC1, c1[1], cc1.y + rq1a);
        m1a = fmaxf(m1a, fmaxf(s0, s1));
        l1a += ex2(s0) + ex2(s1);
      }
      {
        float s0 = fmaf(kTC1, c1[2], cc1.x + rq1b);
        float s1 = fmaf(kTC1, c1[3], cc1.y + rq1b);
        m1b = fmaxf(m1b, fmaxf(s0, s1));
        l1b += ex2(s0) + ex2(s1);
      }
      {
        float s0 = fmaf(kTC2, c2[0], cc2.x + rq2a);
        float s1 = fmaf(kTC2, c2[1], cc2.y + rq2a);
        m2a = fmaxf(m2a, fmaxf(s0, s1));
        l2a += ex2(s0) + ex2(s1);
      }
      {
        float s0 = fmaf(kTC2, c2[2], cc2.x + rq2b);
        float s1 = fmaf(kTC2, c2[3], cc2.y + rq2b);
        m2b = fmaxf(m2b, fmaxf(s0, s1));
        l2b += ex2(s0) + ex2(s1);
      }
    }
  }
#pragma unroll
  for (int o = 1; o < 4; o <<= 1) {
    m1a = fmaxf(m1a, __shfl_xor_sync(0xffffffffu, m1a, o));
    m1b = fmaxf(m1b, __shfl_xor_sync(0xffffffffu, m1b, o));
    m2a = fmaxf(m2a, __shfl_xor_sync(0xffffffffu, m2a, o));
    m2b = fmaxf(m2b, __shfl_xor_sync(0xffffffffu, m2b, o));
    l1a += __shfl_xor_sync(0xffffffffu, l1a, o);
    l1b += __shfl_xor_sync(0xffffffffu, l1b, o);
    l2a += __shfl_xor_sync(0xffffffffu, l2a, o);
    l2b += __shfl_xor_sync(0xffffffffu, l2b, o);
  }
  const float inv0 = 1.0f / (pi0 * ex2(-m1a) * l1a +
                             pi1 * ex2(-m2a) * l2a + 1e-6f);
  const float inv1 = 1.0f / (pi0 * ex2(-m1b) * l1b +
                             pi1 * ex2(-m2b) * l2b + 1e-6f);
  const float rq1a2 = rq1a + lp0 - m1a, rq1b2 = rq1b + lp0 - m1b;
  const float rq2a2 = rq2a + lp1 - m2a, rq2b2 = rq2b + lp1 - m2b;

  // ====== pass 2 ======
  float cctx[4][4];
#pragma unroll
  for (int i = 0; i < 4; i++)
#pragma unroll
    for (int j = 0; j < 4; j++) cctx[i][j] = 0.f;

  uint32_t eh[4], el[4];

  for (int kt = 0; kt < 8; kt++) {
    __syncthreads();
    LOAD_K(kt * 128)
    {
      const size_t vg = ((size_t)bh * 8 + kt) * (kD * 64);
      for (int i = tid; i < 512; i += 256) {
        const int row = i >> 4, c4 = (i & 15) << 2;
        *(uint4*)&Vth[row * 72 + c4] = *(const uint4*)&g_vth[vg + (row << 6) + c4];
        *(uint4*)&Vtl[row * 72 + c4] = *(const uint4*)&g_vtl[vg + (row << 6) + c4];
      }
    }
    __syncthreads();

#pragma unroll 2
    for (int nt = 0; nt < 16; nt++) {
      const int rb = ((nt * 8 + g) << 4) + t * 4;
      const int col = kt * 128 + nt * 8 + 2 * t;
      const float2 cc1 = *(const float2*)&colc1[col];
      const float2 cc2 = *(const float2*)&colc2[col];
      float c1[4], c2[4];
      score6(c1, aqh, aql, K1h, K1l, rb);
      score6(c2, aqh, aql, K2h, K2l, rb);
      float p00 = (ex2(fmaf(kTC1, c1[0], cc1.x + rq1a2))
                 + ex2(fmaf(kTC2, c2[0], cc2.x + rq2a2))) * inv0;
      float p01 = (ex2(fmaf(kTC1, c1[1], cc1.y + rq1a2))
                 + ex2(fmaf(kTC2, c2[1], cc2.y + rq2a2))) * inv0;
      float p10 = (ex2(fmaf(kTC1, c1[2], cc1.x + rq1b2))
                 + ex2(fmaf(kTC2, c2[2], cc2.x + rq2b2))) * inv1;
      float p11 = (ex2(fmaf(kTC1, c1[3], cc1.y + rq1b2))
                 + ex2(fmaf(kTC2, c2[3], cc2.y + rq2b2))) * inv1;

      const size_t pb = ((size_t)bh * kS + q0 + R0) * kS + col;
      __stcs((float2*)&out_probs[pb], make_float2(p00, p01));
      __stcs((float2*)&out_probs[pb + 8 * kS], make_float2(p10, p11));

      if ((nt & 1) == 0) {
        split2(p00, p01, eh[0], el[0]);
        split2(p10, p11, eh[1], el[1]);
      } else {
        split2(p00, p01, eh[2], el[2]);
        split2(p10, p11, eh[3], el[3]);
        const int ks = nt >> 1;
#pragma unroll
        for (int nd = 0; nd < 4; nd++) {
          const int vb = (nd * 8 + g) * 72 + 8 * ks + 2 * t;
          uint2 vh = *(const uint2*)&Vth[vb];
          uint2 vl = *(const uint2*)&Vtl[vb];
          mma_bf16(cctx[nd], eh, vh.x, vh.y);
          mma_bf16(cctx[nd], eh, vl.x, vl.y);
          mma_bf16(cctx[nd], el, vh.x, vh.y);
        }
      }
    }
  }

#pragma unroll
  for (int nd = 0; nd < 4; nd++) {
    const int d = nd * 8 + 2 * t;
    *(float2*)&out_ctx[((size_t)b * kS + q0 + R0) * kAH + h * kD + d] =
        make_float2(cctx[nd][0], cctx[nd][1]);
    *(float2*)&out_ctx[((size_t)b * kS + q0 + R1) * kAH + h * kD + d] =
        make_float2(cctx[nd][2], cctx[nd][3]);
  }
#undef LOAD_K
}

// ---------------------------------------------------------------------------
extern "C" void kernel_launch(void* const* d_in, const int* in_sizes, int n_in,
                              void* d_out, int out_size) {
  (void)in_sizes; (void)n_in; (void)out_size;
  const float* hs   = (const float*)d_in[0];
  const float* mask = (const float*)d_in[1];
  const float* Wq   = (const float*)d_in[2];
  const float* bq   = (const float*)d_in[3];
  const float* Wk1  = (const float*)d_in[4];
  const float* bk1  = (const float*)d_in[5];
  const float* Wk2  = (const float*)d_in[6];
  const float* bk2  = (const float*)d_in[7];
  const float* Wv   = (const float*)d_in[8];
  const float* bv   = (const float*)d_in[9];
  const float* pi   = (const float*)d_in[10];

  float* out_ctx   = (float*)d_out;
  float* out_probs = out_ctx + (size_t)kB * kS * kAH;

  cudaFuncSetAttribute(attn_kernel, cudaFuncAttributeMaxDynamicSharedMemorySize,
                       kAttnSmemBytes);

  // pre-split X (12288 warps) + 4x W (9216 warps) -> 21504 warps -> 2688 CTAs
  const int total_warps = kMB * kKC + 4 * kNB * kKC;
  presplit_kernel<<<(total_warps + 7) / 8, 256>>>(hs, Wq, Wk1, Wk2, Wv);

  dim3 pgrid(kAH / 64, (kB * kS) / 128, 4);   // (6, 32, 4) = 768 CTAs
  proj_kernel<<<pgrid, 256>>>(bq, bk1, bk2, bv);
  attn_kernel<<<dim3(kS / 128, kBH), 256, kAttnSmemBytes>>>(
      mask, pi, out_ctx, out_probs);
}